// round 1
// baseline (speedup 1.0000x reference)
#include <cuda_runtime.h>
#include <math.h>

// Problem constants
#define BB     4
#define NN     4096
#define MM     32768
#define DTOK   512
#define DATOM  128
#define NHEAD  4
#define DH     32
#define WMAX   16
#define LNEPS  1e-5f

#define NTOK   (BB * NN)    // 16384 token rows
#define NATOM  (BB * MM)    // 131072 atom rows

// -------- scratch (device globals; no allocations allowed) --------
__device__ float g_K[(size_t)NATOM * DATOM];
__device__ float g_V[(size_t)NATOM * DATOM];
__device__ float g_Q[(size_t)NTOK * DATOM];
__device__ float g_G[(size_t)NTOK * DATOM];
__device__ float g_smu[NTOK];
__device__ float g_srs[NTOK];

__device__ __forceinline__ float warp_sum(float v) {
#pragma unroll
    for (int o = 16; o > 0; o >>= 1) v += __shfl_xor_sync(0xffffffffu, v, o);
    return v;
}
__device__ __forceinline__ float warp_max(float v) {
#pragma unroll
    for (int o = 16; o > 0; o >>= 1) v = fmaxf(v, __shfl_xor_sync(0xffffffffu, v, o));
    return v;
}

// ==================================================================
// Kernel 1: per-row LN stats for s (rows of 512). One warp per row.
// ==================================================================
__global__ void stats_s_kernel(const float* __restrict__ s) {
    int row  = blockIdx.x * 8 + (threadIdx.x >> 5);
    int lane = threadIdx.x & 31;
    const float4* p = (const float4*)(s + (size_t)row * DTOK);
    float sum = 0.f, sq = 0.f;
#pragma unroll
    for (int j = 0; j < 4; j++) {
        float4 v = p[lane + 32 * j];
        sum += v.x + v.y + v.z + v.w;
        sq  += v.x * v.x + v.y * v.y + v.z * v.z + v.w * v.w;
    }
    sum = warp_sum(sum);
    sq  = warp_sum(sq);
    if (lane == 0) {
        float mu  = sum * (1.f / DTOK);
        float var = sq * (1.f / DTOK) - mu * mu;
        g_smu[row] = mu;
        g_srs[row] = rsqrtf(var + LNEPS);
    }
}

// ==================================================================
// Kernel 2: LN(a) fused + K = a_n @ w_k, V = a_n @ w_v.
// 128-row tile per block. smem: A(64KB) + Wk(64KB) + Wv(64KB) = 192KB.
// 256 threads, 8x8 microtile, two passes (K then V).
// ==================================================================
__global__ void __launch_bounds__(256, 1)
kv_kernel(const float* __restrict__ a, const float* __restrict__ wk,
          const float* __restrict__ wv, const float* __restrict__ lng,
          const float* __restrict__ lnb) {
    extern __shared__ float sm[];
    float* As  = sm;            // 128 x 128
    float* Wks = sm + 16384;    // 128 x 128
    float* Wvs = sm + 32768;    // 128 x 128

    int tid = threadIdx.x;
    size_t rowbase = (size_t)blockIdx.x * 128;

    const float4* ag  = (const float4*)(a + rowbase * DATOM);
    const float4* wkg = (const float4*)wk;
    const float4* wvg = (const float4*)wv;
#pragma unroll
    for (int t = 0; t < 16; t++) {
        int j = tid + t * 256;                 // 0..4095 float4s
        ((float4*)As)[j]  = ag[j];
        ((float4*)Wks)[j] = wkg[j];
        ((float4*)Wvs)[j] = wvg[j];
    }
    __syncthreads();

    // In-place LayerNorm of A rows (128 elems). warp per row, 16 rows/warp.
    int warp = tid >> 5, lane = tid & 31;
    float4 gln = ((const float4*)lng)[lane];
    float4 bln = ((const float4*)lnb)[lane];
    for (int r = warp; r < 128; r += 8) {
        float4 v = ((float4*)As)[r * 32 + lane];
        float sum = warp_sum(v.x + v.y + v.z + v.w);
        float sq  = warp_sum(v.x * v.x + v.y * v.y + v.z * v.z + v.w * v.w);
        float mu  = sum * (1.f / 128.f);
        float rs  = rsqrtf(sq * (1.f / 128.f) - mu * mu + LNEPS);
        v.x = (v.x - mu) * rs * gln.x + bln.x;
        v.y = (v.y - mu) * rs * gln.y + bln.y;
        v.z = (v.z - mu) * rs * gln.z + bln.z;
        v.w = (v.w - mu) * rs * gln.w + bln.w;
        ((float4*)As)[r * 32 + lane] = v;
    }
    __syncthreads();

    int ty = tid >> 4;      // 0..15  -> rows ty*8 .. ty*8+7
    int tx = tid & 15;      // 0..15  -> cols tx*4..+3 and 64+tx*4..+3

    const float* Ws  = Wks;
    float*       outp = g_K;
#pragma unroll 1
    for (int pass = 0; pass < 2; pass++) {
        if (pass == 1) { Ws = Wvs; outp = g_V; }
        float acc[8][8];
#pragma unroll
        for (int i = 0; i < 8; i++)
#pragma unroll
            for (int j = 0; j < 8; j++) acc[i][j] = 0.f;

#pragma unroll 4
        for (int k = 0; k < 128; k++) {
            float av[8], bv[8];
#pragma unroll
            for (int i = 0; i < 8; i++) av[i] = As[(ty * 8 + i) * 128 + k];
            *(float4*)&bv[0] = *(const float4*)&Ws[k * 128 + tx * 4];
            *(float4*)&bv[4] = *(const float4*)&Ws[k * 128 + 64 + tx * 4];
#pragma unroll
            for (int i = 0; i < 8; i++)
#pragma unroll
                for (int j = 0; j < 8; j++)
                    acc[i][j] = fmaf(av[i], bv[j], acc[i][j]);
        }
#pragma unroll
        for (int i = 0; i < 8; i++) {
            size_t ro = (rowbase + ty * 8 + i) * DATOM;
            *(float4*)&outp[ro + tx * 4] =
                make_float4(acc[i][0], acc[i][1], acc[i][2], acc[i][3]);
            *(float4*)&outp[ro + 64 + tx * 4] =
                make_float4(acc[i][4], acc[i][5], acc[i][6], acc[i][7]);
        }
    }
}

// ==================================================================
// Kernel 3: LN(s) fused (via stats) + Q = s_n @ w_q, G = s_n @ w_g.
// 128 rows x 256 cols ([Q|G]) per block, K tiled by 32. 512 threads.
// ==================================================================
__global__ void __launch_bounds__(512, 1)
qg_kernel(const float* __restrict__ s, const float* __restrict__ wq,
          const float* __restrict__ wg, const float* __restrict__ lng,
          const float* __restrict__ lnb) {
    __shared__ float As[128 * 32];
    __shared__ float Bs[32 * 256];

    int tid = threadIdx.x;
    size_t rowbase = (size_t)blockIdx.x * 128;
    int ty = tid >> 5;   // 0..15 -> rows ty*8..+7
    int tx = tid & 31;   // 0..31 -> cols tx*4..+3 (Q) and 128+tx*4..+3 (G)

    float acc[8][8];
#pragma unroll
    for (int i = 0; i < 8; i++)
#pragma unroll
        for (int j = 0; j < 8; j++) acc[i][j] = 0.f;

    for (int k0 = 0; k0 < DTOK; k0 += 32) {
        // A tile: 128 x 32, LN applied on the fly
#pragma unroll
        for (int t = 0; t < 2; t++) {
            int j   = tid + t * 512;       // 0..1023 float4s
            int row = j >> 3;
            int c   = (j & 7) << 2;
            float4 v  = *(const float4*)(s + (rowbase + row) * DTOK + k0 + c);
            float mu = g_smu[rowbase + row];
            float rs = g_srs[rowbase + row];
            float4 gv = *(const float4*)(lng + k0 + c);
            float4 bv = *(const float4*)(lnb + k0 + c);
            float4 o;
            o.x = (v.x - mu) * rs * gv.x + bv.x;
            o.y = (v.y - mu) * rs * gv.y + bv.y;
            o.z = (v.z - mu) * rs * gv.z + bv.z;
            o.w = (v.w - mu) * rs * gv.w + bv.w;
            *(float4*)&As[row * 32 + c] = o;
        }
        // B tile: [wq_rows | wg_rows] 32 x 256
#pragma unroll
        for (int t = 0; t < 2; t++) {
            int j  = tid + t * 512;        // 0..1023 float4s of the wq part
            int kk = j >> 5;
            int c  = (j & 31) << 2;
            *(float4*)&Bs[kk * 256 + c] =
                *(const float4*)(wq + (size_t)(k0 + kk) * DATOM + c);
            *(float4*)&Bs[kk * 256 + 128 + c] =
                *(const float4*)(wg + (size_t)(k0 + kk) * DATOM + c);
        }
        __syncthreads();
#pragma unroll
        for (int k = 0; k < 32; k++) {
            float av[8], bv[8];
#pragma unroll
            for (int i = 0; i < 8; i++) av[i] = As[(ty * 8 + i) * 32 + k];
            *(float4*)&bv[0] = *(const float4*)&Bs[k * 256 + tx * 4];
            *(float4*)&bv[4] = *(const float4*)&Bs[k * 256 + 128 + tx * 4];
#pragma unroll
            for (int i = 0; i < 8; i++)
#pragma unroll
                for (int j = 0; j < 8; j++)
                    acc[i][j] = fmaf(av[i], bv[j], acc[i][j]);
        }
        __syncthreads();
    }
#pragma unroll
    for (int i = 0; i < 8; i++) {
        size_t ro = (rowbase + ty * 8 + i) * DATOM;
        *(float4*)&g_Q[ro + tx * 4] =
            make_float4(acc[i][0], acc[i][1], acc[i][2], acc[i][3]);
        *(float4*)&g_G[ro + tx * 4] =
            make_float4(acc[i][4], acc[i][5], acc[i][6], acc[i][7]);
    }
}

// ==================================================================
// Kernel 4: ragged window attention + gate + output GEMM.
// 32 tokens/block, 256 threads.
// Phase 1: warp per token (4 tokens/warp): scores via shfl over dh=32
//          lanes, softmax over <=16 window slots, att, sigmoid gate,
//          token_mask -> U[32][128] in smem.
// Phase 2: U @ w_o (128 x 512), w_o staged in smem 32 k-rows at a time.
// ==================================================================
__global__ void __launch_bounds__(256, 1)
attn_kernel(const int* __restrict__ starts, const int* __restrict__ counts,
            const float* __restrict__ tmask, const float* __restrict__ wo,
            float* __restrict__ out) {
    extern __shared__ float sm[];
    float* U   = sm;          // 32 x 128
    float* Wos = sm + 4096;   // 32 x 512

    int tid  = threadIdx.x;
    int warp = tid >> 5, lane = tid & 31;
    int tokbase = blockIdx.x * 32;
    const float scale = 0.17677669529663687f;   // 1/sqrt(32)

    for (int it = 0; it < 4; it++) {
        int lt = warp * 4 + it;
        int bt = tokbase + lt;
        int b  = bt >> 12;                       // / N (4096)
        int start = starts[bt];
        int count = counts[bt];
        size_t kvbase = ((size_t)b * MM + start) * DATOM;

        float q[NHEAD], acc[NHEAD], sc[NHEAD], p[NHEAD];
#pragma unroll
        for (int h = 0; h < NHEAD; h++) {
            q[h]   = g_Q[(size_t)bt * DATOM + h * DH + lane];
            acc[h] = 0.f;
            sc[h]  = 0.f;
        }
        // scores
        for (int w = 0; w < count; w++) {
            const float* kr = g_K + kvbase + (size_t)w * DATOM;
            float s0 = q[0] * kr[lane];
            float s1 = q[1] * kr[32 + lane];
            float s2 = q[2] * kr[64 + lane];
            float s3 = q[3] * kr[96 + lane];
            s0 = warp_sum(s0); s1 = warp_sum(s1);
            s2 = warp_sum(s2); s3 = warp_sum(s3);
            if (lane == w) { sc[0] = s0; sc[1] = s1; sc[2] = s2; sc[3] = s3; }
        }
        // softmax over window slots held one-per-lane
#pragma unroll
        for (int h = 0; h < NHEAD; h++) {
            float v = (lane < count) ? sc[h] * scale : -1e30f;
            float m = warp_max(v);
            float e = (lane < count) ? expf(v - m) : 0.f;
            float ssum = warp_sum(e);
            p[h] = e / ssum;
        }
        // attention output
        for (int w = 0; w < count; w++) {
            const float* vr = g_V + kvbase + (size_t)w * DATOM;
#pragma unroll
            for (int h = 0; h < NHEAD; h++) {
                float pw = __shfl_sync(0xffffffffu, p[h], w);
                acc[h] = fmaf(pw, vr[h * DH + lane], acc[h]);
            }
        }
        float msk = tmask[bt];
#pragma unroll
        for (int h = 0; h < NHEAD; h++) {
            float gv   = g_G[(size_t)bt * DATOM + h * DH + lane];
            float gate = 1.f / (1.f + expf(-gv));
            U[lt * DATOM + h * DH + lane] = gate * acc[h] * msk;
        }
    }
    __syncthreads();

    // Phase 2: (32 x 128) @ (128 x 512)
    int ty = tid >> 6;   // 0..3  -> rows ty*8..+7
    int tx = tid & 63;   // 0..63 -> cols tx*4..+3 and 256+tx*4..+3
    float acc2[8][8];
#pragma unroll
    for (int i = 0; i < 8; i++)
#pragma unroll
        for (int j = 0; j < 8; j++) acc2[i][j] = 0.f;

    for (int k0 = 0; k0 < DATOM; k0 += 32) {
#pragma unroll
        for (int t = 0; t < 16; t++) {
            int j = tid + t * 256;               // 0..4095 float4s
            ((float4*)Wos)[j] = ((const float4*)(wo + (size_t)k0 * DTOK))[j];
        }
        __syncthreads();
#pragma unroll
        for (int k = 0; k < 32; k++) {
            float av[8], bv[8];
#pragma unroll
            for (int i = 0; i < 8; i++) av[i] = U[(ty * 8 + i) * DATOM + k0 + k];
            *(float4*)&bv[0] = *(const float4*)&Wos[k * DTOK + tx * 4];
            *(float4*)&bv[4] = *(const float4*)&Wos[k * DTOK + 256 + tx * 4];
#pragma unroll
            for (int i = 0; i < 8; i++)
#pragma unroll
                for (int j = 0; j < 8; j++)
                    acc2[i][j] = fmaf(av[i], bv[j], acc2[i][j]);
        }
        __syncthreads();
    }
#pragma unroll
    for (int i = 0; i < 8; i++) {
        size_t ob = (size_t)(tokbase + ty * 8 + i) * DTOK;
        *(float4*)&out[ob + tx * 4] =
            make_float4(acc2[i][0], acc2[i][1], acc2[i][2], acc2[i][3]);
        *(float4*)&out[ob + 256 + tx * 4] =
            make_float4(acc2[i][4], acc2[i][5], acc2[i][6], acc2[i][7]);
    }
}

// ==================================================================
// Launch. Input order (metadata): s, a, token_atom_starts,
// token_atom_counts, token_mask, w_q, w_k, w_v, w_g, w_o,
// ln_q_g, ln_q_b, ln_kv_g, ln_kv_b. Output: (B,N,512) float32.
// ==================================================================
extern "C" void kernel_launch(void* const* d_in, const int* in_sizes, int n_in,
                              void* d_out, int out_size) {
    const float* s      = (const float*)d_in[0];
    const float* a      = (const float*)d_in[1];
    const int*   starts = (const int*)  d_in[2];
    const int*   counts = (const int*)  d_in[3];
    const float* tmask  = (const float*)d_in[4];
    const float* wq     = (const float*)d_in[5];
    const float* wk     = (const float*)d_in[6];
    const float* wv     = (const float*)d_in[7];
    const float* wg     = (const float*)d_in[8];
    const float* wo     = (const float*)d_in[9];
    const float* lnqg   = (const float*)d_in[10];
    const float* lnqb   = (const float*)d_in[11];
    const float* lnkg   = (const float*)d_in[12];
    const float* lnkb   = (const float*)d_in[13];
    float* out = (float*)d_out;

    cudaFuncSetAttribute(kv_kernel, cudaFuncAttributeMaxDynamicSharedMemorySize,
                         192 * 1024);
    cudaFuncSetAttribute(attn_kernel, cudaFuncAttributeMaxDynamicSharedMemorySize,
                         80 * 1024);

    stats_s_kernel<<<NTOK / 8, 256>>>(s);
    kv_kernel<<<NATOM / 128, 256, 192 * 1024>>>(a, wk, wv, lnkg, lnkb);
    qg_kernel<<<NTOK / 128, 512>>>(s, wq, wg, lnqg, lnqb);
    attn_kernel<<<NTOK / 32, 256, 80 * 1024>>>(starts, counts, tmask, wo, out);
}

// round 5
// speedup vs baseline: 1.5024x; 1.5024x over previous
#include <cuda_runtime.h>
#include <cuda_bf16.h>
#include <cstdint>
#include <math.h>

// Problem constants
#define BB     4
#define NN     4096
#define MM     32768
#define DTOK   512
#define DATOM  128
#define NHEAD  4
#define DH     32
#define WMAX   16
#define LNEPS  1e-5f

#define NTOK   (BB * NN)    // 16384 token rows
#define NATOM  (BB * MM)    // 131072 atom rows

// Single dynamic smem symbol shared by all kernels (cast locally).
extern __shared__ char dyn_smem[];

// -------- scratch (device globals; no allocations allowed) --------
__device__ float g_K[(size_t)NATOM * DATOM];
__device__ float g_V[(size_t)NATOM * DATOM];
__device__ float g_Q[(size_t)NTOK * DATOM];
__device__ float g_G[(size_t)NTOK * DATOM];
__device__ float g_U[(size_t)NTOK * DATOM];
__device__ float g_smu[NTOK];
__device__ float g_srs[NTOK];

__device__ __forceinline__ float warp_sum(float v) {
#pragma unroll
    for (int o = 16; o > 0; o >>= 1) v += __shfl_xor_sync(0xffffffffu, v, o);
    return v;
}
__device__ __forceinline__ uint32_t smem_u32(const void* p) {
    uint32_t a;
    asm("{ .reg .u64 t; cvta.to.shared.u64 t, %1; cvt.u32.u64 %0, t; }"
        : "=r"(a) : "l"(p));
    return a;
}
__device__ __forceinline__ uint32_t pack_bf2(float a, float b) {
    __nv_bfloat162 t = __floats2bfloat162_rn(a, b);
    return *(uint32_t*)&t;
}
// hi = bf16 round of x; lo = x - hi (exact in fp32, fits bf16 well enough)
__device__ __forceinline__ void split_bf(float x, float& hi, float& lo) {
    __nv_bfloat16 h = __float2bfloat16(x);
    hi = __bfloat162float(h);
    lo = x - hi;
}

// ---- warp-level MMA helpers (sm_80+, works on sm_100 base target) ----
__device__ __forceinline__ void ldm4(uint32_t* d, uint32_t addr) {
    asm volatile("ldmatrix.sync.aligned.m8n8.x4.shared.b16 {%0,%1,%2,%3}, [%4];"
                 : "=r"(d[0]), "=r"(d[1]), "=r"(d[2]), "=r"(d[3]) : "r"(addr));
}
__device__ __forceinline__ void ldm4t(uint32_t* d, uint32_t addr) {
    asm volatile("ldmatrix.sync.aligned.m8n8.x4.trans.shared.b16 {%0,%1,%2,%3}, [%4];"
                 : "=r"(d[0]), "=r"(d[1]), "=r"(d[2]), "=r"(d[3]) : "r"(addr));
}
__device__ __forceinline__ void mma16816(float* c, const uint32_t* a,
                                         uint32_t b0, uint32_t b1) {
    asm volatile(
        "mma.sync.aligned.m16n8k16.row.col.f32.bf16.bf16.f32 "
        "{%0,%1,%2,%3}, {%4,%5,%6,%7}, {%8,%9}, {%0,%1,%2,%3};"
        : "+f"(c[0]), "+f"(c[1]), "+f"(c[2]), "+f"(c[3])
        : "r"(a[0]), "r"(a[1]), "r"(a[2]), "r"(a[3]), "r"(b0), "r"(b1));
}

// ==================================================================
// Kernel 1: per-row LN stats for s (rows of 512). One warp per row.
// ==================================================================
__global__ void stats_s_kernel(const float* __restrict__ s) {
    int row  = blockIdx.x * 8 + (threadIdx.x >> 5);
    int lane = threadIdx.x & 31;
    const float4* p = (const float4*)(s + (size_t)row * DTOK);
    float sum = 0.f, sq = 0.f;
#pragma unroll
    for (int j = 0; j < 4; j++) {
        float4 v = p[lane + 32 * j];
        sum += v.x + v.y + v.z + v.w;
        sq  += v.x * v.x + v.y * v.y + v.z * v.z + v.w * v.w;
    }
    sum = warp_sum(sum);
    sq  = warp_sum(sq);
    if (lane == 0) {
        float mu  = sum * (1.f / DTOK);
        float var = sq * (1.f / DTOK) - mu * mu;
        g_smu[row] = mu;
        g_srs[row] = rsqrtf(var + LNEPS);
    }
}

// ==================================================================
// Kernel 2 (mma.sync bf16 split): LN(a) + K = a_n @ w_k, V = a_n @ w_v.
// Tile 128x128x128 per block, 8 warps as 4(m) x 2(n); each warp owns
// 32 rows x 64 cols = 2 mtiles x 8 ntiles of m16n8k16.
// SMEM (bf16, padded row stride 136 elems = 272 B, conflict-free ldmatrix):
//   A_hi/A_lo [m][k], Wk_hi/lo [k][n], Wv_hi/lo [k][n].
// 3 accumulation passes: Ah*Wh + Ah*Wl + Al*Wh.
// C staged via smem (reusing Wk / Wv regions) for coalesced stores.
// ==================================================================
#define KV_STRIDE_B 272              // bytes per smem row (136 bf16)
#define KV_TILE_B   (128 * KV_STRIDE_B)   // 34816
#define OFF_AHI  0
#define OFF_ALO  (OFF_AHI + KV_TILE_B)
#define OFF_WKHI (OFF_ALO + KV_TILE_B)
#define OFF_WKLO (OFF_WKHI + KV_TILE_B)
#define OFF_WVHI (OFF_WKLO + KV_TILE_B)
#define OFF_WVLO (OFF_WVHI + KV_TILE_B)
#define KV_SMEM  (OFF_WVLO + KV_TILE_B)   // 208896 bytes
#define STG_STRIDE 136                    // floats per staged row

__global__ void __launch_bounds__(256, 1)
kv_mma_kernel(const float* __restrict__ a, const float* __restrict__ wk,
              const float* __restrict__ wv, const float* __restrict__ lng,
              const float* __restrict__ lnb) {
    char* sm = dyn_smem;
    uint32_t sbase = smem_u32(sm);
    int tid = threadIdx.x;
    int warp = tid >> 5, lane = tid & 31;
    size_t rowbase = (size_t)blockIdx.x * 128;

    // ---- A tile: LN rows -> hi/lo bf16 (row-major [m][k], padded) ----
    float4 gln = ((const float4*)lng)[lane];
    float4 bln = ((const float4*)lnb)[lane];
    for (int r = warp; r < 128; r += 8) {
        float4 v = *(const float4*)(a + (rowbase + r) * DATOM + lane * 4);
        float sum = warp_sum(v.x + v.y + v.z + v.w);
        float sq  = warp_sum(v.x * v.x + v.y * v.y + v.z * v.z + v.w * v.w);
        float mu  = sum * (1.f / 128.f);
        float rs  = rsqrtf(sq * (1.f / 128.f) - mu * mu + LNEPS);
        float n0 = (v.x - mu) * rs * gln.x + bln.x;
        float n1 = (v.y - mu) * rs * gln.y + bln.y;
        float n2 = (v.z - mu) * rs * gln.z + bln.z;
        float n3 = (v.w - mu) * rs * gln.w + bln.w;
        float h0, l0, h1, l1, h2, l2, h3, l3;
        split_bf(n0, h0, l0); split_bf(n1, h1, l1);
        split_bf(n2, h2, l2); split_bf(n3, h3, l3);
        uint32_t off = (uint32_t)r * KV_STRIDE_B + lane * 8;
        *(uint32_t*)(sm + OFF_AHI + off)     = pack_bf2(h0, h1);
        *(uint32_t*)(sm + OFF_AHI + off + 4) = pack_bf2(h2, h3);
        *(uint32_t*)(sm + OFF_ALO + off)     = pack_bf2(l0, l1);
        *(uint32_t*)(sm + OFF_ALO + off + 4) = pack_bf2(l2, l3);
    }
    // ---- W tiles: row-major [k][n], hi/lo ----
#pragma unroll
    for (int t = 0; t < 16; t++) {
        int j  = tid + t * 256;      // 0..4095 float4s
        int k  = j >> 5;
        int c4 = (j & 31) * 4;
        uint32_t off = (uint32_t)k * KV_STRIDE_B + c4 * 2;
        float4 v = *(const float4*)(wk + (size_t)k * DATOM + c4);
        float h0, l0, h1, l1, h2, l2, h3, l3;
        split_bf(v.x, h0, l0); split_bf(v.y, h1, l1);
        split_bf(v.z, h2, l2); split_bf(v.w, h3, l3);
        *(uint32_t*)(sm + OFF_WKHI + off)     = pack_bf2(h0, h1);
        *(uint32_t*)(sm + OFF_WKHI + off + 4) = pack_bf2(h2, h3);
        *(uint32_t*)(sm + OFF_WKLO + off)     = pack_bf2(l0, l1);
        *(uint32_t*)(sm + OFF_WKLO + off + 4) = pack_bf2(l2, l3);
        v = *(const float4*)(wv + (size_t)k * DATOM + c4);
        split_bf(v.x, h0, l0); split_bf(v.y, h1, l1);
        split_bf(v.z, h2, l2); split_bf(v.w, h3, l3);
        *(uint32_t*)(sm + OFF_WVHI + off)     = pack_bf2(h0, h1);
        *(uint32_t*)(sm + OFF_WVHI + off + 4) = pack_bf2(h2, h3);
        *(uint32_t*)(sm + OFF_WVLO + off)     = pack_bf2(l0, l1);
        *(uint32_t*)(sm + OFF_WVLO + off + 4) = pack_bf2(l2, l3);
    }
    __syncthreads();

    int wm = warp & 3;   // m block: rows wm*32 .. +31
    int wn = warp >> 2;  // n half:  cols wn*64 .. +63
    int lr = lane & 15;  // ldmatrix row within 16
    int lc = lane >> 4;  // ldmatrix col-8 selector

    // per-lane ldmatrix address components
    // A (non-trans): row = wm*32 + mt*16 + lr, col = k0 + lc*8
    uint32_t aAddr = sbase + (uint32_t)(wm * 32 + lr) * KV_STRIDE_B + lc * 16;
    // W (.trans): row = k0 + lr, col = wn*64 + i*16 + lc*8
    uint32_t bAddr = sbase + (uint32_t)lr * KV_STRIDE_B + (wn * 64 + lc * 8) * 2;

    const int woff_hi[2] = {OFF_WKHI, OFF_WVHI};
    const int woff_lo[2] = {OFF_WKLO, OFF_WVLO};
    const int stg_off[2] = {OFF_WKHI, OFF_WVHI};   // stage reuses W regions

#pragma unroll 1
    for (int o = 0; o < 2; o++) {
        float c[2][8][4];
#pragma unroll
        for (int mt = 0; mt < 2; mt++)
#pragma unroll
            for (int nt = 0; nt < 8; nt++)
#pragma unroll
                for (int e = 0; e < 4; e++) c[mt][nt][e] = 0.f;

#pragma unroll
        for (int ks = 0; ks < 8; ks++) {
            uint32_t ak = aAddr + ks * 32;             // k0*2 bytes
            uint32_t bk = bAddr + ks * 16 * KV_STRIDE_B;
            uint32_t aH[2][4], aL[2][4];
            ldm4(aH[0], ak + OFF_AHI);
            ldm4(aH[1], ak + OFF_AHI + 16 * KV_STRIDE_B);
            ldm4(aL[0], ak + OFF_ALO);
            ldm4(aL[1], ak + OFF_ALO + 16 * KV_STRIDE_B);
            uint32_t bH[4][4], bL[4][4];
#pragma unroll
            for (int i = 0; i < 4; i++) {
                ldm4t(bH[i], bk + woff_hi[o] + i * 32);
                ldm4t(bL[i], bk + woff_lo[o] + i * 32);
            }
#pragma unroll
            for (int mt = 0; mt < 2; mt++)
#pragma unroll
                for (int i = 0; i < 4; i++) {
                    // ntile 2i:   b = {d0, d1};  ntile 2i+1: b = {d2, d3}
                    mma16816(c[mt][2 * i],     aH[mt], bH[i][0], bH[i][1]);
                    mma16816(c[mt][2 * i + 1], aH[mt], bH[i][2], bH[i][3]);
                    mma16816(c[mt][2 * i],     aH[mt], bL[i][0], bL[i][1]);
                    mma16816(c[mt][2 * i + 1], aH[mt], bL[i][2], bL[i][3]);
                    mma16816(c[mt][2 * i],     aL[mt], bH[i][0], bH[i][1]);
                    mma16816(c[mt][2 * i + 1], aL[mt], bH[i][2], bH[i][3]);
                }
        }
        __syncthreads();   // all warps done reading W region 'o' before reuse
        // stage C into smem (fp32, stride 136 floats)
        float* stg = (float*)(sm + stg_off[o]);
        int cr = lane >> 2, cc2 = (lane & 3) * 2;
#pragma unroll
        for (int mt = 0; mt < 2; mt++) {
            int r0 = wm * 32 + mt * 16 + cr;
#pragma unroll
            for (int nt = 0; nt < 8; nt++) {
                int cc = wn * 64 + nt * 8 + cc2;
                *(float2*)&stg[r0 * STG_STRIDE + cc] =
                    make_float2(c[mt][nt][0], c[mt][nt][1]);
                *(float2*)&stg[(r0 + 8) * STG_STRIDE + cc] =
                    make_float2(c[mt][nt][2], c[mt][nt][3]);
            }
        }
        __syncthreads();
        // coalesced copy to global
        float* dst = (o == 0) ? g_K : g_V;
#pragma unroll
        for (int t = 0; t < 16; t++) {
            int j  = tid + t * 256;
            int r  = j >> 5;
            int c4 = (j & 31) * 4;
            float4 v = *(float4*)&stg[r * STG_STRIDE + c4];
            *(float4*)&dst[(rowbase + r) * DATOM + c4] = v;
        }
    }
}

// ==================================================================
// Kernel 3: LN(s) fused (via stats) + Q = s_n @ w_q, G = s_n @ w_g.
// 128 rows x 256 cols ([Q|G]) per block, K tiled by 32. 512 threads.
// ==================================================================
__global__ void __launch_bounds__(512, 1)
qg_kernel(const float* __restrict__ s, const float* __restrict__ wq,
          const float* __restrict__ wg, const float* __restrict__ lng,
          const float* __restrict__ lnb) {
    __shared__ float As[128 * 32];
    __shared__ float Bs[32 * 256];

    int tid = threadIdx.x;
    size_t rowbase = (size_t)blockIdx.x * 128;
    int ty = tid >> 5;
    int tx = tid & 31;

    float acc[8][8];
#pragma unroll
    for (int i = 0; i < 8; i++)
#pragma unroll
        for (int j = 0; j < 8; j++) acc[i][j] = 0.f;

    for (int k0 = 0; k0 < DTOK; k0 += 32) {
#pragma unroll
        for (int t = 0; t < 2; t++) {
            int j   = tid + t * 512;
            int row = j >> 3;
            int c   = (j & 7) << 2;
            float4 v  = *(const float4*)(s + (rowbase + row) * DTOK + k0 + c);
            float mu = g_smu[rowbase + row];
            float rs = g_srs[rowbase + row];
            float4 gv = *(const float4*)(lng + k0 + c);
            float4 bv = *(const float4*)(lnb + k0 + c);
            float4 o;
            o.x = (v.x - mu) * rs * gv.x + bv.x;
            o.y = (v.y - mu) * rs * gv.y + bv.y;
            o.z = (v.z - mu) * rs * gv.z + bv.z;
            o.w = (v.w - mu) * rs * gv.w + bv.w;
            *(float4*)&As[row * 32 + c] = o;
        }
#pragma unroll
        for (int t = 0; t < 2; t++) {
            int j  = tid + t * 512;
            int kk = j >> 5;
            int c  = (j & 31) << 2;
            *(float4*)&Bs[kk * 256 + c] =
                *(const float4*)(wq + (size_t)(k0 + kk) * DATOM + c);
            *(float4*)&Bs[kk * 256 + 128 + c] =
                *(const float4*)(wg + (size_t)(k0 + kk) * DATOM + c);
        }
        __syncthreads();
#pragma unroll
        for (int k = 0; k < 32; k++) {
            float av[8], bv[8];
#pragma unroll
            for (int i = 0; i < 8; i++) av[i] = As[(ty * 8 + i) * 32 + k];
            *(float4*)&bv[0] = *(const float4*)&Bs[k * 256 + tx * 4];
            *(float4*)&bv[4] = *(const float4*)&Bs[k * 256 + 128 + tx * 4];
#pragma unroll
            for (int i = 0; i < 8; i++)
#pragma unroll
                for (int j = 0; j < 8; j++)
                    acc[i][j] = fmaf(av[i], bv[j], acc[i][j]);
        }
        __syncthreads();
    }
#pragma unroll
    for (int i = 0; i < 8; i++) {
        size_t ro = (rowbase + ty * 8 + i) * DATOM;
        *(float4*)&g_Q[ro + tx * 4] =
            make_float4(acc[i][0], acc[i][1], acc[i][2], acc[i][3]);
        *(float4*)&g_G[ro + tx * 4] =
            make_float4(acc[i][4], acc[i][5], acc[i][6], acc[i][7]);
    }
}

// ==================================================================
// Kernel 4: ragged window attention + gate. Thread = (token, head).
// ==================================================================
__global__ void __launch_bounds__(256, 1)
attn_gate_kernel(const int* __restrict__ starts, const int* __restrict__ counts,
                 const float* __restrict__ tmask) {
    __shared__ float sc[WMAX][256];
    int tid = threadIdx.x;
    int gt  = blockIdx.x * 256 + tid;
    int bt  = gt >> 2;
    int h   = gt & 3;
    int b   = bt >> 12;
    int start = starts[bt];
    int count = counts[bt];
    const float scale = 0.17677669529663687f;   // 1/sqrt(32)

    float4 q[8];
    const float4* qp = (const float4*)(g_Q + (size_t)bt * DATOM + h * DH);
#pragma unroll
    for (int j = 0; j < 8; j++) q[j] = qp[j];

    const float* kb = g_K + ((size_t)b * MM + start) * DATOM + h * DH;
    for (int w = 0; w < count; w++) {
        const float4* kr = (const float4*)(kb + (size_t)w * DATOM);
        float d = 0.f;
#pragma unroll
        for (int j = 0; j < 8; j++) {
            float4 kv = kr[j];
            d = fmaf(q[j].x, kv.x, d);
            d = fmaf(q[j].y, kv.y, d);
            d = fmaf(q[j].z, kv.z, d);
            d = fmaf(q[j].w, kv.w, d);
        }
        sc[w][tid] = d * scale;
    }
    float m = -1e30f;
    for (int w = 0; w < count; w++) m = fmaxf(m, sc[w][tid]);
    float sum = 0.f;
    for (int w = 0; w < count; w++) {
        float e = expf(sc[w][tid] - m);
        sc[w][tid] = e;
        sum += e;
    }
    float inv = 1.f / sum;

    float4 acc[8];
#pragma unroll
    for (int j = 0; j < 8; j++) acc[j] = make_float4(0.f, 0.f, 0.f, 0.f);
    const float* vb = g_V + ((size_t)b * MM + start) * DATOM + h * DH;
    for (int w = 0; w < count; w++) {
        float p = sc[w][tid] * inv;
        const float4* vr = (const float4*)(vb + (size_t)w * DATOM);
#pragma unroll
        for (int j = 0; j < 8; j++) {
            float4 vv = vr[j];
            acc[j].x = fmaf(p, vv.x, acc[j].x);
            acc[j].y = fmaf(p, vv.y, acc[j].y);
            acc[j].z = fmaf(p, vv.z, acc[j].z);
            acc[j].w = fmaf(p, vv.w, acc[j].w);
        }
    }
    float msk = tmask[bt];
    const float4* gp = (const float4*)(g_G + (size_t)bt * DATOM + h * DH);
    float4* up = (float4*)(g_U + (size_t)bt * DATOM + h * DH);
#pragma unroll
    for (int j = 0; j < 8; j++) {
        float4 gv = gp[j];
        float4 u;
        u.x = acc[j].x * msk / (1.f + expf(-gv.x));
        u.y = acc[j].y * msk / (1.f + expf(-gv.y));
        u.z = acc[j].z * msk / (1.f + expf(-gv.z));
        u.w = acc[j].w * msk / (1.f + expf(-gv.w));
        up[j] = u;
    }
}

// ==================================================================
// Kernel 5: out = U @ w_o  (16384x128 @ 128x512).
// ==================================================================
__global__ void __launch_bounds__(512, 1)
out_gemm_kernel(const float* __restrict__ wo, float* __restrict__ out) {
    float* smf = (float*)dyn_smem;
    float* Us = smf;            // 128 x 128
    float* Ws = smf + 16384;    // 128 x 256

    int tid = threadIdx.x;
    size_t rowbase = (size_t)blockIdx.x * 128;
    int half = blockIdx.y;

    const float4* ug = (const float4*)(g_U + rowbase * DATOM);
#pragma unroll
    for (int t = 0; t < 8; t++)
        ((float4*)Us)[tid + t * 512] = ug[tid + t * 512];
#pragma unroll
    for (int t = 0; t < 16; t++) {
        int j = tid + t * 512;
        int k = j >> 6;
        int c = (j & 63) << 2;
        *(float4*)&Ws[k * 256 + c] =
            *(const float4*)(wo + (size_t)k * DTOK + half * 256 + c);
    }
    __syncthreads();

    int ty = tid >> 5;
    int tx = tid & 31;
    float acc[8][8];
#pragma unroll
    for (int i = 0; i < 8; i++)
#pragma unroll
        for (int j = 0; j < 8; j++) acc[i][j] = 0.f;

#pragma unroll 4
    for (int k = 0; k < 128; k++) {
        float av[8], bv[8];
#pragma unroll
        for (int i = 0; i < 8; i++) av[i] = Us[(ty * 8 + i) * 128 + k];
        *(float4*)&bv[0] = *(const float4*)&Ws[k * 256 + tx * 4];
        *(float4*)&bv[4] = *(const float4*)&Ws[k * 256 + 128 + tx * 4];
#pragma unroll
        for (int i = 0; i < 8; i++)
#pragma unroll
            for (int j = 0; j < 8; j++)
                acc[i][j] = fmaf(av[i], bv[j], acc[i][j]);
    }
#pragma unroll
    for (int i = 0; i < 8; i++) {
        size_t ob = (rowbase + ty * 8 + i) * DTOK + half * 256;
        *(float4*)&out[ob + tx * 4] =
            make_float4(acc[i][0], acc[i][1], acc[i][2], acc[i][3]);
        *(float4*)&out[ob + 128 + tx * 4] =
            make_float4(acc[i][4], acc[i][5], acc[i][6], acc[i][7]);
    }
}

// ==================================================================
// Launch. Input order: s, a, starts, counts, token_mask, w_q, w_k,
// w_v, w_g, w_o, ln_q_g, ln_q_b, ln_kv_g, ln_kv_b. Output fp32.
// ==================================================================
extern "C" void kernel_launch(void* const* d_in, const int* in_sizes, int n_in,
                              void* d_out, int out_size) {
    const float* s      = (const float*)d_in[0];
    const float* a      = (const float*)d_in[1];
    const int*   starts = (const int*)  d_in[2];
    const int*   counts = (const int*)  d_in[3];
    const float* tmask  = (const float*)d_in[4];
    const float* wq     = (const float*)d_in[5];
    const float* wk     = (const float*)d_in[6];
    const float* wv     = (const float*)d_in[7];
    const float* wg     = (const float*)d_in[8];
    const float* wo     = (const float*)d_in[9];
    const float* lnqg   = (const float*)d_in[10];
    const float* lnqb   = (const float*)d_in[11];
    const float* lnkg   = (const float*)d_in[12];
    const float* lnkb   = (const float*)d_in[13];
    float* out = (float*)d_out;

    cudaFuncSetAttribute(kv_mma_kernel,
                         cudaFuncAttributeMaxDynamicSharedMemorySize, KV_SMEM);
    cudaFuncSetAttribute(out_gemm_kernel,
                         cudaFuncAttributeMaxDynamicSharedMemorySize, 192 * 1024);

    stats_s_kernel<<<NTOK / 8, 256>>>(s);
    kv_mma_kernel<<<NATOM / 128, 256, KV_SMEM>>>(a, wk, wv, lnkg, lnkb);
    qg_kernel<<<NTOK / 128, 512>>>(s, wq, wg, lnqg, lnqb);
    // one thread per (token, head): NTOK * NHEAD threads total
    attn_gate_kernel<<<NTOK * NHEAD / 256, 256>>>(starts, counts, tmask);
    out_gemm_kernel<<<dim3(128, 2), 512, 192 * 1024>>>(wo, out);
}

// round 6
// speedup vs baseline: 2.0111x; 1.3386x over previous
#include <cuda_runtime.h>
#include <cuda_bf16.h>
#include <cstdint>
#include <math.h>

// Problem constants
#define BB     4
#define NN     4096
#define MM     32768
#define DTOK   512
#define DATOM  128
#define NHEAD  4
#define DH     32
#define WMAX   16
#define LNEPS  1e-5f

#define NTOK   (BB * NN)    // 16384 token rows
#define NATOM  (BB * MM)    // 131072 atom rows

// Single dynamic smem symbol shared by all kernels (cast locally).
extern __shared__ char dyn_smem[];

// -------- scratch (device globals; no allocations allowed) --------
__device__ float g_K[(size_t)NATOM * DATOM];
__device__ float g_V[(size_t)NATOM * DATOM];
__device__ float g_Q[(size_t)NTOK * DATOM];
__device__ float g_G[(size_t)NTOK * DATOM];
__device__ float g_U[(size_t)NTOK * DATOM];
__device__ float g_smu[NTOK];
__device__ float g_srs[NTOK];

__device__ __forceinline__ float warp_sum(float v) {
#pragma unroll
    for (int o = 16; o > 0; o >>= 1) v += __shfl_xor_sync(0xffffffffu, v, o);
    return v;
}
__device__ __forceinline__ uint32_t smem_u32(const void* p) {
    uint32_t a;
    asm("{ .reg .u64 t; cvta.to.shared.u64 t, %1; cvt.u32.u64 %0, t; }"
        : "=r"(a) : "l"(p));
    return a;
}
__device__ __forceinline__ uint32_t pack_bf2(float a, float b) {
    __nv_bfloat162 t = __floats2bfloat162_rn(a, b);
    return *(uint32_t*)&t;
}
// hi = bf16 round of x; lo = x - hi
__device__ __forceinline__ void split_bf(float x, float& hi, float& lo) {
    __nv_bfloat16 h = __float2bfloat16(x);
    hi = __bfloat162float(h);
    lo = x - hi;
}

// ---- warp-level MMA helpers (sm_80+, works on sm_100 base target) ----
__device__ __forceinline__ void ldm4(uint32_t* d, uint32_t addr) {
    asm volatile("ldmatrix.sync.aligned.m8n8.x4.shared.b16 {%0,%1,%2,%3}, [%4];"
                 : "=r"(d[0]), "=r"(d[1]), "=r"(d[2]), "=r"(d[3]) : "r"(addr));
}
__device__ __forceinline__ void ldm4t(uint32_t* d, uint32_t addr) {
    asm volatile("ldmatrix.sync.aligned.m8n8.x4.trans.shared.b16 {%0,%1,%2,%3}, [%4];"
                 : "=r"(d[0]), "=r"(d[1]), "=r"(d[2]), "=r"(d[3]) : "r"(addr));
}
__device__ __forceinline__ void mma16816(float* c, const uint32_t* a,
                                         uint32_t b0, uint32_t b1) {
    asm volatile(
        "mma.sync.aligned.m16n8k16.row.col.f32.bf16.bf16.f32 "
        "{%0,%1,%2,%3}, {%4,%5,%6,%7}, {%8,%9}, {%0,%1,%2,%3};"
        : "+f"(c[0]), "+f"(c[1]), "+f"(c[2]), "+f"(c[3])
        : "r"(a[0]), "r"(a[1]), "r"(a[2]), "r"(a[3]), "r"(b0), "r"(b1));
}

// Shared tile geometry (128x128 bf16 tiles, padded)
#define KV_STRIDE_B 272                   // bytes per smem row (136 bf16)
#define KV_TILE_B   (128 * KV_STRIDE_B)   // 34816 bytes
#define STG_STRIDE  136                   // floats per staged row

// ==================================================================
// Kernel 1: per-row LN stats for s (rows of 512). One warp per row.
// ==================================================================
__global__ void stats_s_kernel(const float* __restrict__ s) {
    int row  = blockIdx.x * 8 + (threadIdx.x >> 5);
    int lane = threadIdx.x & 31;
    const float4* p = (const float4*)(s + (size_t)row * DTOK);
    float sum = 0.f, sq = 0.f;
#pragma unroll
    for (int j = 0; j < 4; j++) {
        float4 v = p[lane + 32 * j];
        sum += v.x + v.y + v.z + v.w;
        sq  += v.x * v.x + v.y * v.y + v.z * v.z + v.w * v.w;
    }
    sum = warp_sum(sum);
    sq  = warp_sum(sq);
    if (lane == 0) {
        float mu  = sum * (1.f / DTOK);
        float var = sq * (1.f / DTOK) - mu * mu;
        g_smu[row] = mu;
        g_srs[row] = rsqrtf(var + LNEPS);
    }
}

// ==================================================================
// Kernel 2 (mma.sync bf16 split): LN(a) + K = a_n @ w_k, V = a_n @ w_v.
// (unchanged from R5 — proven)
// ==================================================================
#define OFF_AHI  0
#define OFF_ALO  (OFF_AHI + KV_TILE_B)
#define OFF_WKHI (OFF_ALO + KV_TILE_B)
#define OFF_WKLO (OFF_WKHI + KV_TILE_B)
#define OFF_WVHI (OFF_WKLO + KV_TILE_B)
#define OFF_WVLO (OFF_WVHI + KV_TILE_B)
#define KV_SMEM  (OFF_WVLO + KV_TILE_B)   // 208896 bytes

__global__ void __launch_bounds__(256, 1)
kv_mma_kernel(const float* __restrict__ a, const float* __restrict__ wk,
              const float* __restrict__ wv, const float* __restrict__ lng,
              const float* __restrict__ lnb) {
    char* sm = dyn_smem;
    uint32_t sbase = smem_u32(sm);
    int tid = threadIdx.x;
    int warp = tid >> 5, lane = tid & 31;
    size_t rowbase = (size_t)blockIdx.x * 128;

    // ---- A tile: LN rows -> hi/lo bf16 ----
    float4 gln = ((const float4*)lng)[lane];
    float4 bln = ((const float4*)lnb)[lane];
    for (int r = warp; r < 128; r += 8) {
        float4 v = *(const float4*)(a + (rowbase + r) * DATOM + lane * 4);
        float sum = warp_sum(v.x + v.y + v.z + v.w);
        float sq  = warp_sum(v.x * v.x + v.y * v.y + v.z * v.z + v.w * v.w);
        float mu  = sum * (1.f / 128.f);
        float rs  = rsqrtf(sq * (1.f / 128.f) - mu * mu + LNEPS);
        float n0 = (v.x - mu) * rs * gln.x + bln.x;
        float n1 = (v.y - mu) * rs * gln.y + bln.y;
        float n2 = (v.z - mu) * rs * gln.z + bln.z;
        float n3 = (v.w - mu) * rs * gln.w + bln.w;
        float h0, l0, h1, l1, h2, l2, h3, l3;
        split_bf(n0, h0, l0); split_bf(n1, h1, l1);
        split_bf(n2, h2, l2); split_bf(n3, h3, l3);
        uint32_t off = (uint32_t)r * KV_STRIDE_B + lane * 8;
        *(uint32_t*)(sm + OFF_AHI + off)     = pack_bf2(h0, h1);
        *(uint32_t*)(sm + OFF_AHI + off + 4) = pack_bf2(h2, h3);
        *(uint32_t*)(sm + OFF_ALO + off)     = pack_bf2(l0, l1);
        *(uint32_t*)(sm + OFF_ALO + off + 4) = pack_bf2(l2, l3);
    }
    // ---- W tiles ----
#pragma unroll
    for (int t = 0; t < 16; t++) {
        int j  = tid + t * 256;
        int k  = j >> 5;
        int c4 = (j & 31) * 4;
        uint32_t off = (uint32_t)k * KV_STRIDE_B + c4 * 2;
        float4 v = *(const float4*)(wk + (size_t)k * DATOM + c4);
        float h0, l0, h1, l1, h2, l2, h3, l3;
        split_bf(v.x, h0, l0); split_bf(v.y, h1, l1);
        split_bf(v.z, h2, l2); split_bf(v.w, h3, l3);
        *(uint32_t*)(sm + OFF_WKHI + off)     = pack_bf2(h0, h1);
        *(uint32_t*)(sm + OFF_WKHI + off + 4) = pack_bf2(h2, h3);
        *(uint32_t*)(sm + OFF_WKLO + off)     = pack_bf2(l0, l1);
        *(uint32_t*)(sm + OFF_WKLO + off + 4) = pack_bf2(l2, l3);
        v = *(const float4*)(wv + (size_t)k * DATOM + c4);
        split_bf(v.x, h0, l0); split_bf(v.y, h1, l1);
        split_bf(v.z, h2, l2); split_bf(v.w, h3, l3);
        *(uint32_t*)(sm + OFF_WVHI + off)     = pack_bf2(h0, h1);
        *(uint32_t*)(sm + OFF_WVHI + off + 4) = pack_bf2(h2, h3);
        *(uint32_t*)(sm + OFF_WVLO + off)     = pack_bf2(l0, l1);
        *(uint32_t*)(sm + OFF_WVLO + off + 4) = pack_bf2(l2, l3);
    }
    __syncthreads();

    int wm = warp & 3;
    int wn = warp >> 2;
    int lr = lane & 15;
    int lc = lane >> 4;

    uint32_t aAddr = sbase + (uint32_t)(wm * 32 + lr) * KV_STRIDE_B + lc * 16;
    uint32_t bAddr = sbase + (uint32_t)lr * KV_STRIDE_B + (wn * 64 + lc * 8) * 2;

    const int woff_hi[2] = {OFF_WKHI, OFF_WVHI};
    const int woff_lo[2] = {OFF_WKLO, OFF_WVLO};
    const int stg_off[2] = {OFF_WKHI, OFF_WVHI};

#pragma unroll 1
    for (int o = 0; o < 2; o++) {
        float c[2][8][4];
#pragma unroll
        for (int mt = 0; mt < 2; mt++)
#pragma unroll
            for (int nt = 0; nt < 8; nt++)
#pragma unroll
                for (int e = 0; e < 4; e++) c[mt][nt][e] = 0.f;

#pragma unroll
        for (int ks = 0; ks < 8; ks++) {
            uint32_t ak = aAddr + ks * 32;
            uint32_t bk = bAddr + ks * 16 * KV_STRIDE_B;
            uint32_t aH[2][4], aL[2][4];
            ldm4(aH[0], ak + OFF_AHI);
            ldm4(aH[1], ak + OFF_AHI + 16 * KV_STRIDE_B);
            ldm4(aL[0], ak + OFF_ALO);
            ldm4(aL[1], ak + OFF_ALO + 16 * KV_STRIDE_B);
            uint32_t bH[4][4], bL[4][4];
#pragma unroll
            for (int i = 0; i < 4; i++) {
                ldm4t(bH[i], bk + woff_hi[o] + i * 32);
                ldm4t(bL[i], bk + woff_lo[o] + i * 32);
            }
#pragma unroll
            for (int mt = 0; mt < 2; mt++)
#pragma unroll
                for (int i = 0; i < 4; i++) {
                    mma16816(c[mt][2 * i],     aH[mt], bH[i][0], bH[i][1]);
                    mma16816(c[mt][2 * i + 1], aH[mt], bH[i][2], bH[i][3]);
                    mma16816(c[mt][2 * i],     aH[mt], bL[i][0], bL[i][1]);
                    mma16816(c[mt][2 * i + 1], aH[mt], bL[i][2], bL[i][3]);
                    mma16816(c[mt][2 * i],     aL[mt], bH[i][0], bH[i][1]);
                    mma16816(c[mt][2 * i + 1], aL[mt], bH[i][2], bH[i][3]);
                }
        }
        __syncthreads();
        float* stg = (float*)(sm + stg_off[o]);
        int cr = lane >> 2, cc2 = (lane & 3) * 2;
#pragma unroll
        for (int mt = 0; mt < 2; mt++) {
            int r0 = wm * 32 + mt * 16 + cr;
#pragma unroll
            for (int nt = 0; nt < 8; nt++) {
                int cc = wn * 64 + nt * 8 + cc2;
                *(float2*)&stg[r0 * STG_STRIDE + cc] =
                    make_float2(c[mt][nt][0], c[mt][nt][1]);
                *(float2*)&stg[(r0 + 8) * STG_STRIDE + cc] =
                    make_float2(c[mt][nt][2], c[mt][nt][3]);
            }
        }
        __syncthreads();
        float* dst = (o == 0) ? g_K : g_V;
#pragma unroll
        for (int t = 0; t < 16; t++) {
            int j  = tid + t * 256;
            int r  = j >> 5;
            int c4 = (j & 31) * 4;
            float4 v = *(float4*)&stg[r * STG_STRIDE + c4];
            *(float4*)&dst[(rowbase + r) * DATOM + c4] = v;
        }
    }
}

// ==================================================================
// Kernel 3 (mma.sync bf16 split): LN(s) + [Q|G] = s_n @ [w_q|w_g].
// Grid (NTOK/128, 2): blockIdx.y = 0 -> Q (w_q), 1 -> G (w_g).
// K = 512 in 4 accumulating chunks of 128. Tile/warp layout = kv kernel.
// SMEM: A_hi/A_lo + B_hi/B_lo (4 x 34816 = 139264 B).
// ==================================================================
#define OFF_BHI  (2 * KV_TILE_B)
#define OFF_BLO  (3 * KV_TILE_B)
#define MM4_SMEM (4 * KV_TILE_B)    // 139264 bytes

__global__ void __launch_bounds__(256, 1)
qg_mma_kernel(const float* __restrict__ s, const float* __restrict__ wq,
              const float* __restrict__ wg, const float* __restrict__ lng,
              const float* __restrict__ lnb) {
    char* sm = dyn_smem;
    uint32_t sbase = smem_u32(sm);
    int tid = threadIdx.x;
    int warp = tid >> 5, lane = tid & 31;
    size_t rowbase = (size_t)blockIdx.x * 128;
    const float* w = (blockIdx.y == 0) ? wq : wg;
    float* dst     = (blockIdx.y == 0) ? g_Q : g_G;

    int wm = warp & 3;
    int wn = warp >> 2;
    int lr = lane & 15;
    int lc = lane >> 4;
    uint32_t aAddr = sbase + (uint32_t)(wm * 32 + lr) * KV_STRIDE_B + lc * 16;
    uint32_t bAddr = sbase + (uint32_t)lr * KV_STRIDE_B + (wn * 64 + lc * 8) * 2;

    float c[2][8][4];
#pragma unroll
    for (int mt = 0; mt < 2; mt++)
#pragma unroll
        for (int nt = 0; nt < 8; nt++)
#pragma unroll
            for (int e = 0; e < 4; e++) c[mt][nt][e] = 0.f;

#pragma unroll 1
    for (int kc = 0; kc < 4; kc++) {
        int k0 = kc * 128;
        // ---- A tile: LN(s) chunk -> hi/lo ----
#pragma unroll
        for (int t = 0; t < 16; t++) {
            int j   = tid + t * 256;
            int row = j >> 5;
            int c4  = (j & 31) * 4;
            float4 v = *(const float4*)(s + (rowbase + row) * DTOK + k0 + c4);
            float mu = g_smu[rowbase + row];
            float rs = g_srs[rowbase + row];
            float4 gv = *(const float4*)(lng + k0 + c4);
            float4 bv = *(const float4*)(lnb + k0 + c4);
            float n0 = (v.x - mu) * rs * gv.x + bv.x;
            float n1 = (v.y - mu) * rs * gv.y + bv.y;
            float n2 = (v.z - mu) * rs * gv.z + bv.z;
            float n3 = (v.w - mu) * rs * gv.w + bv.w;
            float h0, l0, h1, l1, h2, l2, h3, l3;
            split_bf(n0, h0, l0); split_bf(n1, h1, l1);
            split_bf(n2, h2, l2); split_bf(n3, h3, l3);
            uint32_t off = (uint32_t)row * KV_STRIDE_B + c4 * 2;
            *(uint32_t*)(sm + OFF_AHI + off)     = pack_bf2(h0, h1);
            *(uint32_t*)(sm + OFF_AHI + off + 4) = pack_bf2(h2, h3);
            *(uint32_t*)(sm + OFF_ALO + off)     = pack_bf2(l0, l1);
            *(uint32_t*)(sm + OFF_ALO + off + 4) = pack_bf2(l2, l3);
        }
        // ---- B tile: w rows k0..k0+127 ----
#pragma unroll
        for (int t = 0; t < 16; t++) {
            int j  = tid + t * 256;
            int k  = j >> 5;
            int c4 = (j & 31) * 4;
            uint32_t off = (uint32_t)k * KV_STRIDE_B + c4 * 2;
            float4 v = *(const float4*)(w + (size_t)(k0 + k) * DATOM + c4);
            float h0, l0, h1, l1, h2, l2, h3, l3;
            split_bf(v.x, h0, l0); split_bf(v.y, h1, l1);
            split_bf(v.z, h2, l2); split_bf(v.w, h3, l3);
            *(uint32_t*)(sm + OFF_BHI + off)     = pack_bf2(h0, h1);
            *(uint32_t*)(sm + OFF_BHI + off + 4) = pack_bf2(h2, h3);
            *(uint32_t*)(sm + OFF_BLO + off)     = pack_bf2(l0, l1);
            *(uint32_t*)(sm + OFF_BLO + off + 4) = pack_bf2(l2, l3);
        }
        __syncthreads();
#pragma unroll
        for (int ks = 0; ks < 8; ks++) {
            uint32_t ak = aAddr + ks * 32;
            uint32_t bk = bAddr + ks * 16 * KV_STRIDE_B;
            uint32_t aH[2][4], aL[2][4];
            ldm4(aH[0], ak + OFF_AHI);
            ldm4(aH[1], ak + OFF_AHI + 16 * KV_STRIDE_B);
            ldm4(aL[0], ak + OFF_ALO);
            ldm4(aL[1], ak + OFF_ALO + 16 * KV_STRIDE_B);
            uint32_t bH[4][4], bL[4][4];
#pragma unroll
            for (int i = 0; i < 4; i++) {
                ldm4t(bH[i], bk + OFF_BHI + i * 32);
                ldm4t(bL[i], bk + OFF_BLO + i * 32);
            }
#pragma unroll
            for (int mt = 0; mt < 2; mt++)
#pragma unroll
                for (int i = 0; i < 4; i++) {
                    mma16816(c[mt][2 * i],     aH[mt], bH[i][0], bH[i][1]);
                    mma16816(c[mt][2 * i + 1], aH[mt], bH[i][2], bH[i][3]);
                    mma16816(c[mt][2 * i],     aH[mt], bL[i][0], bL[i][1]);
                    mma16816(c[mt][2 * i + 1], aH[mt], bL[i][2], bL[i][3]);
                    mma16816(c[mt][2 * i],     aL[mt], bH[i][0], bH[i][1]);
                    mma16816(c[mt][2 * i + 1], aL[mt], bH[i][2], bH[i][3]);
                }
        }
        __syncthreads();
    }
    // ---- epilogue: stage into B region (69632 B) then coalesced write ----
    {
        float* stg = (float*)(sm + OFF_BHI);
        int cr = lane >> 2, cc2 = (lane & 3) * 2;
#pragma unroll
        for (int mt = 0; mt < 2; mt++) {
            int r0 = wm * 32 + mt * 16 + cr;
#pragma unroll
            for (int nt = 0; nt < 8; nt++) {
                int cc = wn * 64 + nt * 8 + cc2;
                *(float2*)&stg[r0 * STG_STRIDE + cc] =
                    make_float2(c[mt][nt][0], c[mt][nt][1]);
                *(float2*)&stg[(r0 + 8) * STG_STRIDE + cc] =
                    make_float2(c[mt][nt][2], c[mt][nt][3]);
            }
        }
        __syncthreads();
#pragma unroll
        for (int t = 0; t < 16; t++) {
            int j  = tid + t * 256;
            int r  = j >> 5;
            int c4 = (j & 31) * 4;
            float4 v = *(float4*)&stg[r * STG_STRIDE + c4];
            *(float4*)&dst[(rowbase + r) * DATOM + c4] = v;
        }
    }
}

// ==================================================================
// Kernel 4: ragged window attention + gate. Thread = (token, head).
// (unchanged from R5)
// ==================================================================
__global__ void __launch_bounds__(256, 1)
attn_gate_kernel(const int* __restrict__ starts, const int* __restrict__ counts,
                 const float* __restrict__ tmask) {
    __shared__ float sc[WMAX][256];
    int tid = threadIdx.x;
    int gt  = blockIdx.x * 256 + tid;
    int bt  = gt >> 2;
    int h   = gt & 3;
    int b   = bt >> 12;
    int start = starts[bt];
    int count = counts[bt];
    const float scale = 0.17677669529663687f;   // 1/sqrt(32)

    float4 q[8];
    const float4* qp = (const float4*)(g_Q + (size_t)bt * DATOM + h * DH);
#pragma unroll
    for (int j = 0; j < 8; j++) q[j] = qp[j];

    const float* kb = g_K + ((size_t)b * MM + start) * DATOM + h * DH;
    for (int w = 0; w < count; w++) {
        const float4* kr = (const float4*)(kb + (size_t)w * DATOM);
        float d = 0.f;
#pragma unroll
        for (int j = 0; j < 8; j++) {
            float4 kv = kr[j];
            d = fmaf(q[j].x, kv.x, d);
            d = fmaf(q[j].y, kv.y, d);
            d = fmaf(q[j].z, kv.z, d);
            d = fmaf(q[j].w, kv.w, d);
        }
        sc[w][tid] = d * scale;
    }
    float m = -1e30f;
    for (int w = 0; w < count; w++) m = fmaxf(m, sc[w][tid]);
    float sum = 0.f;
    for (int w = 0; w < count; w++) {
        float e = expf(sc[w][tid] - m);
        sc[w][tid] = e;
        sum += e;
    }
    float inv = 1.f / sum;

    float4 acc[8];
#pragma unroll
    for (int j = 0; j < 8; j++) acc[j] = make_float4(0.f, 0.f, 0.f, 0.f);
    const float* vb = g_V + ((size_t)b * MM + start) * DATOM + h * DH;
    for (int w = 0; w < count; w++) {
        float p = sc[w][tid] * inv;
        const float4* vr = (const float4*)(vb + (size_t)w * DATOM);
#pragma unroll
        for (int j = 0; j < 8; j++) {
            float4 vv = vr[j];
            acc[j].x = fmaf(p, vv.x, acc[j].x);
            acc[j].y = fmaf(p, vv.y, acc[j].y);
            acc[j].z = fmaf(p, vv.z, acc[j].z);
            acc[j].w = fmaf(p, vv.w, acc[j].w);
        }
    }
    float msk = tmask[bt];
    const float4* gp = (const float4*)(g_G + (size_t)bt * DATOM + h * DH);
    float4* up = (float4*)(g_U + (size_t)bt * DATOM + h * DH);
#pragma unroll
    for (int j = 0; j < 8; j++) {
        float4 gv = gp[j];
        float4 u;
        u.x = acc[j].x * msk / (1.f + expf(-gv.x));
        u.y = acc[j].y * msk / (1.f + expf(-gv.y));
        u.z = acc[j].z * msk / (1.f + expf(-gv.z));
        u.w = acc[j].w * msk / (1.f + expf(-gv.w));
        up[j] = u;
    }
}

// ==================================================================
// Kernel 5 (mma.sync bf16 split): out = U @ w_o (16384x128 @ 128x512).
// Grid (NTOK/128, 4): blockIdx.y = col quarter. K = 128 single chunk.
// ==================================================================
__global__ void __launch_bounds__(256, 1)
out_mma_kernel(const float* __restrict__ wo, float* __restrict__ out) {
    char* sm = dyn_smem;
    uint32_t sbase = smem_u32(sm);
    int tid = threadIdx.x;
    int warp = tid >> 5, lane = tid & 31;
    size_t rowbase = (size_t)blockIdx.x * 128;
    int colbase = blockIdx.y * 128;

    // ---- A tile: g_U rows -> hi/lo ----
#pragma unroll
    for (int t = 0; t < 16; t++) {
        int j   = tid + t * 256;
        int row = j >> 5;
        int c4  = (j & 31) * 4;
        float4 v = *(const float4*)(g_U + (rowbase + row) * DATOM + c4);
        float h0, l0, h1, l1, h2, l2, h3, l3;
        split_bf(v.x, h0, l0); split_bf(v.y, h1, l1);
        split_bf(v.z, h2, l2); split_bf(v.w, h3, l3);
        uint32_t off = (uint32_t)row * KV_STRIDE_B + c4 * 2;
        *(uint32_t*)(sm + OFF_AHI + off)     = pack_bf2(h0, h1);
        *(uint32_t*)(sm + OFF_AHI + off + 4) = pack_bf2(h2, h3);
        *(uint32_t*)(sm + OFF_ALO + off)     = pack_bf2(l0, l1);
        *(uint32_t*)(sm + OFF_ALO + off + 4) = pack_bf2(l2, l3);
    }
    // ---- B tile: wo[k][colbase + 0..127] ----
#pragma unroll
    for (int t = 0; t < 16; t++) {
        int j  = tid + t * 256;
        int k  = j >> 5;
        int c4 = (j & 31) * 4;
        uint32_t off = (uint32_t)k * KV_STRIDE_B + c4 * 2;
        float4 v = *(const float4*)(wo + (size_t)k * DTOK + colbase + c4);
        float h0, l0, h1, l1, h2, l2, h3, l3;
        split_bf(v.x, h0, l0); split_bf(v.y, h1, l1);
        split_bf(v.z, h2, l2); split_bf(v.w, h3, l3);
        *(uint32_t*)(sm + OFF_BHI + off)     = pack_bf2(h0, h1);
        *(uint32_t*)(sm + OFF_BHI + off + 4) = pack_bf2(h2, h3);
        *(uint32_t*)(sm + OFF_BLO + off)     = pack_bf2(l0, l1);
        *(uint32_t*)(sm + OFF_BLO + off + 4) = pack_bf2(l2, l3);
    }
    __syncthreads();

    int wm = warp & 3;
    int wn = warp >> 2;
    int lr = lane & 15;
    int lc = lane >> 4;
    uint32_t aAddr = sbase + (uint32_t)(wm * 32 + lr) * KV_STRIDE_B + lc * 16;
    uint32_t bAddr = sbase + (uint32_t)lr * KV_STRIDE_B + (wn * 64 + lc * 8) * 2;

    float c[2][8][4];
#pragma unroll
    for (int mt = 0; mt < 2; mt++)
#pragma unroll
        for (int nt = 0; nt < 8; nt++)
#pragma unroll
            for (int e = 0; e < 4; e++) c[mt][nt][e] = 0.f;

#pragma unroll
    for (int ks = 0; ks < 8; ks++) {
        uint32_t ak = aAddr + ks * 32;
        uint32_t bk = bAddr + ks * 16 * KV_STRIDE_B;
        uint32_t aH[2][4], aL[2][4];
        ldm4(aH[0], ak + OFF_AHI);
        ldm4(aH[1], ak + OFF_AHI + 16 * KV_STRIDE_B);
        ldm4(aL[0], ak + OFF_ALO);
        ldm4(aL[1], ak + OFF_ALO + 16 * KV_STRIDE_B);
        uint32_t bH[4][4], bL[4][4];
#pragma unroll
        for (int i = 0; i < 4; i++) {
            ldm4t(bH[i], bk + OFF_BHI + i * 32);
            ldm4t(bL[i], bk + OFF_BLO + i * 32);
        }
#pragma unroll
        for (int mt = 0; mt < 2; mt++)
#pragma unroll
            for (int i = 0; i < 4; i++) {
                mma16816(c[mt][2 * i],     aH[mt], bH[i][0], bH[i][1]);
                mma16816(c[mt][2 * i + 1], aH[mt], bH[i][2], bH[i][3]);
                mma16816(c[mt][2 * i],     aH[mt], bL[i][0], bL[i][1]);
                mma16816(c[mt][2 * i + 1], aH[mt], bL[i][2], bL[i][3]);
                mma16816(c[mt][2 * i],     aL[mt], bH[i][0], bH[i][1]);
                mma16816(c[mt][2 * i + 1], aL[mt], bH[i][2], bH[i][3]);
            }
    }
    __syncthreads();
    // ---- epilogue: stage + coalesced write ----
    {
        float* stg = (float*)(sm + OFF_BHI);
        int cr = lane >> 2, cc2 = (lane & 3) * 2;
#pragma unroll
        for (int mt = 0; mt < 2; mt++) {
            int r0 = wm * 32 + mt * 16 + cr;
#pragma unroll
            for (int nt = 0; nt < 8; nt++) {
                int cc = wn * 64 + nt * 8 + cc2;
                *(float2*)&stg[r0 * STG_STRIDE + cc] =
                    make_float2(c[mt][nt][0], c[mt][nt][1]);
                *(float2*)&stg[(r0 + 8) * STG_STRIDE + cc] =
                    make_float2(c[mt][nt][2], c[mt][nt][3]);
            }
        }
        __syncthreads();
#pragma unroll
        for (int t = 0; t < 16; t++) {
            int j  = tid + t * 256;
            int r  = j >> 5;
            int c4 = (j & 31) * 4;
            float4 v = *(float4*)&stg[r * STG_STRIDE + c4];
            *(float4*)&out[(rowbase + r) * DTOK + colbase + c4] = v;
        }
    }
}

// ==================================================================
// Launch. Input order: s, a, starts, counts, token_mask, w_q, w_k,
// w_v, w_g, w_o, ln_q_g, ln_q_b, ln_kv_g, ln_kv_b. Output fp32.
// ==================================================================
extern "C" void kernel_launch(void* const* d_in, const int* in_sizes, int n_in,
                              void* d_out, int out_size) {
    const float* s      = (const float*)d_in[0];
    const float* a      = (const float*)d_in[1];
    const int*   starts = (const int*)  d_in[2];
    const int*   counts = (const int*)  d_in[3];
    const float* tmask  = (const float*)d_in[4];
    const float* wq     = (const float*)d_in[5];
    const float* wk     = (const float*)d_in[6];
    const float* wv     = (const float*)d_in[7];
    const float* wg     = (const float*)d_in[8];
    const float* wo     = (const float*)d_in[9];
    const float* lnqg   = (const float*)d_in[10];
    const float* lnqb   = (const float*)d_in[11];
    const float* lnkg   = (const float*)d_in[12];
    const float* lnkb   = (const float*)d_in[13];
    float* out = (float*)d_out;

    cudaFuncSetAttribute(kv_mma_kernel,
                         cudaFuncAttributeMaxDynamicSharedMemorySize, KV_SMEM);
    cudaFuncSetAttribute(qg_mma_kernel,
                         cudaFuncAttributeMaxDynamicSharedMemorySize, MM4_SMEM);
    cudaFuncSetAttribute(out_mma_kernel,
                         cudaFuncAttributeMaxDynamicSharedMemorySize, MM4_SMEM);

    stats_s_kernel<<<NTOK / 8, 256>>>(s);
    kv_mma_kernel<<<NATOM / 128, 256, KV_SMEM>>>(a, wk, wv, lnkg, lnkb);
    qg_mma_kernel<<<dim3(NTOK / 128, 2), 256, MM4_SMEM>>>(s, wq, wg, lnqg, lnqb);
    attn_gate_kernel<<<NTOK * NHEAD / 256, 256>>>(starts, counts, tmask);
    out_mma_kernel<<<dim3(NTOK / 128, 4), 256, MM4_SMEM>>>(wo, out);
}

// round 7
// speedup vs baseline: 2.1617x; 1.0749x over previous
#include <cuda_runtime.h>
#include <cuda_bf16.h>
#include <cstdint>
#include <math.h>

// Problem constants
#define BB     4
#define NN     4096
#define MM     32768
#define DTOK   512
#define DATOM  128
#define NHEAD  4
#define DH     32
#define WMAX   16
#define LNEPS  1e-5f

#define NTOK   (BB * NN)    // 16384 token rows
#define NATOM  (BB * MM)    // 131072 atom rows

// Single dynamic smem symbol shared by all kernels (cast locally).
extern __shared__ char dyn_smem[];

// -------- scratch (device globals; no allocations allowed) --------
__device__ float g_K[(size_t)NATOM * DATOM];
__device__ float g_V[(size_t)NATOM * DATOM];
__device__ float g_Q[(size_t)NTOK * DATOM];
__device__ float g_G[(size_t)NTOK * DATOM];
__device__ float g_U[(size_t)NTOK * DATOM];
__device__ float g_smu[NTOK];
__device__ float g_srs[NTOK];

__device__ __forceinline__ float warp_sum(float v) {
#pragma unroll
    for (int o = 16; o > 0; o >>= 1) v += __shfl_xor_sync(0xffffffffu, v, o);
    return v;
}
__device__ __forceinline__ uint32_t smem_u32(const void* p) {
    uint32_t a;
    asm("{ .reg .u64 t; cvta.to.shared.u64 t, %1; cvt.u32.u64 %0, t; }"
        : "=r"(a) : "l"(p));
    return a;
}
__device__ __forceinline__ uint32_t pack_bf2(float a, float b) {
    __nv_bfloat162 t = __floats2bfloat162_rn(a, b);
    return *(uint32_t*)&t;
}
// hi = bf16 round of x; lo = x - hi
__device__ __forceinline__ void split_bf(float x, float& hi, float& lo) {
    __nv_bfloat16 h = __float2bfloat16(x);
    hi = __bfloat162float(h);
    lo = x - hi;
}

// ---- warp-level MMA helpers (sm_80+, works on sm_100 base target) ----
__device__ __forceinline__ void ldm4(uint32_t* d, uint32_t addr) {
    asm volatile("ldmatrix.sync.aligned.m8n8.x4.shared.b16 {%0,%1,%2,%3}, [%4];"
                 : "=r"(d[0]), "=r"(d[1]), "=r"(d[2]), "=r"(d[3]) : "r"(addr));
}
__device__ __forceinline__ void ldm4t(uint32_t* d, uint32_t addr) {
    asm volatile("ldmatrix.sync.aligned.m8n8.x4.trans.shared.b16 {%0,%1,%2,%3}, [%4];"
                 : "=r"(d[0]), "=r"(d[1]), "=r"(d[2]), "=r"(d[3]) : "r"(addr));
}
__device__ __forceinline__ void mma16816(float* c, const uint32_t* a,
                                         uint32_t b0, uint32_t b1) {
    asm volatile(
        "mma.sync.aligned.m16n8k16.row.col.f32.bf16.bf16.f32 "
        "{%0,%1,%2,%3}, {%4,%5,%6,%7}, {%8,%9}, {%0,%1,%2,%3};"
        : "+f"(c[0]), "+f"(c[1]), "+f"(c[2]), "+f"(c[3])
        : "r"(a[0]), "r"(a[1]), "r"(a[2]), "r"(a[3]), "r"(b0), "r"(b1));
}

// Shared tile geometry (128x128 bf16 tiles, padded)
#define KV_STRIDE_B 272                   // bytes per smem row (136 bf16)
#define KV_TILE_B   (128 * KV_STRIDE_B)   // 34816 bytes
#define STG_STRIDE  136                   // floats per staged row

// ==================================================================
// Kernel 1: per-row LN stats for s (rows of 512). One warp per row.
// ==================================================================
__global__ void stats_s_kernel(const float* __restrict__ s) {
    int row  = blockIdx.x * 8 + (threadIdx.x >> 5);
    int lane = threadIdx.x & 31;
    const float4* p = (const float4*)(s + (size_t)row * DTOK);
    float sum = 0.f, sq = 0.f;
#pragma unroll
    for (int j = 0; j < 4; j++) {
        float4 v = p[lane + 32 * j];
        sum += v.x + v.y + v.z + v.w;
        sq  += v.x * v.x + v.y * v.y + v.z * v.z + v.w * v.w;
    }
    sum = warp_sum(sum);
    sq  = warp_sum(sq);
    if (lane == 0) {
        float mu  = sum * (1.f / DTOK);
        float var = sq * (1.f / DTOK) - mu * mu;
        g_smu[row] = mu;
        g_srs[row] = rsqrtf(var + LNEPS);
    }
}

// ==================================================================
// Kernel 2 (mma.sync bf16 split): LN(a) + K = a_n @ w_k, V = a_n @ w_v.
// Fused mainloop: A fragments loaded once per ks, used for both K and V.
// ==================================================================
#define OFF_AHI  0
#define OFF_ALO  (OFF_AHI + KV_TILE_B)
#define OFF_WKHI (OFF_ALO + KV_TILE_B)
#define OFF_WKLO (OFF_WKHI + KV_TILE_B)
#define OFF_WVHI (OFF_WKLO + KV_TILE_B)
#define OFF_WVLO (OFF_WVHI + KV_TILE_B)
#define KV_SMEM  (OFF_WVLO + KV_TILE_B)   // 208896 bytes

__global__ void __launch_bounds__(256, 1)
kv_mma_kernel(const float* __restrict__ a, const float* __restrict__ wk,
              const float* __restrict__ wv, const float* __restrict__ lng,
              const float* __restrict__ lnb) {
    char* sm = dyn_smem;
    uint32_t sbase = smem_u32(sm);
    int tid = threadIdx.x;
    int warp = tid >> 5, lane = tid & 31;
    size_t rowbase = (size_t)blockIdx.x * 128;

    // ---- A tile: LN rows -> hi/lo bf16 ----
    float4 gln = ((const float4*)lng)[lane];
    float4 bln = ((const float4*)lnb)[lane];
    for (int r = warp; r < 128; r += 8) {
        float4 v = *(const float4*)(a + (rowbase + r) * DATOM + lane * 4);
        float sum = warp_sum(v.x + v.y + v.z + v.w);
        float sq  = warp_sum(v.x * v.x + v.y * v.y + v.z * v.z + v.w * v.w);
        float mu  = sum * (1.f / 128.f);
        float rs  = rsqrtf(sq * (1.f / 128.f) - mu * mu + LNEPS);
        float n0 = (v.x - mu) * rs * gln.x + bln.x;
        float n1 = (v.y - mu) * rs * gln.y + bln.y;
        float n2 = (v.z - mu) * rs * gln.z + bln.z;
        float n3 = (v.w - mu) * rs * gln.w + bln.w;
        float h0, l0, h1, l1, h2, l2, h3, l3;
        split_bf(n0, h0, l0); split_bf(n1, h1, l1);
        split_bf(n2, h2, l2); split_bf(n3, h3, l3);
        uint32_t off = (uint32_t)r * KV_STRIDE_B + lane * 8;
        *(uint32_t*)(sm + OFF_AHI + off)     = pack_bf2(h0, h1);
        *(uint32_t*)(sm + OFF_AHI + off + 4) = pack_bf2(h2, h3);
        *(uint32_t*)(sm + OFF_ALO + off)     = pack_bf2(l0, l1);
        *(uint32_t*)(sm + OFF_ALO + off + 4) = pack_bf2(l2, l3);
    }
    // ---- W tiles ----
#pragma unroll
    for (int t = 0; t < 16; t++) {
        int j  = tid + t * 256;
        int k  = j >> 5;
        int c4 = (j & 31) * 4;
        uint32_t off = (uint32_t)k * KV_STRIDE_B + c4 * 2;
        float4 v = *(const float4*)(wk + (size_t)k * DATOM + c4);
        float h0, l0, h1, l1, h2, l2, h3, l3;
        split_bf(v.x, h0, l0); split_bf(v.y, h1, l1);
        split_bf(v.z, h2, l2); split_bf(v.w, h3, l3);
        *(uint32_t*)(sm + OFF_WKHI + off)     = pack_bf2(h0, h1);
        *(uint32_t*)(sm + OFF_WKHI + off + 4) = pack_bf2(h2, h3);
        *(uint32_t*)(sm + OFF_WKLO + off)     = pack_bf2(l0, l1);
        *(uint32_t*)(sm + OFF_WKLO + off + 4) = pack_bf2(l2, l3);
        v = *(const float4*)(wv + (size_t)k * DATOM + c4);
        split_bf(v.x, h0, l0); split_bf(v.y, h1, l1);
        split_bf(v.z, h2, l2); split_bf(v.w, h3, l3);
        *(uint32_t*)(sm + OFF_WVHI + off)     = pack_bf2(h0, h1);
        *(uint32_t*)(sm + OFF_WVHI + off + 4) = pack_bf2(h2, h3);
        *(uint32_t*)(sm + OFF_WVLO + off)     = pack_bf2(l0, l1);
        *(uint32_t*)(sm + OFF_WVLO + off + 4) = pack_bf2(l2, l3);
    }
    __syncthreads();

    int wm = warp & 3;
    int wn = warp >> 2;
    int lr = lane & 15;
    int lc = lane >> 4;

    uint32_t aAddr = sbase + (uint32_t)(wm * 32 + lr) * KV_STRIDE_B + lc * 16;
    uint32_t bAddr = sbase + (uint32_t)lr * KV_STRIDE_B + (wn * 64 + lc * 8) * 2;

    float cK[2][8][4], cV[2][8][4];
#pragma unroll
    for (int mt = 0; mt < 2; mt++)
#pragma unroll
        for (int nt = 0; nt < 8; nt++)
#pragma unroll
            for (int e = 0; e < 4; e++) { cK[mt][nt][e] = 0.f; cV[mt][nt][e] = 0.f; }

#pragma unroll
    for (int ks = 0; ks < 8; ks++) {
        uint32_t ak = aAddr + ks * 32;
        uint32_t bk = bAddr + ks * 16 * KV_STRIDE_B;
        uint32_t aH[2][4], aL[2][4];
        ldm4(aH[0], ak + OFF_AHI);
        ldm4(aH[1], ak + OFF_AHI + 16 * KV_STRIDE_B);
        ldm4(aL[0], ak + OFF_ALO);
        ldm4(aL[1], ak + OFF_ALO + 16 * KV_STRIDE_B);
        // ---- K output ----
        {
            uint32_t bH[4][4], bL[4][4];
#pragma unroll
            for (int i = 0; i < 4; i++) {
                ldm4t(bH[i], bk + OFF_WKHI + i * 32);
                ldm4t(bL[i], bk + OFF_WKLO + i * 32);
            }
#pragma unroll
            for (int mt = 0; mt < 2; mt++)
#pragma unroll
                for (int i = 0; i < 4; i++) {
                    mma16816(cK[mt][2 * i],     aH[mt], bH[i][0], bH[i][1]);
                    mma16816(cK[mt][2 * i + 1], aH[mt], bH[i][2], bH[i][3]);
                    mma16816(cK[mt][2 * i],     aH[mt], bL[i][0], bL[i][1]);
                    mma16816(cK[mt][2 * i + 1], aH[mt], bL[i][2], bL[i][3]);
                    mma16816(cK[mt][2 * i],     aL[mt], bH[i][0], bH[i][1]);
                    mma16816(cK[mt][2 * i + 1], aL[mt], bH[i][2], bH[i][3]);
                }
        }
        // ---- V output ----
        {
            uint32_t bH[4][4], bL[4][4];
#pragma unroll
            for (int i = 0; i < 4; i++) {
                ldm4t(bH[i], bk + OFF_WVHI + i * 32);
                ldm4t(bL[i], bk + OFF_WVLO + i * 32);
            }
#pragma unroll
            for (int mt = 0; mt < 2; mt++)
#pragma unroll
                for (int i = 0; i < 4; i++) {
                    mma16816(cV[mt][2 * i],     aH[mt], bH[i][0], bH[i][1]);
                    mma16816(cV[mt][2 * i + 1], aH[mt], bH[i][2], bH[i][3]);
                    mma16816(cV[mt][2 * i],     aH[mt], bL[i][0], bL[i][1]);
                    mma16816(cV[mt][2 * i + 1], aH[mt], bL[i][2], bL[i][3]);
                    mma16816(cV[mt][2 * i],     aL[mt], bH[i][0], bH[i][1]);
                    mma16816(cV[mt][2 * i + 1], aL[mt], bH[i][2], bH[i][3]);
                }
        }
    }
    __syncthreads();   // mainloop reads done; reuse WK/WV regions for staging
    {
        float* stgK = (float*)(sm + OFF_WKHI);   // 69632 B
        float* stgV = (float*)(sm + OFF_WVHI);   // 69632 B
        int cr = lane >> 2, cc2 = (lane & 3) * 2;
#pragma unroll
        for (int mt = 0; mt < 2; mt++) {
            int r0 = wm * 32 + mt * 16 + cr;
#pragma unroll
            for (int nt = 0; nt < 8; nt++) {
                int cc = wn * 64 + nt * 8 + cc2;
                *(float2*)&stgK[r0 * STG_STRIDE + cc] =
                    make_float2(cK[mt][nt][0], cK[mt][nt][1]);
                *(float2*)&stgK[(r0 + 8) * STG_STRIDE + cc] =
                    make_float2(cK[mt][nt][2], cK[mt][nt][3]);
                *(float2*)&stgV[r0 * STG_STRIDE + cc] =
                    make_float2(cV[mt][nt][0], cV[mt][nt][1]);
                *(float2*)&stgV[(r0 + 8) * STG_STRIDE + cc] =
                    make_float2(cV[mt][nt][2], cV[mt][nt][3]);
            }
        }
        __syncthreads();
#pragma unroll
        for (int t = 0; t < 16; t++) {
            int j  = tid + t * 256;
            int r  = j >> 5;
            int c4 = (j & 31) * 4;
            *(float4*)&g_K[(rowbase + r) * DATOM + c4] =
                *(float4*)&stgK[r * STG_STRIDE + c4];
            *(float4*)&g_V[(rowbase + r) * DATOM + c4] =
                *(float4*)&stgV[r * STG_STRIDE + c4];
        }
    }
}

// ==================================================================
// Kernel 3 (mma.sync bf16 split): LN(s) + [Q|G] = s_n @ [w_q|w_g].
// (unchanged from R6 — proven)
// ==================================================================
#define OFF_BHI  (2 * KV_TILE_B)
#define OFF_BLO  (3 * KV_TILE_B)
#define MM4_SMEM (4 * KV_TILE_B)    // 139264 bytes

__global__ void __launch_bounds__(256, 1)
qg_mma_kernel(const float* __restrict__ s, const float* __restrict__ wq,
              const float* __restrict__ wg, const float* __restrict__ lng,
              const float* __restrict__ lnb) {
    char* sm = dyn_smem;
    uint32_t sbase = smem_u32(sm);
    int tid = threadIdx.x;
    int warp = tid >> 5, lane = tid & 31;
    size_t rowbase = (size_t)blockIdx.x * 128;
    const float* w = (blockIdx.y == 0) ? wq : wg;
    float* dst     = (blockIdx.y == 0) ? g_Q : g_G;

    int wm = warp & 3;
    int wn = warp >> 2;
    int lr = lane & 15;
    int lc = lane >> 4;
    uint32_t aAddr = sbase + (uint32_t)(wm * 32 + lr) * KV_STRIDE_B + lc * 16;
    uint32_t bAddr = sbase + (uint32_t)lr * KV_STRIDE_B + (wn * 64 + lc * 8) * 2;

    float c[2][8][4];
#pragma unroll
    for (int mt = 0; mt < 2; mt++)
#pragma unroll
        for (int nt = 0; nt < 8; nt++)
#pragma unroll
            for (int e = 0; e < 4; e++) c[mt][nt][e] = 0.f;

#pragma unroll 1
    for (int kc = 0; kc < 4; kc++) {
        int k0 = kc * 128;
#pragma unroll
        for (int t = 0; t < 16; t++) {
            int j   = tid + t * 256;
            int row = j >> 5;
            int c4  = (j & 31) * 4;
            float4 v = *(const float4*)(s + (rowbase + row) * DTOK + k0 + c4);
            float mu = g_smu[rowbase + row];
            float rs = g_srs[rowbase + row];
            float4 gv = *(const float4*)(lng + k0 + c4);
            float4 bv = *(const float4*)(lnb + k0 + c4);
            float n0 = (v.x - mu) * rs * gv.x + bv.x;
            float n1 = (v.y - mu) * rs * gv.y + bv.y;
            float n2 = (v.z - mu) * rs * gv.z + bv.z;
            float n3 = (v.w - mu) * rs * gv.w + bv.w;
            float h0, l0, h1, l1, h2, l2, h3, l3;
            split_bf(n0, h0, l0); split_bf(n1, h1, l1);
            split_bf(n2, h2, l2); split_bf(n3, h3, l3);
            uint32_t off = (uint32_t)row * KV_STRIDE_B + c4 * 2;
            *(uint32_t*)(sm + OFF_AHI + off)     = pack_bf2(h0, h1);
            *(uint32_t*)(sm + OFF_AHI + off + 4) = pack_bf2(h2, h3);
            *(uint32_t*)(sm + OFF_ALO + off)     = pack_bf2(l0, l1);
            *(uint32_t*)(sm + OFF_ALO + off + 4) = pack_bf2(l2, l3);
        }
#pragma unroll
        for (int t = 0; t < 16; t++) {
            int j  = tid + t * 256;
            int k  = j >> 5;
            int c4 = (j & 31) * 4;
            uint32_t off = (uint32_t)k * KV_STRIDE_B + c4 * 2;
            float4 v = *(const float4*)(w + (size_t)(k0 + k) * DATOM + c4);
            float h0, l0, h1, l1, h2, l2, h3, l3;
            split_bf(v.x, h0, l0); split_bf(v.y, h1, l1);
            split_bf(v.z, h2, l2); split_bf(v.w, h3, l3);
            *(uint32_t*)(sm + OFF_BHI + off)     = pack_bf2(h0, h1);
            *(uint32_t*)(sm + OFF_BHI + off + 4) = pack_bf2(h2, h3);
            *(uint32_t*)(sm + OFF_BLO + off)     = pack_bf2(l0, l1);
            *(uint32_t*)(sm + OFF_BLO + off + 4) = pack_bf2(l2, l3);
        }
        __syncthreads();
#pragma unroll
        for (int ks = 0; ks < 8; ks++) {
            uint32_t ak = aAddr + ks * 32;
            uint32_t bk = bAddr + ks * 16 * KV_STRIDE_B;
            uint32_t aH[2][4], aL[2][4];
            ldm4(aH[0], ak + OFF_AHI);
            ldm4(aH[1], ak + OFF_AHI + 16 * KV_STRIDE_B);
            ldm4(aL[0], ak + OFF_ALO);
            ldm4(aL[1], ak + OFF_ALO + 16 * KV_STRIDE_B);
            uint32_t bH[4][4], bL[4][4];
#pragma unroll
            for (int i = 0; i < 4; i++) {
                ldm4t(bH[i], bk + OFF_BHI + i * 32);
                ldm4t(bL[i], bk + OFF_BLO + i * 32);
            }
#pragma unroll
            for (int mt = 0; mt < 2; mt++)
#pragma unroll
                for (int i = 0; i < 4; i++) {
                    mma16816(c[mt][2 * i],     aH[mt], bH[i][0], bH[i][1]);
                    mma16816(c[mt][2 * i + 1], aH[mt], bH[i][2], bH[i][3]);
                    mma16816(c[mt][2 * i],     aH[mt], bL[i][0], bL[i][1]);
                    mma16816(c[mt][2 * i + 1], aH[mt], bL[i][2], bL[i][3]);
                    mma16816(c[mt][2 * i],     aL[mt], bH[i][0], bH[i][1]);
                    mma16816(c[mt][2 * i + 1], aL[mt], bH[i][2], bH[i][3]);
                }
        }
        __syncthreads();
    }
    {
        float* stg = (float*)(sm + OFF_BHI);
        int cr = lane >> 2, cc2 = (lane & 3) * 2;
#pragma unroll
        for (int mt = 0; mt < 2; mt++) {
            int r0 = wm * 32 + mt * 16 + cr;
#pragma unroll
            for (int nt = 0; nt < 8; nt++) {
                int cc = wn * 64 + nt * 8 + cc2;
                *(float2*)&stg[r0 * STG_STRIDE + cc] =
                    make_float2(c[mt][nt][0], c[mt][nt][1]);
                *(float2*)&stg[(r0 + 8) * STG_STRIDE + cc] =
                    make_float2(c[mt][nt][2], c[mt][nt][3]);
            }
        }
        __syncthreads();
#pragma unroll
        for (int t = 0; t < 16; t++) {
            int j  = tid + t * 256;
            int r  = j >> 5;
            int c4 = (j & 31) * 4;
            float4 v = *(float4*)&stg[r * STG_STRIDE + c4];
            *(float4*)&dst[(rowbase + r) * DATOM + c4] = v;
        }
    }
}

// ==================================================================
// Kernel 4: ragged window attention + gate. WARP PER TOKEN.
// Lane l owns dims [4l, 4l+4) of the 128-dim row (head = l>>3).
// All K/V/Q/G/U accesses fully coalesced (512B per warp).
// Head dot products via 3x shfl-xor within 8-lane groups.
// Fully unrolled over WMAX with predicated loads -> max MLP.
// ==================================================================
__global__ void __launch_bounds__(256, 8)
attn_gate_kernel(const int* __restrict__ starts, const int* __restrict__ counts,
                 const float* __restrict__ tmask) {
    int warp = threadIdx.x >> 5, lane = threadIdx.x & 31;
    int bt = blockIdx.x * 8 + warp;      // token index
    int b  = bt >> 12;                   // batch (N = 4096)
    int start = starts[bt];
    int count = counts[bt];
    const float scale = 0.17677669529663687f;   // 1/sqrt(32)

    float4 q = *(const float4*)(g_Q + (size_t)bt * DATOM + lane * 4);
    const float* kb = g_K + ((size_t)b * MM + start) * DATOM;

    float sc[WMAX];
#pragma unroll
    for (int w = 0; w < WMAX; w++) {
        float d = -1e30f;
        if (w < count) {
            float4 k4 = *(const float4*)(kb + (size_t)w * DATOM + lane * 4);
            float t = q.x * k4.x + q.y * k4.y + q.z * k4.z + q.w * k4.w;
            t += __shfl_xor_sync(0xffffffffu, t, 1);
            t += __shfl_xor_sync(0xffffffffu, t, 2);
            t += __shfl_xor_sync(0xffffffffu, t, 4);
            d = t * scale;
        }
        sc[w] = d;
    }
    float m = -1e30f;
#pragma unroll
    for (int w = 0; w < WMAX; w++) m = fmaxf(m, sc[w]);
    float sum = 0.f;
#pragma unroll
    for (int w = 0; w < WMAX; w++) { sc[w] = expf(sc[w] - m); sum += sc[w]; }
    float inv = 1.f / sum;

    const float* vb = g_V + ((size_t)b * MM + start) * DATOM;
    float4 acc = make_float4(0.f, 0.f, 0.f, 0.f);
#pragma unroll
    for (int w = 0; w < WMAX; w++) {
        if (w < count) {
            float p = sc[w] * inv;
            float4 v4 = *(const float4*)(vb + (size_t)w * DATOM + lane * 4);
            acc.x = fmaf(p, v4.x, acc.x);
            acc.y = fmaf(p, v4.y, acc.y);
            acc.z = fmaf(p, v4.z, acc.z);
            acc.w = fmaf(p, v4.w, acc.w);
        }
    }
    float msk = tmask[bt];
    float4 g = *(const float4*)(g_G + (size_t)bt * DATOM + lane * 4);
    float4 u;
    u.x = acc.x * msk / (1.f + expf(-g.x));
    u.y = acc.y * msk / (1.f + expf(-g.y));
    u.z = acc.z * msk / (1.f + expf(-g.z));
    u.w = acc.w * msk / (1.f + expf(-g.w));
    *(float4*)(g_U + (size_t)bt * DATOM + lane * 4) = u;
}

// ==================================================================
// Kernel 5 (mma.sync bf16 split): out = U @ w_o (16384x128 @ 128x512).
// (unchanged from R6 — proven)
// ==================================================================
__global__ void __launch_bounds__(256, 1)
out_mma_kernel(const float* __restrict__ wo, float* __restrict__ out) {
    char* sm = dyn_smem;
    uint32_t sbase = smem_u32(sm);
    int tid = threadIdx.x;
    int warp = tid >> 5, lane = tid & 31;
    size_t rowbase = (size_t)blockIdx.x * 128;
    int colbase = blockIdx.y * 128;

#pragma unroll
    for (int t = 0; t < 16; t++) {
        int j   = tid + t * 256;
        int row = j >> 5;
        int c4  = (j & 31) * 4;
        float4 v = *(const float4*)(g_U + (rowbase + row) * DATOM + c4);
        float h0, l0, h1, l1, h2, l2, h3, l3;
        split_bf(v.x, h0, l0); split_bf(v.y, h1, l1);
        split_bf(v.z, h2, l2); split_bf(v.w, h3, l3);
        uint32_t off = (uint32_t)row * KV_STRIDE_B + c4 * 2;
        *(uint32_t*)(sm + OFF_AHI + off)     = pack_bf2(h0, h1);
        *(uint32_t*)(sm + OFF_AHI + off + 4) = pack_bf2(h2, h3);
        *(uint32_t*)(sm + OFF_ALO + off)     = pack_bf2(l0, l1);
        *(uint32_t*)(sm + OFF_ALO + off + 4) = pack_bf2(l2, l3);
    }
#pragma unroll
    for (int t = 0; t < 16; t++) {
        int j  = tid + t * 256;
        int k  = j >> 5;
        int c4 = (j & 31) * 4;
        uint32_t off = (uint32_t)k * KV_STRIDE_B + c4 * 2;
        float4 v = *(const float4*)(wo + (size_t)k * DTOK + colbase + c4);
        float h0, l0, h1, l1, h2, l2, h3, l3;
        split_bf(v.x, h0, l0); split_bf(v.y, h1, l1);
        split_bf(v.z, h2, l2); split_bf(v.w, h3, l3);
        *(uint32_t*)(sm + OFF_BHI + off)     = pack_bf2(h0, h1);
        *(uint32_t*)(sm + OFF_BHI + off + 4) = pack_bf2(h2, h3);
        *(uint32_t*)(sm + OFF_BLO + off)     = pack_bf2(l0, l1);
        *(uint32_t*)(sm + OFF_BLO + off + 4) = pack_bf2(l2, l3);
    }
    __syncthreads();

    int wm = warp & 3;
    int wn = warp >> 2;
    int lr = lane & 15;
    int lc = lane >> 4;
    uint32_t aAddr = sbase + (uint32_t)(wm * 32 + lr) * KV_STRIDE_B + lc * 16;
    uint32_t bAddr = sbase + (uint32_t)lr * KV_STRIDE_B + (wn * 64 + lc * 8) * 2;

    float c[2][8][4];
#pragma unroll
    for (int mt = 0; mt < 2; mt++)
#pragma unroll
        for (int nt = 0; nt < 8; nt++)
#pragma unroll
            for (int e = 0; e < 4; e++) c[mt][nt][e] = 0.f;

#pragma unroll
    for (int ks = 0; ks < 8; ks++) {
        uint32_t ak = aAddr + ks * 32;
        uint32_t bk = bAddr + ks * 16 * KV_STRIDE_B;
        uint32_t aH[2][4], aL[2][4];
        ldm4(aH[0], ak + OFF_AHI);
        ldm4(aH[1], ak + OFF_AHI + 16 * KV_STRIDE_B);
        ldm4(aL[0], ak + OFF_ALO);
        ldm4(aL[1], ak + OFF_ALO + 16 * KV_STRIDE_B);
        uint32_t bH[4][4], bL[4][4];
#pragma unroll
        for (int i = 0; i < 4; i++) {
            ldm4t(bH[i], bk + OFF_BHI + i * 32);
            ldm4t(bL[i], bk + OFF_BLO + i * 32);
        }
#pragma unroll
        for (int mt = 0; mt < 2; mt++)
#pragma unroll
            for (int i = 0; i < 4; i++) {
                mma16816(c[mt][2 * i],     aH[mt], bH[i][0], bH[i][1]);
                mma16816(c[mt][2 * i + 1], aH[mt], bH[i][2], bH[i][3]);
                mma16816(c[mt][2 * i],     aH[mt], bL[i][0], bL[i][1]);
                mma16816(c[mt][2 * i + 1], aH[mt], bL[i][2], bL[i][3]);
                mma16816(c[mt][2 * i],     aL[mt], bH[i][0], bH[i][1]);
                mma16816(c[mt][2 * i + 1], aL[mt], bH[i][2], bH[i][3]);
            }
    }
    __syncthreads();
    {
        float* stg = (float*)(sm + OFF_BHI);
        int cr = lane >> 2, cc2 = (lane & 3) * 2;
#pragma unroll
        for (int mt = 0; mt < 2; mt++) {
            int r0 = wm * 32 + mt * 16 + cr;
#pragma unroll
            for (int nt = 0; nt < 8; nt++) {
                int cc = wn * 64 + nt * 8 + cc2;
                *(float2*)&stg[r0 * STG_STRIDE + cc] =
                    make_float2(c[mt][nt][0], c[mt][nt][1]);
                *(float2*)&stg[(r0 + 8) * STG_STRIDE + cc] =
                    make_float2(c[mt][nt][2], c[mt][nt][3]);
            }
        }
        __syncthreads();
#pragma unroll
        for (int t = 0; t < 16; t++) {
            int j  = tid + t * 256;
            int r  = j >> 5;
            int c4 = (j & 31) * 4;
            float4 v = *(float4*)&stg[r * STG_STRIDE + c4];
            *(float4*)&out[(rowbase + r) * DTOK + colbase + c4] = v;
        }
    }
}

// ==================================================================
// Launch. Input order: s, a, starts, counts, token_mask, w_q, w_k,
// w_v, w_g, w_o, ln_q_g, ln_q_b, ln_kv_g, ln_kv_b. Output fp32.
// ==================================================================
extern "C" void kernel_launch(void* const* d_in, const int* in_sizes, int n_in,
                              void* d_out, int out_size) {
    const float* s      = (const float*)d_in[0];
    const float* a      = (const float*)d_in[1];
    const int*   starts = (const int*)  d_in[2];
    const int*   counts = (const int*)  d_in[3];
    const float* tmask  = (const float*)d_in[4];
    const float* wq     = (const float*)d_in[5];
    const float* wk     = (const float*)d_in[6];
    const float* wv     = (const float*)d_in[7];
    const float* wg     = (const float*)d_in[8];
    const float* wo     = (const float*)d_in[9];
    const float* lnqg   = (const float*)d_in[10];
    const float* lnqb   = (const float*)d_in[11];
    const float* lnkg   = (const float*)d_in[12];
    const float* lnkb   = (const float*)d_in[13];
    float* out = (float*)d_out;

    cudaFuncSetAttribute(kv_mma_kernel,
                         cudaFuncAttributeMaxDynamicSharedMemorySize, KV_SMEM);
    cudaFuncSetAttribute(qg_mma_kernel,
                         cudaFuncAttributeMaxDynamicSharedMemorySize, MM4_SMEM);
    cudaFuncSetAttribute(out_mma_kernel,
                         cudaFuncAttributeMaxDynamicSharedMemorySize, MM4_SMEM);

    stats_s_kernel<<<NTOK / 8, 256>>>(s);
    kv_mma_kernel<<<NATOM / 128, 256, KV_SMEM>>>(a, wk, wv, lnkg, lnkb);
    qg_mma_kernel<<<dim3(NTOK / 128, 2), 256, MM4_SMEM>>>(s, wq, wg, lnqg, lnqb);
    attn_gate_kernel<<<NTOK / 8, 256>>>(starts, counts, tmask);
    out_mma_kernel<<<dim3(NTOK / 128, 4), 256, MM4_SMEM>>>(wo, out);
}

// round 8
// speedup vs baseline: 2.5231x; 1.1671x over previous
#include <cuda_runtime.h>
#include <cuda_fp16.h>
#include <cstdint>
#include <math.h>

// Problem constants
#define BB     4
#define NN     4096
#define MM     32768
#define DTOK   512
#define DATOM  128
#define NHEAD  4
#define DH     32
#define WMAX   16
#define LNEPS  1e-5f

#define NTOK   (BB * NN)    // 16384 token rows
#define NATOM  (BB * MM)    // 131072 atom rows

// Single dynamic smem symbol shared by all kernels (cast locally).
extern __shared__ char dyn_smem[];

// -------- scratch (device globals; no allocations allowed) --------
__device__ float g_K[(size_t)NATOM * DATOM];
__device__ float g_V[(size_t)NATOM * DATOM];
__device__ float g_Q[(size_t)NTOK * DATOM];
__device__ float g_G[(size_t)NTOK * DATOM];
__device__ float g_U[(size_t)NTOK * DATOM];
__device__ float g_smu[NTOK];
__device__ float g_srs[NTOK];

__device__ __forceinline__ float warp_sum(float v) {
#pragma unroll
    for (int o = 16; o > 0; o >>= 1) v += __shfl_xor_sync(0xffffffffu, v, o);
    return v;
}
__device__ __forceinline__ uint32_t smem_u32(const void* p) {
    uint32_t a;
    asm("{ .reg .u64 t; cvta.to.shared.u64 t, %1; cvt.u32.u64 %0, t; }"
        : "=r"(a) : "l"(p));
    return a;
}
__device__ __forceinline__ uint32_t pack_h2(float a, float b) {
    __half2 t = __floats2half2_rn(a, b);
    return *(uint32_t*)&t;
}
// hi = fp16 round of x; lo = x - hi (A-side exact split)
__device__ __forceinline__ void split_h(float x, float& hi, float& lo) {
    __half h = __float2half_rn(x);
    hi = __half2float(h);
    lo = x - hi;
}

// ---- warp-level MMA helpers (sm_80+, works on sm_100 base target) ----
__device__ __forceinline__ void ldm4(uint32_t* d, uint32_t addr) {
    asm volatile("ldmatrix.sync.aligned.m8n8.x4.shared.b16 {%0,%1,%2,%3}, [%4];"
                 : "=r"(d[0]), "=r"(d[1]), "=r"(d[2]), "=r"(d[3]) : "r"(addr));
}
__device__ __forceinline__ void ldm4t(uint32_t* d, uint32_t addr) {
    asm volatile("ldmatrix.sync.aligned.m8n8.x4.trans.shared.b16 {%0,%1,%2,%3}, [%4];"
                 : "=r"(d[0]), "=r"(d[1]), "=r"(d[2]), "=r"(d[3]) : "r"(addr));
}
__device__ __forceinline__ void mma16816(float* c, const uint32_t* a,
                                         uint32_t b0, uint32_t b1) {
    asm volatile(
        "mma.sync.aligned.m16n8k16.row.col.f32.f16.f16.f32 "
        "{%0,%1,%2,%3}, {%4,%5,%6,%7}, {%8,%9}, {%0,%1,%2,%3};"
        : "+f"(c[0]), "+f"(c[1]), "+f"(c[2]), "+f"(c[3])
        : "r"(a[0]), "r"(a[1]), "r"(a[2]), "r"(a[3]), "r"(b0), "r"(b1));
}

// Shared tile geometry (128x128 fp16 tiles, padded)
#define KV_STRIDE_B 272                   // bytes per smem row (136 halves)
#define KV_TILE_B   (128 * KV_STRIDE_B)   // 34816 bytes
#define STG_STRIDE  136                   // floats per staged row

// ==================================================================
// Kernel 1: per-row LN stats for s (rows of 512). One warp per row.
// ==================================================================
__global__ void stats_s_kernel(const float* __restrict__ s) {
    int row  = blockIdx.x * 8 + (threadIdx.x >> 5);
    int lane = threadIdx.x & 31;
    const float4* p = (const float4*)(s + (size_t)row * DTOK);
    float sum = 0.f, sq = 0.f;
#pragma unroll
    for (int j = 0; j < 4; j++) {
        float4 v = p[lane + 32 * j];
        sum += v.x + v.y + v.z + v.w;
        sq  += v.x * v.x + v.y * v.y + v.z * v.z + v.w * v.w;
    }
    sum = warp_sum(sum);
    sq  = warp_sum(sq);
    if (lane == 0) {
        float mu  = sum * (1.f / DTOK);
        float var = sq * (1.f / DTOK) - mu * mu;
        g_smu[row] = mu;
        g_srs[row] = rsqrtf(var + LNEPS);
    }
}

// ==================================================================
// Kernel 2 (mma.sync fp16 2-pass): LN(a) + K = a_n @ w_k, V = a_n @ w_v.
// A split exact (hi+lo fp16); weights single fp16.
// SMEM: A_hi, A_lo, WK, WV (4 x 34816 = 139264 B).
// ==================================================================
#define OFF_AHI  0
#define OFF_ALO  (OFF_AHI + KV_TILE_B)
#define OFF_WK   (OFF_ALO + KV_TILE_B)
#define OFF_WV   (OFF_WK + KV_TILE_B)
#define KV_SMEM  (OFF_WV + KV_TILE_B)     // 139264 bytes

__global__ void __launch_bounds__(256, 1)
kv_mma_kernel(const float* __restrict__ a, const float* __restrict__ wk,
              const float* __restrict__ wv, const float* __restrict__ lng,
              const float* __restrict__ lnb) {
    char* sm = dyn_smem;
    uint32_t sbase = smem_u32(sm);
    int tid = threadIdx.x;
    int warp = tid >> 5, lane = tid & 31;
    size_t rowbase = (size_t)blockIdx.x * 128;

    // ---- A tile: LN rows -> hi/lo fp16 ----
    float4 gln = ((const float4*)lng)[lane];
    float4 bln = ((const float4*)lnb)[lane];
    for (int r = warp; r < 128; r += 8) {
        float4 v = *(const float4*)(a + (rowbase + r) * DATOM + lane * 4);
        float sum = warp_sum(v.x + v.y + v.z + v.w);
        float sq  = warp_sum(v.x * v.x + v.y * v.y + v.z * v.z + v.w * v.w);
        float mu  = sum * (1.f / 128.f);
        float rs  = rsqrtf(sq * (1.f / 128.f) - mu * mu + LNEPS);
        float n0 = (v.x - mu) * rs * gln.x + bln.x;
        float n1 = (v.y - mu) * rs * gln.y + bln.y;
        float n2 = (v.z - mu) * rs * gln.z + bln.z;
        float n3 = (v.w - mu) * rs * gln.w + bln.w;
        float h0, l0, h1, l1, h2, l2, h3, l3;
        split_h(n0, h0, l0); split_h(n1, h1, l1);
        split_h(n2, h2, l2); split_h(n3, h3, l3);
        uint32_t off = (uint32_t)r * KV_STRIDE_B + lane * 8;
        *(uint32_t*)(sm + OFF_AHI + off)     = pack_h2(h0, h1);
        *(uint32_t*)(sm + OFF_AHI + off + 4) = pack_h2(h2, h3);
        *(uint32_t*)(sm + OFF_ALO + off)     = pack_h2(l0, l1);
        *(uint32_t*)(sm + OFF_ALO + off + 4) = pack_h2(l2, l3);
    }
    // ---- W tiles: single fp16 ----
#pragma unroll
    for (int t = 0; t < 16; t++) {
        int j  = tid + t * 256;
        int k  = j >> 5;
        int c4 = (j & 31) * 4;
        uint32_t off = (uint32_t)k * KV_STRIDE_B + c4 * 2;
        float4 v = *(const float4*)(wk + (size_t)k * DATOM + c4);
        *(uint32_t*)(sm + OFF_WK + off)     = pack_h2(v.x, v.y);
        *(uint32_t*)(sm + OFF_WK + off + 4) = pack_h2(v.z, v.w);
        v = *(const float4*)(wv + (size_t)k * DATOM + c4);
        *(uint32_t*)(sm + OFF_WV + off)     = pack_h2(v.x, v.y);
        *(uint32_t*)(sm + OFF_WV + off + 4) = pack_h2(v.z, v.w);
    }
    __syncthreads();

    int wm = warp & 3;
    int wn = warp >> 2;
    int lr = lane & 15;
    int lc = lane >> 4;

    uint32_t aAddr = sbase + (uint32_t)(wm * 32 + lr) * KV_STRIDE_B + lc * 16;
    uint32_t bAddr = sbase + (uint32_t)lr * KV_STRIDE_B + (wn * 64 + lc * 8) * 2;

    float cK[2][8][4], cV[2][8][4];
#pragma unroll
    for (int mt = 0; mt < 2; mt++)
#pragma unroll
        for (int nt = 0; nt < 8; nt++)
#pragma unroll
            for (int e = 0; e < 4; e++) { cK[mt][nt][e] = 0.f; cV[mt][nt][e] = 0.f; }

#pragma unroll
    for (int ks = 0; ks < 8; ks++) {
        uint32_t ak = aAddr + ks * 32;
        uint32_t bk = bAddr + ks * 16 * KV_STRIDE_B;
        uint32_t aH[2][4], aL[2][4];
        ldm4(aH[0], ak + OFF_AHI);
        ldm4(aH[1], ak + OFF_AHI + 16 * KV_STRIDE_B);
        ldm4(aL[0], ak + OFF_ALO);
        ldm4(aL[1], ak + OFF_ALO + 16 * KV_STRIDE_B);
        // ---- K ----
        {
            uint32_t b[4][4];
#pragma unroll
            for (int i = 0; i < 4; i++) ldm4t(b[i], bk + OFF_WK + i * 32);
#pragma unroll
            for (int mt = 0; mt < 2; mt++)
#pragma unroll
                for (int i = 0; i < 4; i++) {
                    mma16816(cK[mt][2 * i],     aH[mt], b[i][0], b[i][1]);
                    mma16816(cK[mt][2 * i + 1], aH[mt], b[i][2], b[i][3]);
                    mma16816(cK[mt][2 * i],     aL[mt], b[i][0], b[i][1]);
                    mma16816(cK[mt][2 * i + 1], aL[mt], b[i][2], b[i][3]);
                }
        }
        // ---- V ----
        {
            uint32_t b[4][4];
#pragma unroll
            for (int i = 0; i < 4; i++) ldm4t(b[i], bk + OFF_WV + i * 32);
#pragma unroll
            for (int mt = 0; mt < 2; mt++)
#pragma unroll
                for (int i = 0; i < 4; i++) {
                    mma16816(cV[mt][2 * i],     aH[mt], b[i][0], b[i][1]);
                    mma16816(cV[mt][2 * i + 1], aH[mt], b[i][2], b[i][3]);
                    mma16816(cV[mt][2 * i],     aL[mt], b[i][0], b[i][1]);
                    mma16816(cV[mt][2 * i + 1], aL[mt], b[i][2], b[i][3]);
                }
        }
    }
    __syncthreads();   // mainloop reads done; reuse A region (K) + W region (V)
    {
        float* stgK = (float*)(sm + OFF_AHI);   // 69632 B (AHI+ALO)
        float* stgV = (float*)(sm + OFF_WK);    // 69632 B (WK+WV)
        int cr = lane >> 2, cc2 = (lane & 3) * 2;
#pragma unroll
        for (int mt = 0; mt < 2; mt++) {
            int r0 = wm * 32 + mt * 16 + cr;
#pragma unroll
            for (int nt = 0; nt < 8; nt++) {
                int cc = wn * 64 + nt * 8 + cc2;
                *(float2*)&stgK[r0 * STG_STRIDE + cc] =
                    make_float2(cK[mt][nt][0], cK[mt][nt][1]);
                *(float2*)&stgK[(r0 + 8) * STG_STRIDE + cc] =
                    make_float2(cK[mt][nt][2], cK[mt][nt][3]);
                *(float2*)&stgV[r0 * STG_STRIDE + cc] =
                    make_float2(cV[mt][nt][0], cV[mt][nt][1]);
                *(float2*)&stgV[(r0 + 8) * STG_STRIDE + cc] =
                    make_float2(cV[mt][nt][2], cV[mt][nt][3]);
            }
        }
        __syncthreads();
#pragma unroll
        for (int t = 0; t < 16; t++) {
            int j  = tid + t * 256;
            int r  = j >> 5;
            int c4 = (j & 31) * 4;
            *(float4*)&g_K[(rowbase + r) * DATOM + c4] =
                *(float4*)&stgK[r * STG_STRIDE + c4];
            *(float4*)&g_V[(rowbase + r) * DATOM + c4] =
                *(float4*)&stgV[r * STG_STRIDE + c4];
        }
    }
}

// ==================================================================
// Kernel 3 (mma.sync fp16 2-pass): LN(s) + [Q|G] = s_n @ [w_q|w_g].
// Grid (NTOK/128, 2). K = 512 in 4 accumulating chunks of 128.
// SMEM: A_hi, A_lo, B (3 x 34816 = 104448 B).
// ==================================================================
#define OFF_B    (2 * KV_TILE_B)
#define MM3_SMEM (3 * KV_TILE_B)    // 104448 bytes

__global__ void __launch_bounds__(256, 1)
qg_mma_kernel(const float* __restrict__ s, const float* __restrict__ wq,
              const float* __restrict__ wg, const float* __restrict__ lng,
              const float* __restrict__ lnb) {
    char* sm = dyn_smem;
    uint32_t sbase = smem_u32(sm);
    int tid = threadIdx.x;
    int warp = tid >> 5, lane = tid & 31;
    size_t rowbase = (size_t)blockIdx.x * 128;
    const float* w = (blockIdx.y == 0) ? wq : wg;
    float* dst     = (blockIdx.y == 0) ? g_Q : g_G;

    int wm = warp & 3;
    int wn = warp >> 2;
    int lr = lane & 15;
    int lc = lane >> 4;
    uint32_t aAddr = sbase + (uint32_t)(wm * 32 + lr) * KV_STRIDE_B + lc * 16;
    uint32_t bAddr = sbase + (uint32_t)lr * KV_STRIDE_B + (wn * 64 + lc * 8) * 2;

    float c[2][8][4];
#pragma unroll
    for (int mt = 0; mt < 2; mt++)
#pragma unroll
        for (int nt = 0; nt < 8; nt++)
#pragma unroll
            for (int e = 0; e < 4; e++) c[mt][nt][e] = 0.f;

#pragma unroll 1
    for (int kc = 0; kc < 4; kc++) {
        int k0 = kc * 128;
#pragma unroll
        for (int t = 0; t < 16; t++) {
            int j   = tid + t * 256;
            int row = j >> 5;
            int c4  = (j & 31) * 4;
            float4 v = *(const float4*)(s + (rowbase + row) * DTOK + k0 + c4);
            float mu = g_smu[rowbase + row];
            float rs = g_srs[rowbase + row];
            float4 gv = *(const float4*)(lng + k0 + c4);
            float4 bv = *(const float4*)(lnb + k0 + c4);
            float n0 = (v.x - mu) * rs * gv.x + bv.x;
            float n1 = (v.y - mu) * rs * gv.y + bv.y;
            float n2 = (v.z - mu) * rs * gv.z + bv.z;
            float n3 = (v.w - mu) * rs * gv.w + bv.w;
            float h0, l0, h1, l1, h2, l2, h3, l3;
            split_h(n0, h0, l0); split_h(n1, h1, l1);
            split_h(n2, h2, l2); split_h(n3, h3, l3);
            uint32_t off = (uint32_t)row * KV_STRIDE_B + c4 * 2;
            *(uint32_t*)(sm + OFF_AHI + off)     = pack_h2(h0, h1);
            *(uint32_t*)(sm + OFF_AHI + off + 4) = pack_h2(h2, h3);
            *(uint32_t*)(sm + OFF_ALO + off)     = pack_h2(l0, l1);
            *(uint32_t*)(sm + OFF_ALO + off + 4) = pack_h2(l2, l3);
        }
#pragma unroll
        for (int t = 0; t < 16; t++) {
            int j  = tid + t * 256;
            int k  = j >> 5;
            int c4 = (j & 31) * 4;
            uint32_t off = (uint32_t)k * KV_STRIDE_B + c4 * 2;
            float4 v = *(const float4*)(w + (size_t)(k0 + k) * DATOM + c4);
            *(uint32_t*)(sm + OFF_B + off)     = pack_h2(v.x, v.y);
            *(uint32_t*)(sm + OFF_B + off + 4) = pack_h2(v.z, v.w);
        }
        __syncthreads();
#pragma unroll
        for (int ks = 0; ks < 8; ks++) {
            uint32_t ak = aAddr + ks * 32;
            uint32_t bk = bAddr + ks * 16 * KV_STRIDE_B;
            uint32_t aH[2][4], aL[2][4];
            ldm4(aH[0], ak + OFF_AHI);
            ldm4(aH[1], ak + OFF_AHI + 16 * KV_STRIDE_B);
            ldm4(aL[0], ak + OFF_ALO);
            ldm4(aL[1], ak + OFF_ALO + 16 * KV_STRIDE_B);
            uint32_t b[4][4];
#pragma unroll
            for (int i = 0; i < 4; i++) ldm4t(b[i], bk + OFF_B + i * 32);
#pragma unroll
            for (int mt = 0; mt < 2; mt++)
#pragma unroll
                for (int i = 0; i < 4; i++) {
                    mma16816(c[mt][2 * i],     aH[mt], b[i][0], b[i][1]);
                    mma16816(c[mt][2 * i + 1], aH[mt], b[i][2], b[i][3]);
                    mma16816(c[mt][2 * i],     aL[mt], b[i][0], b[i][1]);
                    mma16816(c[mt][2 * i + 1], aL[mt], b[i][2], b[i][3]);
                }
        }
        __syncthreads();
    }
    // ---- epilogue: stage into A region (69632 B) then coalesced write ----
    {
        float* stg = (float*)(sm + OFF_AHI);
        int cr = lane >> 2, cc2 = (lane & 3) * 2;
#pragma unroll
        for (int mt = 0; mt < 2; mt++) {
            int r0 = wm * 32 + mt * 16 + cr;
#pragma unroll
            for (int nt = 0; nt < 8; nt++) {
                int cc = wn * 64 + nt * 8 + cc2;
                *(float2*)&stg[r0 * STG_STRIDE + cc] =
                    make_float2(c[mt][nt][0], c[mt][nt][1]);
                *(float2*)&stg[(r0 + 8) * STG_STRIDE + cc] =
                    make_float2(c[mt][nt][2], c[mt][nt][3]);
            }
        }
        __syncthreads();
#pragma unroll
        for (int t = 0; t < 16; t++) {
            int j  = tid + t * 256;
            int r  = j >> 5;
            int c4 = (j & 31) * 4;
            float4 v = *(float4*)&stg[r * STG_STRIDE + c4];
            *(float4*)&dst[(rowbase + r) * DATOM + c4] = v;
        }
    }
}

// ==================================================================
// Kernel 4: ragged window attention + gate. WARP PER TOKEN.
// (unchanged from R7 — proven, DRAM-bound at ~48% BW)
// ==================================================================
__global__ void __launch_bounds__(256, 8)
attn_gate_kernel(const int* __restrict__ starts, const int* __restrict__ counts,
                 const float* __restrict__ tmask) {
    int warp = threadIdx.x >> 5, lane = threadIdx.x & 31;
    int bt = blockIdx.x * 8 + warp;      // token index
    int b  = bt >> 12;                   // batch (N = 4096)
    int start = starts[bt];
    int count = counts[bt];
    const float scale = 0.17677669529663687f;   // 1/sqrt(32)

    float4 q = *(const float4*)(g_Q + (size_t)bt * DATOM + lane * 4);
    const float* kb = g_K + ((size_t)b * MM + start) * DATOM;

    float sc[WMAX];
#pragma unroll
    for (int w = 0; w < WMAX; w++) {
        float d = -1e30f;
        if (w < count) {
            float4 k4 = *(const float4*)(kb + (size_t)w * DATOM + lane * 4);
            float t = q.x * k4.x + q.y * k4.y + q.z * k4.z + q.w * k4.w;
            t += __shfl_xor_sync(0xffffffffu, t, 1);
            t += __shfl_xor_sync(0xffffffffu, t, 2);
            t += __shfl_xor_sync(0xffffffffu, t, 4);
            d = t * scale;
        }
        sc[w] = d;
    }
    float m = -1e30f;
#pragma unroll
    for (int w = 0; w < WMAX; w++) m = fmaxf(m, sc[w]);
    float sum = 0.f;
#pragma unroll
    for (int w = 0; w < WMAX; w++) { sc[w] = expf(sc[w] - m); sum += sc[w]; }
    float inv = 1.f / sum;

    const float* vb = g_V + ((size_t)b * MM + start) * DATOM;
    float4 acc = make_float4(0.f, 0.f, 0.f, 0.f);
#pragma unroll
    for (int w = 0; w < WMAX; w++) {
        if (w < count) {
            float p = sc[w] * inv;
            float4 v4 = *(const float4*)(vb + (size_t)w * DATOM + lane * 4);
            acc.x = fmaf(p, v4.x, acc.x);
            acc.y = fmaf(p, v4.y, acc.y);
            acc.z = fmaf(p, v4.z, acc.z);
            acc.w = fmaf(p, v4.w, acc.w);
        }
    }
    float msk = tmask[bt];
    float4 g = *(const float4*)(g_G + (size_t)bt * DATOM + lane * 4);
    float4 u;
    u.x = acc.x * msk / (1.f + expf(-g.x));
    u.y = acc.y * msk / (1.f + expf(-g.y));
    u.z = acc.z * msk / (1.f + expf(-g.z));
    u.w = acc.w * msk / (1.f + expf(-g.w));
    *(float4*)(g_U + (size_t)bt * DATOM + lane * 4) = u;
}

// ==================================================================
// Kernel 5 (mma.sync fp16 2-pass): out = U @ w_o (16384x128 @ 128x512).
// Grid (NTOK/128, 4): blockIdx.y = col quarter. K = 128 single chunk.
// ==================================================================
__global__ void __launch_bounds__(256, 1)
out_mma_kernel(const float* __restrict__ wo, float* __restrict__ out) {
    char* sm = dyn_smem;
    uint32_t sbase = smem_u32(sm);
    int tid = threadIdx.x;
    int warp = tid >> 5, lane = tid & 31;
    size_t rowbase = (size_t)blockIdx.x * 128;
    int colbase = blockIdx.y * 128;

    // ---- A tile: g_U rows -> hi/lo fp16 ----
#pragma unroll
    for (int t = 0; t < 16; t++) {
        int j   = tid + t * 256;
        int row = j >> 5;
        int c4  = (j & 31) * 4;
        float4 v = *(const float4*)(g_U + (rowbase + row) * DATOM + c4);
        float h0, l0, h1, l1, h2, l2, h3, l3;
        split_h(v.x, h0, l0); split_h(v.y, h1, l1);
        split_h(v.z, h2, l2); split_h(v.w, h3, l3);
        uint32_t off = (uint32_t)row * KV_STRIDE_B + c4 * 2;
        *(uint32_t*)(sm + OFF_AHI + off)     = pack_h2(h0, h1);
        *(uint32_t*)(sm + OFF_AHI + off + 4) = pack_h2(h2, h3);
        *(uint32_t*)(sm + OFF_ALO + off)     = pack_h2(l0, l1);
        *(uint32_t*)(sm + OFF_ALO + off + 4) = pack_h2(l2, l3);
    }
    // ---- B tile: wo[k][colbase + 0..127] ----
#pragma unroll
    for (int t = 0; t < 16; t++) {
        int j  = tid + t * 256;
        int k  = j >> 5;
        int c4 = (j & 31) * 4;
        uint32_t off = (uint32_t)k * KV_STRIDE_B + c4 * 2;
        float4 v = *(const float4*)(wo + (size_t)k * DTOK + colbase + c4);
        *(uint32_t*)(sm + OFF_B + off)     = pack_h2(v.x, v.y);
        *(uint32_t*)(sm + OFF_B + off + 4) = pack_h2(v.z, v.w);
    }
    __syncthreads();

    int wm = warp & 3;
    int wn = warp >> 2;
    int lr = lane & 15;
    int lc = lane >> 4;
    uint32_t aAddr = sbase + (uint32_t)(wm * 32 + lr) * KV_STRIDE_B + lc * 16;
    uint32_t bAddr = sbase + (uint32_t)lr * KV_STRIDE_B + (wn * 64 + lc * 8) * 2;

    float c[2][8][4];
#pragma unroll
    for (int mt = 0; mt < 2; mt++)
#pragma unroll
        for (int nt = 0; nt < 8; nt++)
#pragma unroll
            for (int e = 0; e < 4; e++) c[mt][nt][e] = 0.f;

#pragma unroll
    for (int ks = 0; ks < 8; ks++) {
        uint32_t ak = aAddr + ks * 32;
        uint32_t bk = bAddr + ks * 16 * KV_STRIDE_B;
        uint32_t aH[2][4], aL[2][4];
        ldm4(aH[0], ak + OFF_AHI);
        ldm4(aH[1], ak + OFF_AHI + 16 * KV_STRIDE_B);
        ldm4(aL[0], ak + OFF_ALO);
        ldm4(aL[1], ak + OFF_ALO + 16 * KV_STRIDE_B);
        uint32_t b[4][4];
#pragma unroll
        for (int i = 0; i < 4; i++) ldm4t(b[i], bk + OFF_B + i * 32);
#pragma unroll
        for (int mt = 0; mt < 2; mt++)
#pragma unroll
            for (int i = 0; i < 4; i++) {
                mma16816(c[mt][2 * i],     aH[mt], b[i][0], b[i][1]);
                mma16816(c[mt][2 * i + 1], aH[mt], b[i][2], b[i][3]);
                mma16816(c[mt][2 * i],     aL[mt], b[i][0], b[i][1]);
                mma16816(c[mt][2 * i + 1], aL[mt], b[i][2], b[i][3]);
            }
    }
    __syncthreads();
    {
        float* stg = (float*)(sm + OFF_AHI);
        int cr = lane >> 2, cc2 = (lane & 3) * 2;
#pragma unroll
        for (int mt = 0; mt < 2; mt++) {
            int r0 = wm * 32 + mt * 16 + cr;
#pragma unroll
            for (int nt = 0; nt < 8; nt++) {
                int cc = wn * 64 + nt * 8 + cc2;
                *(float2*)&stg[r0 * STG_STRIDE + cc] =
                    make_float2(c[mt][nt][0], c[mt][nt][1]);
                *(float2*)&stg[(r0 + 8) * STG_STRIDE + cc] =
                    make_float2(c[mt][nt][2], c[mt][nt][3]);
            }
        }
        __syncthreads();
#pragma unroll
        for (int t = 0; t < 16; t++) {
            int j  = tid + t * 256;
            int r  = j >> 5;
            int c4 = (j & 31) * 4;
            float4 v = *(float4*)&stg[r * STG_STRIDE + c4];
            *(float4*)&out[(rowbase + r) * DTOK + colbase + c4] = v;
        }
    }
}

// ==================================================================
// Launch. Input order: s, a, starts, counts, token_mask, w_q, w_k,
// w_v, w_g, w_o, ln_q_g, ln_q_b, ln_kv_g, ln_kv_b. Output fp32.
// ==================================================================
extern "C" void kernel_launch(void* const* d_in, const int* in_sizes, int n_in,
                              void* d_out, int out_size) {
    const float* s      = (const float*)d_in[0];
    const float* a      = (const float*)d_in[1];
    const int*   starts = (const int*)  d_in[2];
    const int*   counts = (const int*)  d_in[3];
    const float* tmask  = (const float*)d_in[4];
    const float* wq     = (const float*)d_in[5];
    const float* wk     = (const float*)d_in[6];
    const float* wv     = (const float*)d_in[7];
    const float* wg     = (const float*)d_in[8];
    const float* wo     = (const float*)d_in[9];
    const float* lnqg   = (const float*)d_in[10];
    const float* lnqb   = (const float*)d_in[11];
    const float* lnkg   = (const float*)d_in[12];
    const float* lnkb   = (const float*)d_in[13];
    float* out = (float*)d_out;

    cudaFuncSetAttribute(kv_mma_kernel,
                         cudaFuncAttributeMaxDynamicSharedMemorySize, KV_SMEM);
    cudaFuncSetAttribute(qg_mma_kernel,
                         cudaFuncAttributeMaxDynamicSharedMemorySize, MM3_SMEM);
    cudaFuncSetAttribute(out_mma_kernel,
                         cudaFuncAttributeMaxDynamicSharedMemorySize, MM3_SMEM);

    stats_s_kernel<<<NTOK / 8, 256>>>(s);
    kv_mma_kernel<<<NATOM / 128, 256, KV_SMEM>>>(a, wk, wv, lnkg, lnkb);
    qg_mma_kernel<<<dim3(NTOK / 128, 2), 256, MM3_SMEM>>>(s, wq, wg, lnqg, lnqb);
    attn_gate_kernel<<<NTOK / 8, 256>>>(starts, counts, tmask);
    out_mma_kernel<<<dim3(NTOK / 128, 4), 256, MM3_SMEM>>>(wo, out);
}

// round 9
// speedup vs baseline: 2.6628x; 1.0554x over previous
#include <cuda_runtime.h>
#include <cuda_fp16.h>
#include <cstdint>
#include <math.h>

// Problem constants
#define BB     4
#define NN     4096
#define MM     32768
#define DTOK   512
#define DATOM  128
#define NHEAD  4
#define DH     32
#define WMAX   16
#define LNEPS  1e-5f

#define NTOK   (BB * NN)    // 16384 token rows
#define NATOM  (BB * MM)    // 131072 atom rows

// Single dynamic smem symbol shared by all kernels (cast locally).
extern __shared__ char dyn_smem[];

// -------- scratch (device globals; no allocations allowed) --------
__device__ float g_K[(size_t)NATOM * DATOM];
__device__ float g_V[(size_t)NATOM * DATOM];
__device__ float g_Q[(size_t)NTOK * DATOM];
__device__ float g_G[(size_t)NTOK * DATOM];
__device__ __half g_Uhi[(size_t)NTOK * DATOM];
__device__ __half g_Ulo[(size_t)NTOK * DATOM];
__device__ float g_smu[NTOK];
__device__ float g_srs[NTOK];
// fp16 weights (converted once per launch by wprep_kernel)
__device__ __half g_hwk[DATOM * DATOM];
__device__ __half g_hwv[DATOM * DATOM];
__device__ __half g_hwq[DTOK * DATOM];
__device__ __half g_hwg[DTOK * DATOM];
__device__ __half g_hwo[DATOM * DTOK];

__device__ __forceinline__ float warp_sum(float v) {
#pragma unroll
    for (int o = 16; o > 0; o >>= 1) v += __shfl_xor_sync(0xffffffffu, v, o);
    return v;
}
__device__ __forceinline__ uint32_t smem_u32(const void* p) {
    uint32_t a;
    asm("{ .reg .u64 t; cvta.to.shared.u64 t, %1; cvt.u32.u64 %0, t; }"
        : "=r"(a) : "l"(p));
    return a;
}
__device__ __forceinline__ uint32_t pack_h2(float a, float b) {
    __half2 t = __floats2half2_rn(a, b);
    return *(uint32_t*)&t;
}
// hi = fp16 round of x; lo = x - hi (A-side exact split)
__device__ __forceinline__ void split_h(float x, float& hi, float& lo) {
    __half h = __float2half_rn(x);
    hi = __half2float(h);
    lo = x - hi;
}

// ---- warp-level MMA helpers ----
__device__ __forceinline__ void ldm4(uint32_t* d, uint32_t addr) {
    asm volatile("ldmatrix.sync.aligned.m8n8.x4.shared.b16 {%0,%1,%2,%3}, [%4];"
                 : "=r"(d[0]), "=r"(d[1]), "=r"(d[2]), "=r"(d[3]) : "r"(addr));
}
__device__ __forceinline__ void ldm4t(uint32_t* d, uint32_t addr) {
    asm volatile("ldmatrix.sync.aligned.m8n8.x4.trans.shared.b16 {%0,%1,%2,%3}, [%4];"
                 : "=r"(d[0]), "=r"(d[1]), "=r"(d[2]), "=r"(d[3]) : "r"(addr));
}
__device__ __forceinline__ void mma16816(float* c, const uint32_t* a,
                                         uint32_t b0, uint32_t b1) {
    asm volatile(
        "mma.sync.aligned.m16n8k16.row.col.f32.f16.f16.f32 "
        "{%0,%1,%2,%3}, {%4,%5,%6,%7}, {%8,%9}, {%0,%1,%2,%3};"
        : "+f"(c[0]), "+f"(c[1]), "+f"(c[2]), "+f"(c[3])
        : "r"(a[0]), "r"(a[1]), "r"(a[2]), "r"(a[3]), "r"(b0), "r"(b1));
}

// Shared tile geometry (128x128 fp16 tiles, padded)
#define KV_STRIDE_B 272                   // bytes per smem row (136 halves)
#define KV_TILE_B   (128 * KV_STRIDE_B)   // 34816 bytes
#define STG_STRIDE  136                   // floats per staged row

// ==================================================================
// Kernel 0: convert all weights to fp16 once. 256x256 threads.
// ==================================================================
__global__ void wprep_kernel(const float* __restrict__ wq,
                             const float* __restrict__ wk,
                             const float* __restrict__ wv,
                             const float* __restrict__ wg,
                             const float* __restrict__ wo) {
    int i = blockIdx.x * 256 + threadIdx.x;   // 0..65535
    if (i < DATOM * DATOM) {
        g_hwk[i] = __float2half_rn(wk[i]);
        g_hwv[i] = __float2half_rn(wv[i]);
    }
    g_hwq[i] = __float2half_rn(wq[i]);
    g_hwg[i] = __float2half_rn(wg[i]);
    g_hwo[i] = __float2half_rn(wo[i]);
}

// ==================================================================
// Kernel 1: per-row LN stats for s (rows of 512). One warp per row.
// ==================================================================
__global__ void stats_s_kernel(const float* __restrict__ s) {
    int row  = blockIdx.x * 8 + (threadIdx.x >> 5);
    int lane = threadIdx.x & 31;
    const float4* p = (const float4*)(s + (size_t)row * DTOK);
    float sum = 0.f, sq = 0.f;
#pragma unroll
    for (int j = 0; j < 4; j++) {
        float4 v = p[lane + 32 * j];
        sum += v.x + v.y + v.z + v.w;
        sq  += v.x * v.x + v.y * v.y + v.z * v.z + v.w * v.w;
    }
    sum = warp_sum(sum);
    sq  = warp_sum(sq);
    if (lane == 0) {
        float mu  = sum * (1.f / DTOK);
        float var = sq * (1.f / DTOK) - mu * mu;
        g_smu[row] = mu;
        g_srs[row] = rsqrtf(var + LNEPS);
    }
}

// ==================================================================
// Kernel 2 (mma.sync fp16 2-pass): LN(a) + K = a_n @ w_k, V = a_n @ w_v.
// A split exact (hi+lo fp16); weights direct fp16 copy from globals.
// ==================================================================
#define OFF_AHI  0
#define OFF_ALO  (OFF_AHI + KV_TILE_B)
#define OFF_WK   (OFF_ALO + KV_TILE_B)
#define OFF_WV   (OFF_WK + KV_TILE_B)
#define KV_SMEM  (OFF_WV + KV_TILE_B)     // 139264 bytes

__global__ void __launch_bounds__(256, 1)
kv_mma_kernel(const float* __restrict__ a, const float* __restrict__ lng,
              const float* __restrict__ lnb) {
    char* sm = dyn_smem;
    uint32_t sbase = smem_u32(sm);
    int tid = threadIdx.x;
    int warp = tid >> 5, lane = tid & 31;
    size_t rowbase = (size_t)blockIdx.x * 128;

    // ---- A tile: LN rows -> hi/lo fp16 ----
    float4 gln = ((const float4*)lng)[lane];
    float4 bln = ((const float4*)lnb)[lane];
    for (int r = warp; r < 128; r += 8) {
        float4 v = *(const float4*)(a + (rowbase + r) * DATOM + lane * 4);
        float sum = warp_sum(v.x + v.y + v.z + v.w);
        float sq  = warp_sum(v.x * v.x + v.y * v.y + v.z * v.z + v.w * v.w);
        float mu  = sum * (1.f / 128.f);
        float rs  = rsqrtf(sq * (1.f / 128.f) - mu * mu + LNEPS);
        float n0 = (v.x - mu) * rs * gln.x + bln.x;
        float n1 = (v.y - mu) * rs * gln.y + bln.y;
        float n2 = (v.z - mu) * rs * gln.z + bln.z;
        float n3 = (v.w - mu) * rs * gln.w + bln.w;
        float h0, l0, h1, l1, h2, l2, h3, l3;
        split_h(n0, h0, l0); split_h(n1, h1, l1);
        split_h(n2, h2, l2); split_h(n3, h3, l3);
        uint32_t off = (uint32_t)r * KV_STRIDE_B + lane * 8;
        *(uint32_t*)(sm + OFF_AHI + off)     = pack_h2(h0, h1);
        *(uint32_t*)(sm + OFF_AHI + off + 4) = pack_h2(h2, h3);
        *(uint32_t*)(sm + OFF_ALO + off)     = pack_h2(l0, l1);
        *(uint32_t*)(sm + OFF_ALO + off + 4) = pack_h2(l2, l3);
    }
    // ---- W tiles: direct fp16 copy ----
#pragma unroll
    for (int t = 0; t < 8; t++) {
        int j   = tid + t * 256;         // 0..2047 uint4 (8 halves each)
        int row = j >> 4;
        int c8  = (j & 15) * 8;
        uint32_t off = (uint32_t)row * KV_STRIDE_B + c8 * 2;
        *(uint4*)(sm + OFF_WK + off) = *(const uint4*)(g_hwk + row * DATOM + c8);
        *(uint4*)(sm + OFF_WV + off) = *(const uint4*)(g_hwv + row * DATOM + c8);
    }
    __syncthreads();

    int wm = warp & 3;
    int wn = warp >> 2;
    int lr = lane & 15;
    int lc = lane >> 4;

    uint32_t aAddr = sbase + (uint32_t)(wm * 32 + lr) * KV_STRIDE_B + lc * 16;
    uint32_t bAddr = sbase + (uint32_t)lr * KV_STRIDE_B + (wn * 64 + lc * 8) * 2;

    float cK[2][8][4], cV[2][8][4];
#pragma unroll
    for (int mt = 0; mt < 2; mt++)
#pragma unroll
        for (int nt = 0; nt < 8; nt++)
#pragma unroll
            for (int e = 0; e < 4; e++) { cK[mt][nt][e] = 0.f; cV[mt][nt][e] = 0.f; }

#pragma unroll
    for (int ks = 0; ks < 8; ks++) {
        uint32_t ak = aAddr + ks * 32;
        uint32_t bk = bAddr + ks * 16 * KV_STRIDE_B;
        uint32_t aH[2][4], aL[2][4];
        ldm4(aH[0], ak + OFF_AHI);
        ldm4(aH[1], ak + OFF_AHI + 16 * KV_STRIDE_B);
        ldm4(aL[0], ak + OFF_ALO);
        ldm4(aL[1], ak + OFF_ALO + 16 * KV_STRIDE_B);
        {
            uint32_t b[4][4];
#pragma unroll
            for (int i = 0; i < 4; i++) ldm4t(b[i], bk + OFF_WK + i * 32);
#pragma unroll
            for (int mt = 0; mt < 2; mt++)
#pragma unroll
                for (int i = 0; i < 4; i++) {
                    mma16816(cK[mt][2 * i],     aH[mt], b[i][0], b[i][1]);
                    mma16816(cK[mt][2 * i + 1], aH[mt], b[i][2], b[i][3]);
                    mma16816(cK[mt][2 * i],     aL[mt], b[i][0], b[i][1]);
                    mma16816(cK[mt][2 * i + 1], aL[mt], b[i][2], b[i][3]);
                }
        }
        {
            uint32_t b[4][4];
#pragma unroll
            for (int i = 0; i < 4; i++) ldm4t(b[i], bk + OFF_WV + i * 32);
#pragma unroll
            for (int mt = 0; mt < 2; mt++)
#pragma unroll
                for (int i = 0; i < 4; i++) {
                    mma16816(cV[mt][2 * i],     aH[mt], b[i][0], b[i][1]);
                    mma16816(cV[mt][2 * i + 1], aH[mt], b[i][2], b[i][3]);
                    mma16816(cV[mt][2 * i],     aL[mt], b[i][0], b[i][1]);
                    mma16816(cV[mt][2 * i + 1], aL[mt], b[i][2], b[i][3]);
                }
        }
    }
    __syncthreads();
    {
        float* stgK = (float*)(sm + OFF_AHI);   // 69632 B (AHI+ALO)
        float* stgV = (float*)(sm + OFF_WK);    // 69632 B (WK+WV)
        int cr = lane >> 2, cc2 = (lane & 3) * 2;
#pragma unroll
        for (int mt = 0; mt < 2; mt++) {
            int r0 = wm * 32 + mt * 16 + cr;
#pragma unroll
            for (int nt = 0; nt < 8; nt++) {
                int cc = wn * 64 + nt * 8 + cc2;
                *(float2*)&stgK[r0 * STG_STRIDE + cc] =
                    make_float2(cK[mt][nt][0], cK[mt][nt][1]);
                *(float2*)&stgK[(r0 + 8) * STG_STRIDE + cc] =
                    make_float2(cK[mt][nt][2], cK[mt][nt][3]);
                *(float2*)&stgV[r0 * STG_STRIDE + cc] =
                    make_float2(cV[mt][nt][0], cV[mt][nt][1]);
                *(float2*)&stgV[(r0 + 8) * STG_STRIDE + cc] =
                    make_float2(cV[mt][nt][2], cV[mt][nt][3]);
            }
        }
        __syncthreads();
#pragma unroll
        for (int t = 0; t < 16; t++) {
            int j  = tid + t * 256;
            int r  = j >> 5;
            int c4 = (j & 31) * 4;
            *(float4*)&g_K[(rowbase + r) * DATOM + c4] =
                *(float4*)&stgK[r * STG_STRIDE + c4];
            *(float4*)&g_V[(rowbase + r) * DATOM + c4] =
                *(float4*)&stgV[r * STG_STRIDE + c4];
        }
    }
}

// ==================================================================
// Kernel 3 (mma.sync fp16 2-pass, merged): LN(s) + Q AND G per block.
// Grid NTOK/128. K = 512 in 4 accumulating chunks of 128.
// SMEM: A_hi, A_lo, Bq, Bg (139264 B). A converted once per chunk.
// ==================================================================
#define OFF_BQ   (2 * KV_TILE_B)
#define OFF_BG   (3 * KV_TILE_B)
#define QG_SMEM  (4 * KV_TILE_B)    // 139264 bytes

__global__ void __launch_bounds__(256, 1)
qg_mma_kernel(const float* __restrict__ s, const float* __restrict__ lng,
              const float* __restrict__ lnb) {
    char* sm = dyn_smem;
    uint32_t sbase = smem_u32(sm);
    int tid = threadIdx.x;
    int warp = tid >> 5, lane = tid & 31;
    size_t rowbase = (size_t)blockIdx.x * 128;

    int wm = warp & 3;
    int wn = warp >> 2;
    int lr = lane & 15;
    int lc = lane >> 4;
    uint32_t aAddr = sbase + (uint32_t)(wm * 32 + lr) * KV_STRIDE_B + lc * 16;
    uint32_t bAddr = sbase + (uint32_t)lr * KV_STRIDE_B + (wn * 64 + lc * 8) * 2;

    float cQ[2][8][4], cG[2][8][4];
#pragma unroll
    for (int mt = 0; mt < 2; mt++)
#pragma unroll
        for (int nt = 0; nt < 8; nt++)
#pragma unroll
            for (int e = 0; e < 4; e++) { cQ[mt][nt][e] = 0.f; cG[mt][nt][e] = 0.f; }

#pragma unroll 1
    for (int kc = 0; kc < 4; kc++) {
        int k0 = kc * 128;
        // ---- A tile: LN(s) chunk -> hi/lo ----
#pragma unroll
        for (int t = 0; t < 16; t++) {
            int j   = tid + t * 256;
            int row = j >> 5;
            int c4  = (j & 31) * 4;
            float4 v = *(const float4*)(s + (rowbase + row) * DTOK + k0 + c4);
            float mu = g_smu[rowbase + row];
            float rs = g_srs[rowbase + row];
            float4 gv = *(const float4*)(lng + k0 + c4);
            float4 bv = *(const float4*)(lnb + k0 + c4);
            float n0 = (v.x - mu) * rs * gv.x + bv.x;
            float n1 = (v.y - mu) * rs * gv.y + bv.y;
            float n2 = (v.z - mu) * rs * gv.z + bv.z;
            float n3 = (v.w - mu) * rs * gv.w + bv.w;
            float h0, l0, h1, l1, h2, l2, h3, l3;
            split_h(n0, h0, l0); split_h(n1, h1, l1);
            split_h(n2, h2, l2); split_h(n3, h3, l3);
            uint32_t off = (uint32_t)row * KV_STRIDE_B + c4 * 2;
            *(uint32_t*)(sm + OFF_AHI + off)     = pack_h2(h0, h1);
            *(uint32_t*)(sm + OFF_AHI + off + 4) = pack_h2(h2, h3);
            *(uint32_t*)(sm + OFF_ALO + off)     = pack_h2(l0, l1);
            *(uint32_t*)(sm + OFF_ALO + off + 4) = pack_h2(l2, l3);
        }
        // ---- B tiles: direct fp16 copy (rows k0..k0+127) ----
#pragma unroll
        for (int t = 0; t < 8; t++) {
            int j   = tid + t * 256;
            int row = j >> 4;
            int c8  = (j & 15) * 8;
            uint32_t off = (uint32_t)row * KV_STRIDE_B + c8 * 2;
            *(uint4*)(sm + OFF_BQ + off) =
                *(const uint4*)(g_hwq + (size_t)(k0 + row) * DATOM + c8);
            *(uint4*)(sm + OFF_BG + off) =
                *(const uint4*)(g_hwg + (size_t)(k0 + row) * DATOM + c8);
        }
        __syncthreads();
#pragma unroll
        for (int ks = 0; ks < 8; ks++) {
            uint32_t ak = aAddr + ks * 32;
            uint32_t bk = bAddr + ks * 16 * KV_STRIDE_B;
            uint32_t aH[2][4], aL[2][4];
            ldm4(aH[0], ak + OFF_AHI);
            ldm4(aH[1], ak + OFF_AHI + 16 * KV_STRIDE_B);
            ldm4(aL[0], ak + OFF_ALO);
            ldm4(aL[1], ak + OFF_ALO + 16 * KV_STRIDE_B);
            {
                uint32_t b[4][4];
#pragma unroll
                for (int i = 0; i < 4; i++) ldm4t(b[i], bk + OFF_BQ + i * 32);
#pragma unroll
                for (int mt = 0; mt < 2; mt++)
#pragma unroll
                    for (int i = 0; i < 4; i++) {
                        mma16816(cQ[mt][2 * i],     aH[mt], b[i][0], b[i][1]);
                        mma16816(cQ[mt][2 * i + 1], aH[mt], b[i][2], b[i][3]);
                        mma16816(cQ[mt][2 * i],     aL[mt], b[i][0], b[i][1]);
                        mma16816(cQ[mt][2 * i + 1], aL[mt], b[i][2], b[i][3]);
                    }
            }
            {
                uint32_t b[4][4];
#pragma unroll
                for (int i = 0; i < 4; i++) ldm4t(b[i], bk + OFF_BG + i * 32);
#pragma unroll
                for (int mt = 0; mt < 2; mt++)
#pragma unroll
                    for (int i = 0; i < 4; i++) {
                        mma16816(cG[mt][2 * i],     aH[mt], b[i][0], b[i][1]);
                        mma16816(cG[mt][2 * i + 1], aH[mt], b[i][2], b[i][3]);
                        mma16816(cG[mt][2 * i],     aL[mt], b[i][0], b[i][1]);
                        mma16816(cG[mt][2 * i + 1], aL[mt], b[i][2], b[i][3]);
                    }
            }
        }
        __syncthreads();
    }
    // ---- epilogue: stage Q and G, single sync, coalesced writes ----
    {
        float* stgQ = (float*)(sm + OFF_AHI);   // 69632 B
        float* stgG = (float*)(sm + OFF_BQ);    // 69632 B
        int cr = lane >> 2, cc2 = (lane & 3) * 2;
#pragma unroll
        for (int mt = 0; mt < 2; mt++) {
            int r0 = wm * 32 + mt * 16 + cr;
#pragma unroll
            for (int nt = 0; nt < 8; nt++) {
                int cc = wn * 64 + nt * 8 + cc2;
                *(float2*)&stgQ[r0 * STG_STRIDE + cc] =
                    make_float2(cQ[mt][nt][0], cQ[mt][nt][1]);
                *(float2*)&stgQ[(r0 + 8) * STG_STRIDE + cc] =
                    make_float2(cQ[mt][nt][2], cQ[mt][nt][3]);
                *(float2*)&stgG[r0 * STG_STRIDE + cc] =
                    make_float2(cG[mt][nt][0], cG[mt][nt][1]);
                *(float2*)&stgG[(r0 + 8) * STG_STRIDE + cc] =
                    make_float2(cG[mt][nt][2], cG[mt][nt][3]);
            }
        }
        __syncthreads();
#pragma unroll
        for (int t = 0; t < 16; t++) {
            int j  = tid + t * 256;
            int r  = j >> 5;
            int c4 = (j & 31) * 4;
            *(float4*)&g_Q[(rowbase + r) * DATOM + c4] =
                *(float4*)&stgQ[r * STG_STRIDE + c4];
            *(float4*)&g_G[(rowbase + r) * DATOM + c4] =
                *(float4*)&stgG[r * STG_STRIDE + c4];
        }
    }
}

// ==================================================================
// Kernel 4: ragged window attention + gate. WARP PER TOKEN.
// Writes U pre-split as fp16 hi/lo (out kernel loads directly).
// ==================================================================
__global__ void __launch_bounds__(256, 8)
attn_gate_kernel(const int* __restrict__ starts, const int* __restrict__ counts,
                 const float* __restrict__ tmask) {
    int warp = threadIdx.x >> 5, lane = threadIdx.x & 31;
    int bt = blockIdx.x * 8 + warp;      // token index
    int b  = bt >> 12;                   // batch (N = 4096)
    int start = starts[bt];
    int count = counts[bt];
    const float scale = 0.17677669529663687f;   // 1/sqrt(32)

    float4 q = *(const float4*)(g_Q + (size_t)bt * DATOM + lane * 4);
    const float* kb = g_K + ((size_t)b * MM + start) * DATOM;

    float sc[WMAX];
#pragma unroll
    for (int w = 0; w < WMAX; w++) {
        float d = -1e30f;
        if (w < count) {
            float4 k4 = *(const float4*)(kb + (size_t)w * DATOM + lane * 4);
            float t = q.x * k4.x + q.y * k4.y + q.z * k4.z + q.w * k4.w;
            t += __shfl_xor_sync(0xffffffffu, t, 1);
            t += __shfl_xor_sync(0xffffffffu, t, 2);
            t += __shfl_xor_sync(0xffffffffu, t, 4);
            d = t * scale;
        }
        sc[w] = d;
    }
    float m = -1e30f;
#pragma unroll
    for (int w = 0; w < WMAX; w++) m = fmaxf(m, sc[w]);
    float sum = 0.f;
#pragma unroll
    for (int w = 0; w < WMAX; w++) { sc[w] = expf(sc[w] - m); sum += sc[w]; }
    float inv = 1.f / sum;

    const float* vb = g_V + ((size_t)b * MM + start) * DATOM;
    float4 acc = make_float4(0.f, 0.f, 0.f, 0.f);
#pragma unroll
    for (int w = 0; w < WMAX; w++) {
        if (w < count) {
            float p = sc[w] * inv;
            float4 v4 = *(const float4*)(vb + (size_t)w * DATOM + lane * 4);
            acc.x = fmaf(p, v4.x, acc.x);
            acc.y = fmaf(p, v4.y, acc.y);
            acc.z = fmaf(p, v4.z, acc.z);
            acc.w = fmaf(p, v4.w, acc.w);
        }
    }
    float msk = tmask[bt];
    float4 g = *(const float4*)(g_G + (size_t)bt * DATOM + lane * 4);
    float4 u;
    u.x = acc.x * msk / (1.f + expf(-g.x));
    u.y = acc.y * msk / (1.f + expf(-g.y));
    u.z = acc.z * msk / (1.f + expf(-g.z));
    u.w = acc.w * msk / (1.f + expf(-g.w));

    float hx, lx, hy, ly, hz, lz, hw, lw;
    split_h(u.x, hx, lx); split_h(u.y, hy, ly);
    split_h(u.z, hz, lz); split_h(u.w, hw, lw);
    uint2 hv = make_uint2(pack_h2(hx, hy), pack_h2(hz, hw));
    uint2 lv = make_uint2(pack_h2(lx, ly), pack_h2(lz, lw));
    *(uint2*)(g_Uhi + (size_t)bt * DATOM + lane * 4) = hv;
    *(uint2*)(g_Ulo + (size_t)bt * DATOM + lane * 4) = lv;
}

// ==================================================================
// Kernel 5 (mma.sync fp16 2-pass, merged): out = U @ w_o.
// Grid (NTOK/128, 2): each block does 2 col-quarters (256 cols).
// A tile: direct copy of pre-split U. B: direct fp16 copies.
// ==================================================================
__global__ void __launch_bounds__(256, 1)
out_mma_kernel(float* __restrict__ out) {
    char* sm = dyn_smem;
    uint32_t sbase = smem_u32(sm);
    int tid = threadIdx.x;
    int warp = tid >> 5, lane = tid & 31;
    size_t rowbase = (size_t)blockIdx.x * 128;
    int colbase = blockIdx.y * 256;

    // ---- A tile: direct copy of g_Uhi/g_Ulo; B tiles: fp16 copies ----
#pragma unroll
    for (int t = 0; t < 8; t++) {
        int j   = tid + t * 256;         // 0..2047 uint4
        int row = j >> 4;
        int c8  = (j & 15) * 8;
        uint32_t off = (uint32_t)row * KV_STRIDE_B + c8 * 2;
        *(uint4*)(sm + OFF_AHI + off) =
            *(const uint4*)(g_Uhi + (rowbase + row) * DATOM + c8);
        *(uint4*)(sm + OFF_ALO + off) =
            *(const uint4*)(g_Ulo + (rowbase + row) * DATOM + c8);
        *(uint4*)(sm + OFF_BQ + off) =
            *(const uint4*)(g_hwo + (size_t)row * DTOK + colbase + c8);
        *(uint4*)(sm + OFF_BG + off) =
            *(const uint4*)(g_hwo + (size_t)row * DTOK + colbase + 128 + c8);
    }
    __syncthreads();

    int wm = warp & 3;
    int wn = warp >> 2;
    int lr = lane & 15;
    int lc = lane >> 4;
    uint32_t aAddr = sbase + (uint32_t)(wm * 32 + lr) * KV_STRIDE_B + lc * 16;
    uint32_t bAddr = sbase + (uint32_t)lr * KV_STRIDE_B + (wn * 64 + lc * 8) * 2;

    float c0[2][8][4], c1[2][8][4];
#pragma unroll
    for (int mt = 0; mt < 2; mt++)
#pragma unroll
        for (int nt = 0; nt < 8; nt++)
#pragma unroll
            for (int e = 0; e < 4; e++) { c0[mt][nt][e] = 0.f; c1[mt][nt][e] = 0.f; }

#pragma unroll
    for (int ks = 0; ks < 8; ks++) {
        uint32_t ak = aAddr + ks * 32;
        uint32_t bk = bAddr + ks * 16 * KV_STRIDE_B;
        uint32_t aH[2][4], aL[2][4];
        ldm4(aH[0], ak + OFF_AHI);
        ldm4(aH[1], ak + OFF_AHI + 16 * KV_STRIDE_B);
        ldm4(aL[0], ak + OFF_ALO);
        ldm4(aL[1], ak + OFF_ALO + 16 * KV_STRIDE_B);
        {
            uint32_t b[4][4];
#pragma unroll
            for (int i = 0; i < 4; i++) ldm4t(b[i], bk + OFF_BQ + i * 32);
#pragma unroll
            for (int mt = 0; mt < 2; mt++)
#pragma unroll
                for (int i = 0; i < 4; i++) {
                    mma16816(c0[mt][2 * i],     aH[mt], b[i][0], b[i][1]);
                    mma16816(c0[mt][2 * i + 1], aH[mt], b[i][2], b[i][3]);
                    mma16816(c0[mt][2 * i],     aL[mt], b[i][0], b[i][1]);
                    mma16816(c0[mt][2 * i + 1], aL[mt], b[i][2], b[i][3]);
                }
        }
        {
            uint32_t b[4][4];
#pragma unroll
            for (int i = 0; i < 4; i++) ldm4t(b[i], bk + OFF_BG + i * 32);
#pragma unroll
            for (int mt = 0; mt < 2; mt++)
#pragma unroll
                for (int i = 0; i < 4; i++) {
                    mma16816(c1[mt][2 * i],     aH[mt], b[i][0], b[i][1]);
                    mma16816(c1[mt][2 * i + 1], aH[mt], b[i][2], b[i][3]);
                    mma16816(c1[mt][2 * i],     aL[mt], b[i][0], b[i][1]);
                    mma16816(c1[mt][2 * i + 1], aL[mt], b[i][2], b[i][3]);
                }
        }
    }
    __syncthreads();
    {
        float* stg0 = (float*)(sm + OFF_AHI);
        float* stg1 = (float*)(sm + OFF_BQ);
        int cr = lane >> 2, cc2 = (lane & 3) * 2;
#pragma unroll
        for (int mt = 0; mt < 2; mt++) {
            int r0 = wm * 32 + mt * 16 + cr;
#pragma unroll
            for (int nt = 0; nt < 8; nt++) {
                int cc = wn * 64 + nt * 8 + cc2;
                *(float2*)&stg0[r0 * STG_STRIDE + cc] =
                    make_float2(c0[mt][nt][0], c0[mt][nt][1]);
                *(float2*)&stg0[(r0 + 8) * STG_STRIDE + cc] =
                    make_float2(c0[mt][nt][2], c0[mt][nt][3]);
                *(float2*)&stg1[r0 * STG_STRIDE + cc] =
                    make_float2(c1[mt][nt][0], c1[mt][nt][1]);
                *(float2*)&stg1[(r0 + 8) * STG_STRIDE + cc] =
                    make_float2(c1[mt][nt][2], c1[mt][nt][3]);
            }
        }
        __syncthreads();
#pragma unroll
        for (int t = 0; t < 16; t++) {
            int j  = tid + t * 256;
            int r  = j >> 5;
            int c4 = (j & 31) * 4;
            *(float4*)&out[(rowbase + r) * DTOK + colbase + c4] =
                *(float4*)&stg0[r * STG_STRIDE + c4];
            *(float4*)&out[(rowbase + r) * DTOK + colbase + 128 + c4] =
                *(float4*)&stg1[r * STG_STRIDE + c4];
        }
    }
}

// ==================================================================
// Launch. Input order: s, a, starts, counts, token_mask, w_q, w_k,
// w_v, w_g, w_o, ln_q_g, ln_q_b, ln_kv_g, ln_kv_b. Output fp32.
// ==================================================================
extern "C" void kernel_launch(void* const* d_in, const int* in_sizes, int n_in,
                              void* d_out, int out_size) {
    const float* s      = (const float*)d_in[0];
    const float* a      = (const float*)d_in[1];
    const int*   starts = (const int*)  d_in[2];
    const int*   counts = (const int*)  d_in[3];
    const float* tmask  = (const float*)d_in[4];
    const float* wq     = (const float*)d_in[5];
    const float* wk     = (const float*)d_in[6];
    const float* wv     = (const float*)d_in[7];
    const float* wg     = (const float*)d_in[8];
    const float* wo     = (const float*)d_in[9];
    const float* lnqg   = (const float*)d_in[10];
    const float* lnqb   = (const float*)d_in[11];
    const float* lnkg   = (const float*)d_in[12];
    const float* lnkb   = (const float*)d_in[13];
    float* out = (float*)d_out;

    cudaFuncSetAttribute(kv_mma_kernel,
                         cudaFuncAttributeMaxDynamicSharedMemorySize, KV_SMEM);
    cudaFuncSetAttribute(qg_mma_kernel,
                         cudaFuncAttributeMaxDynamicSharedMemorySize, QG_SMEM);
    cudaFuncSetAttribute(out_mma_kernel,
                         cudaFuncAttributeMaxDynamicSharedMemorySize, QG_SMEM);

    wprep_kernel<<<256, 256>>>(wq, wk, wv, wg, wo);
    stats_s_kernel<<<NTOK / 8, 256>>>(s);
    kv_mma_kernel<<<NATOM / 128, 256, KV_SMEM>>>(a, lnkg, lnkb);
    qg_mma_kernel<<<NTOK / 128, 256, QG_SMEM>>>(s, lnqg, lnqb);
    attn_gate_kernel<<<NTOK / 8, 256>>>(starts, counts, tmask);
    out_mma_kernel<<<dim3(NTOK / 128, 2), 256, QG_SMEM>>>(out);
}

// round 11
// speedup vs baseline: 2.7922x; 1.0486x over previous
#include <cuda_runtime.h>
#include <cuda_fp16.h>
#include <cstdint>
#include <math.h>

// Problem constants
#define BB     4
#define NN     4096
#define MM     32768
#define DTOK   512
#define DATOM  128
#define NHEAD  4
#define DH     32
#define WMAX   16
#define LNEPS  1e-5f

#define NTOK   (BB * NN)    // 16384 token rows
#define NATOM  (BB * MM)    // 131072 atom rows

// Single dynamic smem symbol shared by all kernels (cast locally).
extern __shared__ char dyn_smem[];

// -------- scratch (device globals; no allocations allowed) --------
__device__ __half g_K[(size_t)NATOM * DATOM];     // fp16 now
__device__ __half g_V[(size_t)NATOM * DATOM];     // fp16 now
__device__ float g_Q[(size_t)NTOK * DATOM];
__device__ float g_G[(size_t)NTOK * DATOM];
__device__ __half g_Uhi[(size_t)NTOK * DATOM];
__device__ __half g_Ulo[(size_t)NTOK * DATOM];
__device__ float g_smu[NTOK];
__device__ float g_srs[NTOK];
// fp16 weights (converted once per launch by wprep_kernel)
__device__ __half g_hwk[DATOM * DATOM];
__device__ __half g_hwv[DATOM * DATOM];
__device__ __half g_hwq[DTOK * DATOM];
__device__ __half g_hwg[DTOK * DATOM];
__device__ __half g_hwo[DATOM * DTOK];

__device__ __forceinline__ float warp_sum(float v) {
#pragma unroll
    for (int o = 16; o > 0; o >>= 1) v += __shfl_xor_sync(0xffffffffu, v, o);
    return v;
}
__device__ __forceinline__ uint32_t smem_u32(const void* p) {
    uint32_t a;
    asm("{ .reg .u64 t; cvta.to.shared.u64 t, %1; cvt.u32.u64 %0, t; }"
        : "=r"(a) : "l"(p));
    return a;
}
__device__ __forceinline__ uint32_t pack_h2(float a, float b) {
    __half2 t = __floats2half2_rn(a, b);
    return *(uint32_t*)&t;
}
// hi = fp16 round of x; lo = x - hi (A-side exact split)
__device__ __forceinline__ void split_h(float x, float& hi, float& lo) {
    __half h = __float2half_rn(x);
    hi = __half2float(h);
    lo = x - hi;
}

// ---- cp.async helpers (sm_80+) ----
#define CP_ASYNC16(dst, src) \
    asm volatile("cp.async.cg.shared.global [%0], [%1], 16;" \
                 :: "r"((uint32_t)(dst)), "l"(src))
#define CP_COMMIT() asm volatile("cp.async.commit_group;" ::: "memory")
#define CP_WAIT0()  asm volatile("cp.async.wait_group 0;" ::: "memory")
#define CP_WAIT1()  asm volatile("cp.async.wait_group 1;" ::: "memory")

// ---- warp-level MMA helpers ----
__device__ __forceinline__ void ldm4(uint32_t* d, uint32_t addr) {
    asm volatile("ldmatrix.sync.aligned.m8n8.x4.shared.b16 {%0,%1,%2,%3}, [%4];"
                 : "=r"(d[0]), "=r"(d[1]), "=r"(d[2]), "=r"(d[3]) : "r"(addr));
}
__device__ __forceinline__ void ldm4t(uint32_t* d, uint32_t addr) {
    asm volatile("ldmatrix.sync.aligned.m8n8.x4.trans.shared.b16 {%0,%1,%2,%3}, [%4];"
                 : "=r"(d[0]), "=r"(d[1]), "=r"(d[2]), "=r"(d[3]) : "r"(addr));
}
__device__ __forceinline__ void mma16816(float* c, const uint32_t* a,
                                         uint32_t b0, uint32_t b1) {
    asm volatile(
        "mma.sync.aligned.m16n8k16.row.col.f32.f16.f16.f32 "
        "{%0,%1,%2,%3}, {%4,%5,%6,%7}, {%8,%9}, {%0,%1,%2,%3};"
        : "+f"(c[0]), "+f"(c[1]), "+f"(c[2]), "+f"(c[3])
        : "r"(a[0]), "r"(a[1]), "r"(a[2]), "r"(a[3]), "r"(b0), "r"(b1));
}

// Shared tile geometry (128x128 fp16 tiles, padded)
#define KV_STRIDE_B 272                   // bytes per smem row (136 halves)
#define KV_TILE_B   (128 * KV_STRIDE_B)   // 34816 bytes
#define STG_STRIDE  136                   // floats per staged row
#define STG_STRIDE_H 136                  // halves per fp16 staged row

// ==================================================================
// Kernel 0: convert all weights to fp16 once.
// ==================================================================
__global__ void wprep_kernel(const float* __restrict__ wq,
                             const float* __restrict__ wk,
                             const float* __restrict__ wv,
                             const float* __restrict__ wg,
                             const float* __restrict__ wo) {
    int i = blockIdx.x * 256 + threadIdx.x;   // 0..65535
    if (i < DATOM * DATOM) {
        g_hwk[i] = __float2half_rn(wk[i]);
        g_hwv[i] = __float2half_rn(wv[i]);
    }
    g_hwq[i] = __float2half_rn(wq[i]);
    g_hwg[i] = __float2half_rn(wg[i]);
    g_hwo[i] = __float2half_rn(wo[i]);
}

// ==================================================================
// Kernel 1: per-row LN stats for s (rows of 512). One warp per row.
// ==================================================================
__global__ void stats_s_kernel(const float* __restrict__ s) {
    int row  = blockIdx.x * 8 + (threadIdx.x >> 5);
    int lane = threadIdx.x & 31;
    const float4* p = (const float4*)(s + (size_t)row * DTOK);
    float sum = 0.f, sq = 0.f;
#pragma unroll
    for (int j = 0; j < 4; j++) {
        float4 v = p[lane + 32 * j];
        sum += v.x + v.y + v.z + v.w;
        sq  += v.x * v.x + v.y * v.y + v.z * v.z + v.w * v.w;
    }
    sum = warp_sum(sum);
    sq  = warp_sum(sq);
    if (lane == 0) {
        float mu  = sum * (1.f / DTOK);
        float var = sq * (1.f / DTOK) - mu * mu;
        g_smu[row] = mu;
        g_srs[row] = rsqrtf(var + LNEPS);
    }
}

// ==================================================================
// Kernel 2: LN(a) + K,V GEMM. W copies via cp.async overlap A phase.
// K/V results written fp16.
// ==================================================================
#define OFF_AHI  0
#define OFF_ALO  (OFF_AHI + KV_TILE_B)
#define OFF_WK   (OFF_ALO + KV_TILE_B)
#define OFF_WV   (OFF_WK + KV_TILE_B)
#define KV_SMEM  (OFF_WV + KV_TILE_B)     // 139264 bytes

__global__ void __launch_bounds__(256, 1)
kv_mma_kernel(const float* __restrict__ a, const float* __restrict__ lng,
              const float* __restrict__ lnb) {
    char* sm = dyn_smem;
    uint32_t sbase = smem_u32(sm);
    int tid = threadIdx.x;
    int warp = tid >> 5, lane = tid & 31;
    size_t rowbase = (size_t)blockIdx.x * 128;

    // ---- W tiles via cp.async FIRST (overlaps with A compute below) ----
#pragma unroll
    for (int t = 0; t < 8; t++) {
        int j   = tid + t * 256;
        int row = j >> 4;
        int c8  = (j & 15) * 8;
        uint32_t off = (uint32_t)row * KV_STRIDE_B + c8 * 2;
        CP_ASYNC16(sbase + OFF_WK + off, g_hwk + row * DATOM + c8);
        CP_ASYNC16(sbase + OFF_WV + off, g_hwv + row * DATOM + c8);
    }
    CP_COMMIT();

    // ---- A tile: LN rows -> hi/lo fp16 ----
    float4 gln = ((const float4*)lng)[lane];
    float4 bln = ((const float4*)lnb)[lane];
    for (int r = warp; r < 128; r += 8) {
        float4 v = *(const float4*)(a + (rowbase + r) * DATOM + lane * 4);
        float sum = warp_sum(v.x + v.y + v.z + v.w);
        float sq  = warp_sum(v.x * v.x + v.y * v.y + v.z * v.z + v.w * v.w);
        float mu  = sum * (1.f / 128.f);
        float rs  = rsqrtf(sq * (1.f / 128.f) - mu * mu + LNEPS);
        float n0 = (v.x - mu) * rs * gln.x + bln.x;
        float n1 = (v.y - mu) * rs * gln.y + bln.y;
        float n2 = (v.z - mu) * rs * gln.z + bln.z;
        float n3 = (v.w - mu) * rs * gln.w + bln.w;
        float h0, l0, h1, l1, h2, l2, h3, l3;
        split_h(n0, h0, l0); split_h(n1, h1, l1);
        split_h(n2, h2, l2); split_h(n3, h3, l3);
        uint32_t off = (uint32_t)r * KV_STRIDE_B + lane * 8;
        *(uint32_t*)(sm + OFF_AHI + off)     = pack_h2(h0, h1);
        *(uint32_t*)(sm + OFF_AHI + off + 4) = pack_h2(h2, h3);
        *(uint32_t*)(sm + OFF_ALO + off)     = pack_h2(l0, l1);
        *(uint32_t*)(sm + OFF_ALO + off + 4) = pack_h2(l2, l3);
    }
    CP_WAIT0();
    __syncthreads();

    int wm = warp & 3;
    int wn = warp >> 2;
    int lr = lane & 15;
    int lc = lane >> 4;

    uint32_t aAddr = sbase + (uint32_t)(wm * 32 + lr) * KV_STRIDE_B + lc * 16;
    uint32_t bAddr = sbase + (uint32_t)lr * KV_STRIDE_B + (wn * 64 + lc * 8) * 2;

    float cK[2][8][4], cV[2][8][4];
#pragma unroll
    for (int mt = 0; mt < 2; mt++)
#pragma unroll
        for (int nt = 0; nt < 8; nt++)
#pragma unroll
            for (int e = 0; e < 4; e++) { cK[mt][nt][e] = 0.f; cV[mt][nt][e] = 0.f; }

#pragma unroll
    for (int ks = 0; ks < 8; ks++) {
        uint32_t ak = aAddr + ks * 32;
        uint32_t bk = bAddr + ks * 16 * KV_STRIDE_B;
        uint32_t aH[2][4], aL[2][4];
        ldm4(aH[0], ak + OFF_AHI);
        ldm4(aH[1], ak + OFF_AHI + 16 * KV_STRIDE_B);
        ldm4(aL[0], ak + OFF_ALO);
        ldm4(aL[1], ak + OFF_ALO + 16 * KV_STRIDE_B);
        {
            uint32_t b[4][4];
#pragma unroll
            for (int i = 0; i < 4; i++) ldm4t(b[i], bk + OFF_WK + i * 32);
#pragma unroll
            for (int mt = 0; mt < 2; mt++)
#pragma unroll
                for (int i = 0; i < 4; i++) {
                    mma16816(cK[mt][2 * i],     aH[mt], b[i][0], b[i][1]);
                    mma16816(cK[mt][2 * i + 1], aH[mt], b[i][2], b[i][3]);
                    mma16816(cK[mt][2 * i],     aL[mt], b[i][0], b[i][1]);
                    mma16816(cK[mt][2 * i + 1], aL[mt], b[i][2], b[i][3]);
                }
        }
        {
            uint32_t b[4][4];
#pragma unroll
            for (int i = 0; i < 4; i++) ldm4t(b[i], bk + OFF_WV + i * 32);
#pragma unroll
            for (int mt = 0; mt < 2; mt++)
#pragma unroll
                for (int i = 0; i < 4; i++) {
                    mma16816(cV[mt][2 * i],     aH[mt], b[i][0], b[i][1]);
                    mma16816(cV[mt][2 * i + 1], aH[mt], b[i][2], b[i][3]);
                    mma16816(cV[mt][2 * i],     aL[mt], b[i][0], b[i][1]);
                    mma16816(cV[mt][2 * i + 1], aL[mt], b[i][2], b[i][3]);
                }
        }
    }
    __syncthreads();
    // ---- epilogue: fp16 staging + fp16 global writes ----
    {
        __half* stgK = (__half*)(sm + OFF_AHI);
        __half* stgV = (__half*)(sm + OFF_WK);
        int cr = lane >> 2, cc2 = (lane & 3) * 2;
#pragma unroll
        for (int mt = 0; mt < 2; mt++) {
            int r0 = wm * 32 + mt * 16 + cr;
#pragma unroll
            for (int nt = 0; nt < 8; nt++) {
                int cc = wn * 64 + nt * 8 + cc2;
                *(__half2*)&stgK[r0 * STG_STRIDE_H + cc] =
                    __floats2half2_rn(cK[mt][nt][0], cK[mt][nt][1]);
                *(__half2*)&stgK[(r0 + 8) * STG_STRIDE_H + cc] =
                    __floats2half2_rn(cK[mt][nt][2], cK[mt][nt][3]);
                *(__half2*)&stgV[r0 * STG_STRIDE_H + cc] =
                    __floats2half2_rn(cV[mt][nt][0], cV[mt][nt][1]);
                *(__half2*)&stgV[(r0 + 8) * STG_STRIDE_H + cc] =
                    __floats2half2_rn(cV[mt][nt][2], cV[mt][nt][3]);
            }
        }
        __syncthreads();
#pragma unroll
        for (int t = 0; t < 8; t++) {
            int j  = tid + t * 256;
            int r  = j >> 4;
            int c8 = (j & 15) * 8;
            *(uint4*)&g_K[(rowbase + r) * DATOM + c8] =
                *(uint4*)&stgK[r * STG_STRIDE_H + c8];
            *(uint4*)&g_V[(rowbase + r) * DATOM + c8] =
                *(uint4*)&stgV[r * STG_STRIDE_H + c8];
        }
    }
}

// ==================================================================
// Kernel 3: LN(s) + Q AND G. B tiles double-buffered via cp.async.
// SMEM: A_hi, A_lo, BQ0, BG0, BQ1, BG1 (6 x 34816 = 208896 B).
// ==================================================================
#define OFF_B0   (2 * KV_TILE_B)
#define OFF_B1   (4 * KV_TILE_B)
#define QG_SMEM  (6 * KV_TILE_B)    // 208896 bytes

__global__ void __launch_bounds__(256, 1)
qg_mma_kernel(const float* __restrict__ s, const float* __restrict__ lng,
              const float* __restrict__ lnb) {
    char* sm = dyn_smem;
    uint32_t sbase = smem_u32(sm);
    int tid = threadIdx.x;
    int warp = tid >> 5, lane = tid & 31;
    size_t rowbase = (size_t)blockIdx.x * 128;

    int wm = warp & 3;
    int wn = warp >> 2;
    int lr = lane & 15;
    int lc = lane >> 4;
    uint32_t aAddr = sbase + (uint32_t)(wm * 32 + lr) * KV_STRIDE_B + lc * 16;
    uint32_t bAddr = sbase + (uint32_t)lr * KV_STRIDE_B + (wn * 64 + lc * 8) * 2;

    // prologue: B(0) into buffer 0
#pragma unroll
    for (int t = 0; t < 8; t++) {
        int j   = tid + t * 256;
        int row = j >> 4;
        int c8  = (j & 15) * 8;
        uint32_t off = (uint32_t)row * KV_STRIDE_B + c8 * 2;
        CP_ASYNC16(sbase + OFF_B0 + off,
                   g_hwq + (size_t)row * DATOM + c8);
        CP_ASYNC16(sbase + OFF_B0 + KV_TILE_B + off,
                   g_hwg + (size_t)row * DATOM + c8);
    }
    CP_COMMIT();

    float cQ[2][8][4], cG[2][8][4];
#pragma unroll
    for (int mt = 0; mt < 2; mt++)
#pragma unroll
        for (int nt = 0; nt < 8; nt++)
#pragma unroll
            for (int e = 0; e < 4; e++) { cQ[mt][nt][e] = 0.f; cG[mt][nt][e] = 0.f; }

#pragma unroll 1
    for (int kc = 0; kc < 4; kc++) {
        int k0 = kc * 128;
        // ---- A tile: LN(s) chunk -> hi/lo ----
#pragma unroll
        for (int t = 0; t < 16; t++) {
            int j   = tid + t * 256;
            int row = j >> 5;
            int c4  = (j & 31) * 4;
            float4 v = *(const float4*)(s + (rowbase + row) * DTOK + k0 + c4);
            float mu = g_smu[rowbase + row];
            float rs = g_srs[rowbase + row];
            float4 gv = *(const float4*)(lng + k0 + c4);
            float4 bv = *(const float4*)(lnb + k0 + c4);
            float n0 = (v.x - mu) * rs * gv.x + bv.x;
            float n1 = (v.y - mu) * rs * gv.y + bv.y;
            float n2 = (v.z - mu) * rs * gv.z + bv.z;
            float n3 = (v.w - mu) * rs * gv.w + bv.w;
            float h0, l0, h1, l1, h2, l2, h3, l3;
            split_h(n0, h0, l0); split_h(n1, h1, l1);
            split_h(n2, h2, l2); split_h(n3, h3, l3);
            uint32_t off = (uint32_t)row * KV_STRIDE_B + c4 * 2;
            *(uint32_t*)(sm + OFF_AHI + off)     = pack_h2(h0, h1);
            *(uint32_t*)(sm + OFF_AHI + off + 4) = pack_h2(h2, h3);
            *(uint32_t*)(sm + OFF_ALO + off)     = pack_h2(l0, l1);
            *(uint32_t*)(sm + OFF_ALO + off + 4) = pack_h2(l2, l3);
        }
        // ---- prefetch B(kc+1) into alternate buffer ----
        if (kc < 3) {
            uint32_t dstB = sbase + (((kc + 1) & 1) ? OFF_B1 : OFF_B0);
            int kn = (kc + 1) * 128;
#pragma unroll
            for (int t = 0; t < 8; t++) {
                int j   = tid + t * 256;
                int row = j >> 4;
                int c8  = (j & 15) * 8;
                uint32_t off = (uint32_t)row * KV_STRIDE_B + c8 * 2;
                CP_ASYNC16(dstB + off,
                           g_hwq + (size_t)(kn + row) * DATOM + c8);
                CP_ASYNC16(dstB + KV_TILE_B + off,
                           g_hwg + (size_t)(kn + row) * DATOM + c8);
            }
            CP_COMMIT();
            CP_WAIT1();   // B(kc) complete, B(kc+1) may be in flight
        } else {
            CP_WAIT0();
        }
        __syncthreads();

        uint32_t bufQ = ((kc & 1) ? OFF_B1 : OFF_B0);
        uint32_t bufG = bufQ + KV_TILE_B;
#pragma unroll
        for (int ks = 0; ks < 8; ks++) {
            uint32_t ak = aAddr + ks * 32;
            uint32_t bk = bAddr + ks * 16 * KV_STRIDE_B;
            uint32_t aH[2][4], aL[2][4];
            ldm4(aH[0], ak + OFF_AHI);
            ldm4(aH[1], ak + OFF_AHI + 16 * KV_STRIDE_B);
            ldm4(aL[0], ak + OFF_ALO);
            ldm4(aL[1], ak + OFF_ALO + 16 * KV_STRIDE_B);
            {
                uint32_t b[4][4];
#pragma unroll
                for (int i = 0; i < 4; i++) ldm4t(b[i], bk + bufQ + i * 32);
#pragma unroll
                for (int mt = 0; mt < 2; mt++)
#pragma unroll
                    for (int i = 0; i < 4; i++) {
                        mma16816(cQ[mt][2 * i],     aH[mt], b[i][0], b[i][1]);
                        mma16816(cQ[mt][2 * i + 1], aH[mt], b[i][2], b[i][3]);
                        mma16816(cQ[mt][2 * i],     aL[mt], b[i][0], b[i][1]);
                        mma16816(cQ[mt][2 * i + 1], aL[mt], b[i][2], b[i][3]);
                    }
            }
            {
                uint32_t b[4][4];
#pragma unroll
                for (int i = 0; i < 4; i++) ldm4t(b[i], bk + bufG + i * 32);
#pragma unroll
                for (int mt = 0; mt < 2; mt++)
#pragma unroll
                    for (int i = 0; i < 4; i++) {
                        mma16816(cG[mt][2 * i],     aH[mt], b[i][0], b[i][1]);
                        mma16816(cG[mt][2 * i + 1], aH[mt], b[i][2], b[i][3]);
                        mma16816(cG[mt][2 * i],     aL[mt], b[i][0], b[i][1]);
                        mma16816(cG[mt][2 * i + 1], aL[mt], b[i][2], b[i][3]);
                    }
            }
        }
        __syncthreads();
    }
    // ---- epilogue ----
    {
        float* stgQ = (float*)(sm + OFF_B0);
        float* stgG = (float*)(sm + OFF_B1);
        int cr = lane >> 2, cc2 = (lane & 3) * 2;
#pragma unroll
        for (int mt = 0; mt < 2; mt++) {
            int r0 = wm * 32 + mt * 16 + cr;
#pragma unroll
            for (int nt = 0; nt < 8; nt++) {
                int cc = wn * 64 + nt * 8 + cc2;
                *(float2*)&stgQ[r0 * STG_STRIDE + cc] =
                    make_float2(cQ[mt][nt][0], cQ[mt][nt][1]);
                *(float2*)&stgQ[(r0 + 8) * STG_STRIDE + cc] =
                    make_float2(cQ[mt][nt][2], cQ[mt][nt][3]);
                *(float2*)&stgG[r0 * STG_STRIDE + cc] =
                    make_float2(cG[mt][nt][0], cG[mt][nt][1]);
                *(float2*)&stgG[(r0 + 8) * STG_STRIDE + cc] =
                    make_float2(cG[mt][nt][2], cG[mt][nt][3]);
            }
        }
        __syncthreads();
#pragma unroll
        for (int t = 0; t < 16; t++) {
            int j  = tid + t * 256;
            int r  = j >> 5;
            int c4 = (j & 31) * 4;
            *(float4*)&g_Q[(rowbase + r) * DATOM + c4] =
                *(float4*)&stgQ[r * STG_STRIDE + c4];
            *(float4*)&g_G[(rowbase + r) * DATOM + c4] =
                *(float4*)&stgG[r * STG_STRIDE + c4];
        }
    }
}

// ==================================================================
// Kernel 4: ragged window attention + gate. WARP PER TOKEN.
// K/V read as fp16 (half traffic). Writes U pre-split fp16 hi/lo.
// ==================================================================
__global__ void __launch_bounds__(256, 8)
attn_gate_kernel(const int* __restrict__ starts, const int* __restrict__ counts,
                 const float* __restrict__ tmask) {
    int warp = threadIdx.x >> 5, lane = threadIdx.x & 31;
    int bt = blockIdx.x * 8 + warp;      // token index
    int b  = bt >> 12;                   // batch (N = 4096)
    int start = starts[bt];
    int count = counts[bt];
    const float scale = 0.17677669529663687f;   // 1/sqrt(32)

    float4 q = *(const float4*)(g_Q + (size_t)bt * DATOM + lane * 4);
    const __half* kb = g_K + ((size_t)b * MM + start) * DATOM;

    float sc[WMAX];
#pragma unroll
    for (int w = 0; w < WMAX; w++) {
        float d = -1e30f;
        if (w < count) {
            uint2 raw = *(const uint2*)(kb + (size_t)w * DATOM + lane * 4);
            float2 f01 = __half22float2(*(__half2*)&raw.x);
            float2 f23 = __half22float2(*(__half2*)&raw.y);
            float t = q.x * f01.x + q.y * f01.y + q.z * f23.x + q.w * f23.y;
            t += __shfl_xor_sync(0xffffffffu, t, 1);
            t += __shfl_xor_sync(0xffffffffu, t, 2);
            t += __shfl_xor_sync(0xffffffffu, t, 4);
            d = t * scale;
        }
        sc[w] = d;
    }
    float m = -1e30f;
#pragma unroll
    for (int w = 0; w < WMAX; w++) m = fmaxf(m, sc[w]);
    float sum = 0.f;
#pragma unroll
    for (int w = 0; w < WMAX; w++) { sc[w] = expf(sc[w] - m); sum += sc[w]; }
    float inv = 1.f / sum;

    const __half* vb = g_V + ((size_t)b * MM + start) * DATOM;
    float4 acc = make_float4(0.f, 0.f, 0.f, 0.f);
#pragma unroll
    for (int w = 0; w < WMAX; w++) {
        if (w < count) {
            float p = sc[w] * inv;
            uint2 raw = *(const uint2*)(vb + (size_t)w * DATOM + lane * 4);
            float2 f01 = __half22float2(*(__half2*)&raw.x);
            float2 f23 = __half22float2(*(__half2*)&raw.y);
            acc.x = fmaf(p, f01.x, acc.x);
            acc.y = fmaf(p, f01.y, acc.y);
            acc.z = fmaf(p, f23.x, acc.z);
            acc.w = fmaf(p, f23.y, acc.w);
        }
    }
    float msk = tmask[bt];
    float4 g = *(const float4*)(g_G + (size_t)bt * DATOM + lane * 4);
    float4 u;
    u.x = acc.x * msk / (1.f + expf(-g.x));
    u.y = acc.y * msk / (1.f + expf(-g.y));
    u.z = acc.z * msk / (1.f + expf(-g.z));
    u.w = acc.w * msk / (1.f + expf(-g.w));

    float hx, lx, hy, ly, hz, lz, hw, lw;
    split_h(u.x, hx, lx); split_h(u.y, hy, ly);
    split_h(u.z, hz, lz); split_h(u.w, hw, lw);
    uint2 hv = make_uint2(pack_h2(hx, hy), pack_h2(hz, hw));
    uint2 lv = make_uint2(pack_h2(lx, ly), pack_h2(lz, lw));
    *(uint2*)(g_Uhi + (size_t)bt * DATOM + lane * 4) = hv;
    *(uint2*)(g_Ulo + (size_t)bt * DATOM + lane * 4) = lv;
}

// ==================================================================
// Kernel 5: out = U @ w_o. All smem loads via cp.async (pure copies).
// Grid (NTOK/128, 2): 2 col-quarters per block.
// SMEM: A_hi, A_lo, B0, B1 (4 x 34816 = 139264 B).
// ==================================================================
#define OFF_OB0  (2 * KV_TILE_B)
#define OFF_OB1  (3 * KV_TILE_B)
#define OUT_SMEM (4 * KV_TILE_B)

__global__ void __launch_bounds__(256, 1)
out_mma_kernel(float* __restrict__ out) {
    char* sm = dyn_smem;
    uint32_t sbase = smem_u32(sm);
    int tid = threadIdx.x;
    int warp = tid >> 5, lane = tid & 31;
    size_t rowbase = (size_t)blockIdx.x * 128;
    int colbase = blockIdx.y * 256;

#pragma unroll
    for (int t = 0; t < 8; t++) {
        int j   = tid + t * 256;
        int row = j >> 4;
        int c8  = (j & 15) * 8;
        uint32_t off = (uint32_t)row * KV_STRIDE_B + c8 * 2;
        CP_ASYNC16(sbase + OFF_AHI + off, g_Uhi + (rowbase + row) * DATOM + c8);
        CP_ASYNC16(sbase + OFF_ALO + off, g_Ulo + (rowbase + row) * DATOM + c8);
        CP_ASYNC16(sbase + OFF_OB0 + off,
                   g_hwo + (size_t)row * DTOK + colbase + c8);
        CP_ASYNC16(sbase + OFF_OB1 + off,
                   g_hwo + (size_t)row * DTOK + colbase + 128 + c8);
    }
    CP_COMMIT();
    CP_WAIT0();
    __syncthreads();

    int wm = warp & 3;
    int wn = warp >> 2;
    int lr = lane & 15;
    int lc = lane >> 4;
    uint32_t aAddr = sbase + (uint32_t)(wm * 32 + lr) * KV_STRIDE_B + lc * 16;
    uint32_t bAddr = sbase + (uint32_t)lr * KV_STRIDE_B + (wn * 64 + lc * 8) * 2;

    float c0[2][8][4], c1[2][8][4];
#pragma unroll
    for (int mt = 0; mt < 2; mt++)
#pragma unroll
        for (int nt = 0; nt < 8; nt++)
#pragma unroll
            for (int e = 0; e < 4; e++) { c0[mt][nt][e] = 0.f; c1[mt][nt][e] = 0.f; }

#pragma unroll
    for (int ks = 0; ks < 8; ks++) {
        uint32_t ak = aAddr + ks * 32;
        uint32_t bk = bAddr + ks * 16 * KV_STRIDE_B;
        uint32_t aH[2][4], aL[2][4];
        ldm4(aH[0], ak + OFF_AHI);
        ldm4(aH[1], ak + OFF_AHI + 16 * KV_STRIDE_B);
        ldm4(aL[0], ak + OFF_ALO);
        ldm4(aL[1], ak + OFF_ALO + 16 * KV_STRIDE_B);
        {
            uint32_t b[4][4];
#pragma unroll
            for (int i = 0; i < 4; i++) ldm4t(b[i], bk + OFF_OB0 + i * 32);
#pragma unroll
            for (int mt = 0; mt < 2; mt++)
#pragma unroll
                for (int i = 0; i < 4; i++) {
                    mma16816(c0[mt][2 * i],     aH[mt], b[i][0], b[i][1]);
                    mma16816(c0[mt][2 * i + 1], aH[mt], b[i][2], b[i][3]);
                    mma16816(c0[mt][2 * i],     aL[mt], b[i][0], b[i][1]);
                    mma16816(c0[mt][2 * i + 1], aL[mt], b[i][2], b[i][3]);
                }
        }
        {
            uint32_t b[4][4];
#pragma unroll
            for (int i = 0; i < 4; i++) ldm4t(b[i], bk + OFF_OB1 + i * 32);
#pragma unroll
            for (int mt = 0; mt < 2; mt++)
#pragma unroll
                for (int i = 0; i < 4; i++) {
                    mma16816(c1[mt][2 * i],     aH[mt], b[i][0], b[i][1]);
                    mma16816(c1[mt][2 * i + 1], aH[mt], b[i][2], b[i][3]);
                    mma16816(c1[mt][2 * i],     aL[mt], b[i][0], b[i][1]);
                    mma16816(c1[mt][2 * i + 1], aL[mt], b[i][2], b[i][3]);
                }
        }
    }
    __syncthreads();
    {
        float* stg0 = (float*)(sm + OFF_AHI);
        float* stg1 = (float*)(sm + OFF_OB0);
        int cr = lane >> 2, cc2 = (lane & 3) * 2;
#pragma unroll
        for (int mt = 0; mt < 2; mt++) {
            int r0 = wm * 32 + mt * 16 + cr;
#pragma unroll
            for (int nt = 0; nt < 8; nt++) {
                int cc = wn * 64 + nt * 8 + cc2;
                *(float2*)&stg0[r0 * STG_STRIDE + cc] =
                    make_float2(c0[mt][nt][0], c0[mt][nt][1]);
                *(float2*)&stg0[(r0 + 8) * STG_STRIDE + cc] =
                    make_float2(c0[mt][nt][2], c0[mt][nt][3]);
                *(float2*)&stg1[r0 * STG_STRIDE + cc] =
                    make_float2(c1[mt][nt][0], c1[mt][nt][1]);
                *(float2*)&stg1[(r0 + 8) * STG_STRIDE + cc] =
                    make_float2(c1[mt][nt][2], c1[mt][nt][3]);
            }
        }
        __syncthreads();
#pragma unroll
        for (int t = 0; t < 16; t++) {
            int j  = tid + t * 256;
            int r  = j >> 5;
            int c4 = (j & 31) * 4;
            *(float4*)&out[(rowbase + r) * DTOK + colbase + c4] =
                *(float4*)&stg0[r * STG_STRIDE + c4];
            *(float4*)&out[(rowbase + r) * DTOK + colbase + 128 + c4] =
                *(float4*)&stg1[r * STG_STRIDE + c4];
        }
    }
}

// ==================================================================
// Launch.
// ==================================================================
extern "C" void kernel_launch(void* const* d_in, const int* in_sizes, int n_in,
                              void* d_out, int out_size) {
    const float* s      = (const float*)d_in[0];
    const float* a      = (const float*)d_in[1];
    const int*   starts = (const int*)  d_in[2];
    const int*   counts = (const int*)  d_in[3];
    const float* tmask  = (const float*)d_in[4];
    const float* wq     = (const float*)d_in[5];
    const float* wk     = (const float*)d_in[6];
    const float* wv     = (const float*)d_in[7];
    const float* wg     = (const float*)d_in[8];
    const float* wo     = (const float*)d_in[9];
    const float* lnqg   = (const float*)d_in[10];
    const float* lnqb   = (const float*)d_in[11];
    const float* lnkg   = (const float*)d_in[12];
    const float* lnkb   = (const float*)d_in[13];
    float* out = (float*)d_out;

    cudaFuncSetAttribute(kv_mma_kernel,
                         cudaFuncAttributeMaxDynamicSharedMemorySize, KV_SMEM);
    cudaFuncSetAttribute(qg_mma_kernel,
                         cudaFuncAttributeMaxDynamicSharedMemorySize, QG_SMEM);
    cudaFuncSetAttribute(out_mma_kernel,
                         cudaFuncAttributeMaxDynamicSharedMemorySize, OUT_SMEM);

    wprep_kernel<<<256, 256>>>(wq, wk, wv, wg, wo);
    stats_s_kernel<<<NTOK / 8, 256>>>(s);
    kv_mma_kernel<<<NATOM / 128, 256, KV_SMEM>>>(a, lnkg, lnkb);
    qg_mma_kernel<<<NTOK / 128, 256, QG_SMEM>>>(s, lnqg, lnqb);
    attn_gate_kernel<<<NTOK / 8, 256>>>(starts, counts, tmask);
    out_mma_kernel<<<dim3(NTOK / 128, 2), 256, OUT_SMEM>>>(out);
}

// round 12
// speedup vs baseline: 3.2691x; 1.1708x over previous
#include <cuda_runtime.h>
#include <cuda_fp16.h>
#include <cstdint>
#include <math.h>

// Problem constants
#define BB     4
#define NN     4096
#define MM     32768
#define DTOK   512
#define DATOM  128
#define NHEAD  4
#define DH     32
#define WMAX   16
#define LNEPS  1e-5f

#define NTOK   (BB * NN)    // 16384 token rows
#define NATOM  (BB * MM)    // 131072 atom rows

// Single dynamic smem symbol shared by all kernels (cast locally).
extern __shared__ char dyn_smem[];

// -------- scratch (device globals; no allocations allowed) --------
__device__ __half g_K[(size_t)NATOM * DATOM];
__device__ __half g_V[(size_t)NATOM * DATOM];
__device__ float g_Q[(size_t)NTOK * DATOM];
__device__ float g_G[(size_t)NTOK * DATOM];
__device__ __half g_U[(size_t)NTOK * DATOM];
__device__ float g_smu[NTOK];
__device__ float g_srs[NTOK];
// fp16 weights (converted once per launch by wprep_kernel)
__device__ __half g_hwk[DATOM * DATOM];
__device__ __half g_hwv[DATOM * DATOM];
__device__ __half g_hwq[DTOK * DATOM];
__device__ __half g_hwg[DTOK * DATOM];
__device__ __half g_hwo[DATOM * DTOK];

__device__ __forceinline__ float warp_sum(float v) {
#pragma unroll
    for (int o = 16; o > 0; o >>= 1) v += __shfl_xor_sync(0xffffffffu, v, o);
    return v;
}
__device__ __forceinline__ uint32_t smem_u32(const void* p) {
    uint32_t a;
    asm("{ .reg .u64 t; cvta.to.shared.u64 t, %1; cvt.u32.u64 %0, t; }"
        : "=r"(a) : "l"(p));
    return a;
}
__device__ __forceinline__ uint32_t pack_h2(float a, float b) {
    __half2 t = __floats2half2_rn(a, b);
    return *(uint32_t*)&t;
}

// ---- cp.async helpers (sm_80+) ----
#define CP_ASYNC16(dst, src) \
    asm volatile("cp.async.cg.shared.global [%0], [%1], 16;" \
                 :: "r"((uint32_t)(dst)), "l"(src))
#define CP_COMMIT() asm volatile("cp.async.commit_group;" ::: "memory")
#define CP_WAIT0()  asm volatile("cp.async.wait_group 0;" ::: "memory")

// ---- warp-level MMA helpers ----
__device__ __forceinline__ void ldm4(uint32_t* d, uint32_t addr) {
    asm volatile("ldmatrix.sync.aligned.m8n8.x4.shared.b16 {%0,%1,%2,%3}, [%4];"
                 : "=r"(d[0]), "=r"(d[1]), "=r"(d[2]), "=r"(d[3]) : "r"(addr));
}
__device__ __forceinline__ void ldm4t(uint32_t* d, uint32_t addr) {
    asm volatile("ldmatrix.sync.aligned.m8n8.x4.trans.shared.b16 {%0,%1,%2,%3}, [%4];"
                 : "=r"(d[0]), "=r"(d[1]), "=r"(d[2]), "=r"(d[3]) : "r"(addr));
}
__device__ __forceinline__ void mma16816(float* c, const uint32_t* a,
                                         uint32_t b0, uint32_t b1) {
    asm volatile(
        "mma.sync.aligned.m16n8k16.row.col.f32.f16.f16.f32 "
        "{%0,%1,%2,%3}, {%4,%5,%6,%7}, {%8,%9}, {%0,%1,%2,%3};"
        : "+f"(c[0]), "+f"(c[1]), "+f"(c[2]), "+f"(c[3])
        : "r"(a[0]), "r"(a[1]), "r"(a[2]), "r"(a[3]), "r"(b0), "r"(b1));
}

// Shared tile geometry (128x128 fp16 tiles, padded)
#define KV_STRIDE_B 272                   // bytes per smem row (136 halves)
#define KV_TILE_B   (128 * KV_STRIDE_B)   // 34816 bytes
#define STG_STRIDE  136                   // floats per staged row
#define STG_STRIDE_H 136                  // halves per fp16 staged row

// All GEMM kernels: smem = A tile + B tile = 2 tiles
#define OFF_A    0
#define OFF_B    KV_TILE_B
#define GEMM_SMEM (2 * KV_TILE_B)   // 69632 bytes

// ==================================================================
// Kernel 0: convert all weights to fp16 once.
// ==================================================================
__global__ void wprep_kernel(const float* __restrict__ wq,
                             const float* __restrict__ wk,
                             const float* __restrict__ wv,
                             const float* __restrict__ wg,
                             const float* __restrict__ wo) {
    int i = blockIdx.x * 256 + threadIdx.x;   // 0..65535
    if (i < DATOM * DATOM) {
        g_hwk[i] = __float2half_rn(wk[i]);
        g_hwv[i] = __float2half_rn(wv[i]);
    }
    g_hwq[i] = __float2half_rn(wq[i]);
    g_hwg[i] = __float2half_rn(wg[i]);
    g_hwo[i] = __float2half_rn(wo[i]);
}

// ==================================================================
// Kernel 1: per-row LN stats for s (rows of 512). One warp per row.
// ==================================================================
__global__ void stats_s_kernel(const float* __restrict__ s) {
    int row  = blockIdx.x * 8 + (threadIdx.x >> 5);
    int lane = threadIdx.x & 31;
    const float4* p = (const float4*)(s + (size_t)row * DTOK);
    float sum = 0.f, sq = 0.f;
#pragma unroll
    for (int j = 0; j < 4; j++) {
        float4 v = p[lane + 32 * j];
        sum += v.x + v.y + v.z + v.w;
        sq  += v.x * v.x + v.y * v.y + v.z * v.z + v.w * v.w;
    }
    sum = warp_sum(sum);
    sq  = warp_sum(sq);
    if (lane == 0) {
        float mu  = sum * (1.f / DTOK);
        float var = sq * (1.f / DTOK) - mu * mu;
        g_smu[row] = mu;
        g_srs[row] = rsqrtf(var + LNEPS);
    }
}

// ==================================================================
// Kernel 2: LN(a) + one of {K,V} per block (blockIdx.y selects).
// Single-pass fp16, 64 acc regs, 2 blocks/SM.
// ==================================================================
__global__ void __launch_bounds__(256, 2)
kv_mma_kernel(const float* __restrict__ a, const float* __restrict__ lng,
              const float* __restrict__ lnb) {
    char* sm = dyn_smem;
    uint32_t sbase = smem_u32(sm);
    int tid = threadIdx.x;
    int warp = tid >> 5, lane = tid & 31;
    size_t rowbase = (size_t)blockIdx.x * 128;
    const __half* w = blockIdx.y ? g_hwv : g_hwk;
    __half* dst     = blockIdx.y ? g_V : g_K;

    // ---- B (weight) tile via cp.async, overlapped with A compute ----
#pragma unroll
    for (int t = 0; t < 8; t++) {
        int j   = tid + t * 256;
        int row = j >> 4;
        int c8  = (j & 15) * 8;
        CP_ASYNC16(sbase + OFF_B + (uint32_t)row * KV_STRIDE_B + c8 * 2,
                   w + row * DATOM + c8);
    }
    CP_COMMIT();

    // ---- A tile: LN rows -> single fp16 ----
    float4 gln = ((const float4*)lng)[lane];
    float4 bln = ((const float4*)lnb)[lane];
    for (int r = warp; r < 128; r += 8) {
        float4 v = *(const float4*)(a + (rowbase + r) * DATOM + lane * 4);
        float sum = warp_sum(v.x + v.y + v.z + v.w);
        float sq  = warp_sum(v.x * v.x + v.y * v.y + v.z * v.z + v.w * v.w);
        float mu  = sum * (1.f / 128.f);
        float rs  = rsqrtf(sq * (1.f / 128.f) - mu * mu + LNEPS);
        float n0 = (v.x - mu) * rs * gln.x + bln.x;
        float n1 = (v.y - mu) * rs * gln.y + bln.y;
        float n2 = (v.z - mu) * rs * gln.z + bln.z;
        float n3 = (v.w - mu) * rs * gln.w + bln.w;
        uint32_t off = (uint32_t)r * KV_STRIDE_B + lane * 8;
        *(uint32_t*)(sm + OFF_A + off)     = pack_h2(n0, n1);
        *(uint32_t*)(sm + OFF_A + off + 4) = pack_h2(n2, n3);
    }
    CP_WAIT0();
    __syncthreads();

    int wm = warp & 3;
    int wn = warp >> 2;
    int lr = lane & 15;
    int lc = lane >> 4;
    uint32_t aAddr = sbase + OFF_A + (uint32_t)(wm * 32 + lr) * KV_STRIDE_B + lc * 16;
    uint32_t bAddr = sbase + OFF_B + (uint32_t)lr * KV_STRIDE_B + (wn * 64 + lc * 8) * 2;

    float c[2][8][4];
#pragma unroll
    for (int mt = 0; mt < 2; mt++)
#pragma unroll
        for (int nt = 0; nt < 8; nt++)
#pragma unroll
            for (int e = 0; e < 4; e++) c[mt][nt][e] = 0.f;

#pragma unroll
    for (int ks = 0; ks < 8; ks++) {
        uint32_t ak = aAddr + ks * 32;
        uint32_t bk = bAddr + ks * 16 * KV_STRIDE_B;
        uint32_t aF[2][4];
        ldm4(aF[0], ak);
        ldm4(aF[1], ak + 16 * KV_STRIDE_B);
        uint32_t b[4][4];
#pragma unroll
        for (int i = 0; i < 4; i++) ldm4t(b[i], bk + i * 32);
#pragma unroll
        for (int mt = 0; mt < 2; mt++)
#pragma unroll
            for (int i = 0; i < 4; i++) {
                mma16816(c[mt][2 * i],     aF[mt], b[i][0], b[i][1]);
                mma16816(c[mt][2 * i + 1], aF[mt], b[i][2], b[i][3]);
            }
    }
    __syncthreads();
    // ---- epilogue: fp16 stage into A region, coalesced write ----
    {
        __half* stg = (__half*)(sm + OFF_A);
        int cr = lane >> 2, cc2 = (lane & 3) * 2;
#pragma unroll
        for (int mt = 0; mt < 2; mt++) {
            int r0 = wm * 32 + mt * 16 + cr;
#pragma unroll
            for (int nt = 0; nt < 8; nt++) {
                int cc = wn * 64 + nt * 8 + cc2;
                *(__half2*)&stg[r0 * STG_STRIDE_H + cc] =
                    __floats2half2_rn(c[mt][nt][0], c[mt][nt][1]);
                *(__half2*)&stg[(r0 + 8) * STG_STRIDE_H + cc] =
                    __floats2half2_rn(c[mt][nt][2], c[mt][nt][3]);
            }
        }
        __syncthreads();
#pragma unroll
        for (int t = 0; t < 8; t++) {
            int j  = tid + t * 256;
            int r  = j >> 4;
            int c8 = (j & 15) * 8;
            *(uint4*)&dst[(rowbase + r) * DATOM + c8] =
                *(uint4*)&stg[r * STG_STRIDE_H + c8];
        }
    }
}

// ==================================================================
// Kernel 3: LN(s) + one of {Q,G} per block (blockIdx.y selects).
// Single-pass fp16, 64 acc regs, 2 blocks/SM. K = 512 in 4 chunks.
// ==================================================================
__global__ void __launch_bounds__(256, 2)
qg_mma_kernel(const float* __restrict__ s, const float* __restrict__ lng,
              const float* __restrict__ lnb) {
    char* sm = dyn_smem;
    uint32_t sbase = smem_u32(sm);
    int tid = threadIdx.x;
    int warp = tid >> 5, lane = tid & 31;
    size_t rowbase = (size_t)blockIdx.x * 128;
    const __half* w = blockIdx.y ? g_hwg : g_hwq;
    float* dst      = blockIdx.y ? g_G : g_Q;

    int wm = warp & 3;
    int wn = warp >> 2;
    int lr = lane & 15;
    int lc = lane >> 4;
    uint32_t aAddr = sbase + OFF_A + (uint32_t)(wm * 32 + lr) * KV_STRIDE_B + lc * 16;
    uint32_t bAddr = sbase + OFF_B + (uint32_t)lr * KV_STRIDE_B + (wn * 64 + lc * 8) * 2;

    float c[2][8][4];
#pragma unroll
    for (int mt = 0; mt < 2; mt++)
#pragma unroll
        for (int nt = 0; nt < 8; nt++)
#pragma unroll
            for (int e = 0; e < 4; e++) c[mt][nt][e] = 0.f;

#pragma unroll 1
    for (int kc = 0; kc < 4; kc++) {
        int k0 = kc * 128;
        // ---- B chunk via cp.async (overlaps A compute) ----
#pragma unroll
        for (int t = 0; t < 8; t++) {
            int j   = tid + t * 256;
            int row = j >> 4;
            int c8  = (j & 15) * 8;
            CP_ASYNC16(sbase + OFF_B + (uint32_t)row * KV_STRIDE_B + c8 * 2,
                       w + (size_t)(k0 + row) * DATOM + c8);
        }
        CP_COMMIT();
        // ---- A tile: LN(s) chunk -> single fp16 ----
#pragma unroll
        for (int t = 0; t < 16; t++) {
            int j   = tid + t * 256;
            int row = j >> 5;
            int c4  = (j & 31) * 4;
            float4 v = *(const float4*)(s + (rowbase + row) * DTOK + k0 + c4);
            float mu = g_smu[rowbase + row];
            float rs = g_srs[rowbase + row];
            float4 gv = *(const float4*)(lng + k0 + c4);
            float4 bv = *(const float4*)(lnb + k0 + c4);
            float n0 = (v.x - mu) * rs * gv.x + bv.x;
            float n1 = (v.y - mu) * rs * gv.y + bv.y;
            float n2 = (v.z - mu) * rs * gv.z + bv.z;
            float n3 = (v.w - mu) * rs * gv.w + bv.w;
            uint32_t off = (uint32_t)row * KV_STRIDE_B + c4 * 2;
            *(uint32_t*)(sm + OFF_A + off)     = pack_h2(n0, n1);
            *(uint32_t*)(sm + OFF_A + off + 4) = pack_h2(n2, n3);
        }
        CP_WAIT0();
        __syncthreads();
#pragma unroll
        for (int ks = 0; ks < 8; ks++) {
            uint32_t ak = aAddr + ks * 32;
            uint32_t bk = bAddr + ks * 16 * KV_STRIDE_B;
            uint32_t aF[2][4];
            ldm4(aF[0], ak);
            ldm4(aF[1], ak + 16 * KV_STRIDE_B);
            uint32_t b[4][4];
#pragma unroll
            for (int i = 0; i < 4; i++) ldm4t(b[i], bk + i * 32);
#pragma unroll
            for (int mt = 0; mt < 2; mt++)
#pragma unroll
                for (int i = 0; i < 4; i++) {
                    mma16816(c[mt][2 * i],     aF[mt], b[i][0], b[i][1]);
                    mma16816(c[mt][2 * i + 1], aF[mt], b[i][2], b[i][3]);
                }
        }
        __syncthreads();
    }
    // ---- epilogue: fp32 stage across full smem (A+B = 69632 B) ----
    {
        float* stg = (float*)sm;
        int cr = lane >> 2, cc2 = (lane & 3) * 2;
#pragma unroll
        for (int mt = 0; mt < 2; mt++) {
            int r0 = wm * 32 + mt * 16 + cr;
#pragma unroll
            for (int nt = 0; nt < 8; nt++) {
                int cc = wn * 64 + nt * 8 + cc2;
                *(float2*)&stg[r0 * STG_STRIDE + cc] =
                    make_float2(c[mt][nt][0], c[mt][nt][1]);
                *(float2*)&stg[(r0 + 8) * STG_STRIDE + cc] =
                    make_float2(c[mt][nt][2], c[mt][nt][3]);
            }
        }
        __syncthreads();
#pragma unroll
        for (int t = 0; t < 16; t++) {
            int j  = tid + t * 256;
            int r  = j >> 5;
            int c4 = (j & 31) * 4;
            *(float4*)&dst[(rowbase + r) * DATOM + c4] =
                *(float4*)&stg[r * STG_STRIDE + c4];
        }
    }
}

// ==================================================================
// Kernel 4: ragged window attention + gate. WARP PER TOKEN.
// K/V fp16, U written single fp16.
// ==================================================================
__global__ void __launch_bounds__(256, 8)
attn_gate_kernel(const int* __restrict__ starts, const int* __restrict__ counts,
                 const float* __restrict__ tmask) {
    int warp = threadIdx.x >> 5, lane = threadIdx.x & 31;
    int bt = blockIdx.x * 8 + warp;      // token index
    int b  = bt >> 12;                   // batch (N = 4096)
    int start = starts[bt];
    int count = counts[bt];
    const float scale = 0.17677669529663687f;   // 1/sqrt(32)

    float4 q = *(const float4*)(g_Q + (size_t)bt * DATOM + lane * 4);
    const __half* kb = g_K + ((size_t)b * MM + start) * DATOM;

    float sc[WMAX];
#pragma unroll
    for (int w = 0; w < WMAX; w++) {
        float d = -1e30f;
        if (w < count) {
            uint2 raw = *(const uint2*)(kb + (size_t)w * DATOM + lane * 4);
            float2 f01 = __half22float2(*(__half2*)&raw.x);
            float2 f23 = __half22float2(*(__half2*)&raw.y);
            float t = q.x * f01.x + q.y * f01.y + q.z * f23.x + q.w * f23.y;
            t += __shfl_xor_sync(0xffffffffu, t, 1);
            t += __shfl_xor_sync(0xffffffffu, t, 2);
            t += __shfl_xor_sync(0xffffffffu, t, 4);
            d = t * scale;
        }
        sc[w] = d;
    }
    float m = -1e30f;
#pragma unroll
    for (int w = 0; w < WMAX; w++) m = fmaxf(m, sc[w]);
    float sum = 0.f;
#pragma unroll
    for (int w = 0; w < WMAX; w++) { sc[w] = expf(sc[w] - m); sum += sc[w]; }
    float inv = 1.f / sum;

    const __half* vb = g_V + ((size_t)b * MM + start) * DATOM;
    float4 acc = make_float4(0.f, 0.f, 0.f, 0.f);
#pragma unroll
    for (int w = 0; w < WMAX; w++) {
        if (w < count) {
            float p = sc[w] * inv;
            uint2 raw = *(const uint2*)(vb + (size_t)w * DATOM + lane * 4);
            float2 f01 = __half22float2(*(__half2*)&raw.x);
            float2 f23 = __half22float2(*(__half2*)&raw.y);
            acc.x = fmaf(p, f01.x, acc.x);
            acc.y = fmaf(p, f01.y, acc.y);
            acc.z = fmaf(p, f23.x, acc.z);
            acc.w = fmaf(p, f23.y, acc.w);
        }
    }
    float msk = tmask[bt];
    float4 g = *(const float4*)(g_G + (size_t)bt * DATOM + lane * 4);
    float ux = acc.x * msk / (1.f + expf(-g.x));
    float uy = acc.y * msk / (1.f + expf(-g.y));
    float uz = acc.z * msk / (1.f + expf(-g.z));
    float uw = acc.w * msk / (1.f + expf(-g.w));
    uint2 hv = make_uint2(pack_h2(ux, uy), pack_h2(uz, uw));
    *(uint2*)(g_U + (size_t)bt * DATOM + lane * 4) = hv;
}

// ==================================================================
// Kernel 5: out = U @ w_o. One 128-col quarter per block (y = 0..3).
// Single-pass fp16 U, all loads cp.async, 2 blocks/SM.
// ==================================================================
__global__ void __launch_bounds__(256, 2)
out_mma_kernel(float* __restrict__ out) {
    char* sm = dyn_smem;
    uint32_t sbase = smem_u32(sm);
    int tid = threadIdx.x;
    int warp = tid >> 5, lane = tid & 31;
    size_t rowbase = (size_t)blockIdx.x * 128;
    int colbase = blockIdx.y * 128;

#pragma unroll
    for (int t = 0; t < 8; t++) {
        int j   = tid + t * 256;
        int row = j >> 4;
        int c8  = (j & 15) * 8;
        uint32_t off = (uint32_t)row * KV_STRIDE_B + c8 * 2;
        CP_ASYNC16(sbase + OFF_A + off, g_U + (rowbase + row) * DATOM + c8);
        CP_ASYNC16(sbase + OFF_B + off,
                   g_hwo + (size_t)row * DTOK + colbase + c8);
    }
    CP_COMMIT();
    CP_WAIT0();
    __syncthreads();

    int wm = warp & 3;
    int wn = warp >> 2;
    int lr = lane & 15;
    int lc = lane >> 4;
    uint32_t aAddr = sbase + OFF_A + (uint32_t)(wm * 32 + lr) * KV_STRIDE_B + lc * 16;
    uint32_t bAddr = sbase + OFF_B + (uint32_t)lr * KV_STRIDE_B + (wn * 64 + lc * 8) * 2;

    float c[2][8][4];
#pragma unroll
    for (int mt = 0; mt < 2; mt++)
#pragma unroll
        for (int nt = 0; nt < 8; nt++)
#pragma unroll
            for (int e = 0; e < 4; e++) c[mt][nt][e] = 0.f;

#pragma unroll
    for (int ks = 0; ks < 8; ks++) {
        uint32_t ak = aAddr + ks * 32;
        uint32_t bk = bAddr + ks * 16 * KV_STRIDE_B;
        uint32_t aF[2][4];
        ldm4(aF[0], ak);
        ldm4(aF[1], ak + 16 * KV_STRIDE_B);
        uint32_t b[4][4];
#pragma unroll
        for (int i = 0; i < 4; i++) ldm4t(b[i], bk + i * 32);
#pragma unroll
        for (int mt = 0; mt < 2; mt++)
#pragma unroll
            for (int i = 0; i < 4; i++) {
                mma16816(c[mt][2 * i],     aF[mt], b[i][0], b[i][1]);
                mma16816(c[mt][2 * i + 1], aF[mt], b[i][2], b[i][3]);
            }
    }
    __syncthreads();
    {
        float* stg = (float*)sm;   // full 69632 B
        int cr = lane >> 2, cc2 = (lane & 3) * 2;
#pragma unroll
        for (int mt = 0; mt < 2; mt++) {
            int r0 = wm * 32 + mt * 16 + cr;
#pragma unroll
            for (int nt = 0; nt < 8; nt++) {
                int cc = wn * 64 + nt * 8 + cc2;
                *(float2*)&stg[r0 * STG_STRIDE + cc] =
                    make_float2(c[mt][nt][0], c[mt][nt][1]);
                *(float2*)&stg[(r0 + 8) * STG_STRIDE + cc] =
                    make_float2(c[mt][nt][2], c[mt][nt][3]);
            }
        }
        __syncthreads();
#pragma unroll
        for (int t = 0; t < 16; t++) {
            int j  = tid + t * 256;
            int r  = j >> 5;
            int c4 = (j & 31) * 4;
            *(float4*)&out[(rowbase + r) * DTOK + colbase + c4] =
                *(float4*)&stg[r * STG_STRIDE + c4];
        }
    }
}

// ==================================================================
// Launch.
// ==================================================================
extern "C" void kernel_launch(void* const* d_in, const int* in_sizes, int n_in,
                              void* d_out, int out_size) {
    const float* s      = (const float*)d_in[0];
    const float* a      = (const float*)d_in[1];
    const int*   starts = (const int*)  d_in[2];
    const int*   counts = (const int*)  d_in[3];
    const float* tmask  = (const float*)d_in[4];
    const float* wq     = (const float*)d_in[5];
    const float* wk     = (const float*)d_in[6];
    const float* wv     = (const float*)d_in[7];
    const float* wg     = (const float*)d_in[8];
    const float* wo     = (const float*)d_in[9];
    const float* lnqg   = (const float*)d_in[10];
    const float* lnqb   = (const float*)d_in[11];
    const float* lnkg   = (const float*)d_in[12];
    const float* lnkb   = (const float*)d_in[13];
    float* out = (float*)d_out;

    cudaFuncSetAttribute(kv_mma_kernel,
                         cudaFuncAttributeMaxDynamicSharedMemorySize, GEMM_SMEM);
    cudaFuncSetAttribute(qg_mma_kernel,
                         cudaFuncAttributeMaxDynamicSharedMemorySize, GEMM_SMEM);
    cudaFuncSetAttribute(out_mma_kernel,
                         cudaFuncAttributeMaxDynamicSharedMemorySize, GEMM_SMEM);

    wprep_kernel<<<256, 256>>>(wq, wk, wv, wg, wo);
    stats_s_kernel<<<NTOK / 8, 256>>>(s);
    kv_mma_kernel<<<dim3(NATOM / 128, 2), 256, GEMM_SMEM>>>(a, lnkg, lnkb);
    qg_mma_kernel<<<dim3(NTOK / 128, 2), 256, GEMM_SMEM>>>(s, lnqg, lnqb);
    attn_gate_kernel<<<NTOK / 8, 256>>>(starts, counts, tmask);
    out_mma_kernel<<<dim3(NTOK / 128, 4), 256, GEMM_SMEM>>>(out);
}

// round 13
// speedup vs baseline: 4.5418x; 1.3893x over previous
#include <cuda_runtime.h>
#include <cuda_fp16.h>
#include <cstdint>
#include <math.h>

// Problem constants
#define BB     4
#define NN     4096
#define MM     32768
#define DTOK   512
#define DATOM  128
#define NHEAD  4
#define DH     32
#define WMAX   16
#define LNEPS  1e-5f

#define NTOK   (BB * NN)    // 16384 token rows
#define NATOM  (BB * MM)    // 131072 atom rows

// Single dynamic smem symbol shared by all kernels (cast locally).
extern __shared__ char dyn_smem[];

// -------- scratch (device globals; no allocations allowed) --------
__device__ __half g_K[(size_t)NATOM * DATOM];
__device__ __half g_V[(size_t)NATOM * DATOM];
__device__ float g_Q[(size_t)NTOK * DATOM];
__device__ float g_G[(size_t)NTOK * DATOM];
__device__ __half g_U[(size_t)NTOK * DATOM];
__device__ __half g_sn[(size_t)NTOK * DTOK];     // LN(s) fp16
__device__ __half g_an[(size_t)NATOM * DATOM];   // LN(a) fp16
// fp16 weights (converted once per launch by wprep_kernel)
__device__ __half g_hwk[DATOM * DATOM];
__device__ __half g_hwv[DATOM * DATOM];
__device__ __half g_hwq[DTOK * DATOM];
__device__ __half g_hwg[DTOK * DATOM];
__device__ __half g_hwo[DATOM * DTOK];

__device__ __forceinline__ float warp_sum(float v) {
#pragma unroll
    for (int o = 16; o > 0; o >>= 1) v += __shfl_xor_sync(0xffffffffu, v, o);
    return v;
}
__device__ __forceinline__ uint32_t smem_u32(const void* p) {
    uint32_t a;
    asm("{ .reg .u64 t; cvta.to.shared.u64 t, %1; cvt.u32.u64 %0, t; }"
        : "=r"(a) : "l"(p));
    return a;
}
__device__ __forceinline__ uint32_t pack_h2(float a, float b) {
    __half2 t = __floats2half2_rn(a, b);
    return *(uint32_t*)&t;
}

// ---- cp.async helpers (sm_80+) ----
#define CP_ASYNC16(dst, src) \
    asm volatile("cp.async.cg.shared.global [%0], [%1], 16;" \
                 :: "r"((uint32_t)(dst)), "l"(src))
#define CP_COMMIT() asm volatile("cp.async.commit_group;" ::: "memory")
#define CP_WAIT0()  asm volatile("cp.async.wait_group 0;" ::: "memory")

// ---- warp-level MMA helpers ----
__device__ __forceinline__ void ldm4(uint32_t* d, uint32_t addr) {
    asm volatile("ldmatrix.sync.aligned.m8n8.x4.shared.b16 {%0,%1,%2,%3}, [%4];"
                 : "=r"(d[0]), "=r"(d[1]), "=r"(d[2]), "=r"(d[3]) : "r"(addr));
}
__device__ __forceinline__ void ldm4t(uint32_t* d, uint32_t addr) {
    asm volatile("ldmatrix.sync.aligned.m8n8.x4.trans.shared.b16 {%0,%1,%2,%3}, [%4];"
                 : "=r"(d[0]), "=r"(d[1]), "=r"(d[2]), "=r"(d[3]) : "r"(addr));
}
__device__ __forceinline__ void mma16816(float* c, const uint32_t* a,
                                         uint32_t b0, uint32_t b1) {
    asm volatile(
        "mma.sync.aligned.m16n8k16.row.col.f32.f16.f16.f32 "
        "{%0,%1,%2,%3}, {%4,%5,%6,%7}, {%8,%9}, {%0,%1,%2,%3};"
        : "+f"(c[0]), "+f"(c[1]), "+f"(c[2]), "+f"(c[3])
        : "r"(a[0]), "r"(a[1]), "r"(a[2]), "r"(a[3]), "r"(b0), "r"(b1));
}

// Shared tile geometry (128x128 fp16 tiles, padded)
#define KV_STRIDE_B 272                   // bytes per smem row (136 halves)
#define KV_TILE_B   (128 * KV_STRIDE_B)   // 34816 bytes
#define STG_STRIDE  136                   // floats per staged row
#define STG_STRIDE_H 136                  // halves per fp16 staged row

#define OFF_A    0
#define OFF_B    KV_TILE_B
#define GEMM_SMEM (2 * KV_TILE_B)   // 69632 bytes

// ==================================================================
// Kernel 0: convert all weights to fp16 once.
// ==================================================================
__global__ void wprep_kernel(const float* __restrict__ wq,
                             const float* __restrict__ wk,
                             const float* __restrict__ wv,
                             const float* __restrict__ wg,
                             const float* __restrict__ wo) {
    int i = blockIdx.x * 256 + threadIdx.x;   // 0..65535
    if (i < DATOM * DATOM) {
        g_hwk[i] = __float2half_rn(wk[i]);
        g_hwv[i] = __float2half_rn(wv[i]);
    }
    g_hwq[i] = __float2half_rn(wq[i]);
    g_hwg[i] = __float2half_rn(wg[i]);
    g_hwo[i] = __float2half_rn(wo[i]);
}

// ==================================================================
// Kernel 1: LN(s) -> g_sn fp16. One warp per row of 512.
// ==================================================================
__global__ void s_prep_kernel(const float* __restrict__ s,
                              const float* __restrict__ lng,
                              const float* __restrict__ lnb) {
    int row  = blockIdx.x * 8 + (threadIdx.x >> 5);
    int lane = threadIdx.x & 31;
    const float4* p = (const float4*)(s + (size_t)row * DTOK);
    float4 v[4];
    float sum = 0.f, sq = 0.f;
#pragma unroll
    for (int j = 0; j < 4; j++) {
        v[j] = p[lane + 32 * j];
        sum += v[j].x + v[j].y + v[j].z + v[j].w;
        sq  += v[j].x * v[j].x + v[j].y * v[j].y + v[j].z * v[j].z + v[j].w * v[j].w;
    }
    sum = warp_sum(sum);
    sq  = warp_sum(sq);
    float mu = sum * (1.f / DTOK);
    float rs = rsqrtf(sq * (1.f / DTOK) - mu * mu + LNEPS);
    __half* dst = g_sn + (size_t)row * DTOK;
#pragma unroll
    for (int j = 0; j < 4; j++) {
        int c = (lane + 32 * j) * 4;
        float4 gv = *(const float4*)(lng + c);
        float4 bv = *(const float4*)(lnb + c);
        float n0 = (v[j].x - mu) * rs * gv.x + bv.x;
        float n1 = (v[j].y - mu) * rs * gv.y + bv.y;
        float n2 = (v[j].z - mu) * rs * gv.z + bv.z;
        float n3 = (v[j].w - mu) * rs * gv.w + bv.w;
        *(uint2*)(dst + c) = make_uint2(pack_h2(n0, n1), pack_h2(n2, n3));
    }
}

// ==================================================================
// Kernel 2: LN(a) -> g_an fp16. One warp per row of 128.
// ==================================================================
__global__ void a_prep_kernel(const float* __restrict__ a,
                              const float* __restrict__ lng,
                              const float* __restrict__ lnb) {
    int row  = blockIdx.x * 8 + (threadIdx.x >> 5);
    int lane = threadIdx.x & 31;
    float4 v = *(const float4*)(a + (size_t)row * DATOM + lane * 4);
    float sum = warp_sum(v.x + v.y + v.z + v.w);
    float sq  = warp_sum(v.x * v.x + v.y * v.y + v.z * v.z + v.w * v.w);
    float mu  = sum * (1.f / 128.f);
    float rs  = rsqrtf(sq * (1.f / 128.f) - mu * mu + LNEPS);
    float4 gv = ((const float4*)lng)[lane];
    float4 bv = ((const float4*)lnb)[lane];
    float n0 = (v.x - mu) * rs * gv.x + bv.x;
    float n1 = (v.y - mu) * rs * gv.y + bv.y;
    float n2 = (v.z - mu) * rs * gv.z + bv.z;
    float n3 = (v.w - mu) * rs * gv.w + bv.w;
    *(uint2*)(g_an + (size_t)row * DATOM + lane * 4) =
        make_uint2(pack_h2(n0, n1), pack_h2(n2, n3));
}

// ==================================================================
// Kernel 3: one of {K,V} per block (blockIdx.y). Pure async copies.
// ==================================================================
__global__ void __launch_bounds__(256, 2)
kv_mma_kernel() {
    char* sm = dyn_smem;
    uint32_t sbase = smem_u32(sm);
    int tid = threadIdx.x;
    int warp = tid >> 5, lane = tid & 31;
    size_t rowbase = (size_t)blockIdx.x * 128;
    const __half* w = blockIdx.y ? g_hwv : g_hwk;
    __half* dst     = blockIdx.y ? g_V : g_K;

#pragma unroll
    for (int t = 0; t < 8; t++) {
        int j   = tid + t * 256;
        int row = j >> 4;
        int c8  = (j & 15) * 8;
        uint32_t off = (uint32_t)row * KV_STRIDE_B + c8 * 2;
        CP_ASYNC16(sbase + OFF_A + off, g_an + (rowbase + row) * DATOM + c8);
        CP_ASYNC16(sbase + OFF_B + off, w + row * DATOM + c8);
    }
    CP_COMMIT();
    CP_WAIT0();
    __syncthreads();

    int wm = warp & 3;
    int wn = warp >> 2;
    int lr = lane & 15;
    int lc = lane >> 4;
    uint32_t aAddr = sbase + OFF_A + (uint32_t)(wm * 32 + lr) * KV_STRIDE_B + lc * 16;
    uint32_t bAddr = sbase + OFF_B + (uint32_t)lr * KV_STRIDE_B + (wn * 64 + lc * 8) * 2;

    float c[2][8][4];
#pragma unroll
    for (int mt = 0; mt < 2; mt++)
#pragma unroll
        for (int nt = 0; nt < 8; nt++)
#pragma unroll
            for (int e = 0; e < 4; e++) c[mt][nt][e] = 0.f;

#pragma unroll
    for (int ks = 0; ks < 8; ks++) {
        uint32_t ak = aAddr + ks * 32;
        uint32_t bk = bAddr + ks * 16 * KV_STRIDE_B;
        uint32_t aF[2][4];
        ldm4(aF[0], ak);
        ldm4(aF[1], ak + 16 * KV_STRIDE_B);
        uint32_t b[4][4];
#pragma unroll
        for (int i = 0; i < 4; i++) ldm4t(b[i], bk + i * 32);
#pragma unroll
        for (int mt = 0; mt < 2; mt++)
#pragma unroll
            for (int i = 0; i < 4; i++) {
                mma16816(c[mt][2 * i],     aF[mt], b[i][0], b[i][1]);
                mma16816(c[mt][2 * i + 1], aF[mt], b[i][2], b[i][3]);
            }
    }
    __syncthreads();
    {
        __half* stg = (__half*)(sm + OFF_A);
        int cr = lane >> 2, cc2 = (lane & 3) * 2;
#pragma unroll
        for (int mt = 0; mt < 2; mt++) {
            int r0 = wm * 32 + mt * 16 + cr;
#pragma unroll
            for (int nt = 0; nt < 8; nt++) {
                int cc = wn * 64 + nt * 8 + cc2;
                *(__half2*)&stg[r0 * STG_STRIDE_H + cc] =
                    __floats2half2_rn(c[mt][nt][0], c[mt][nt][1]);
                *(__half2*)&stg[(r0 + 8) * STG_STRIDE_H + cc] =
                    __floats2half2_rn(c[mt][nt][2], c[mt][nt][3]);
            }
        }
        __syncthreads();
#pragma unroll
        for (int t = 0; t < 8; t++) {
            int j  = tid + t * 256;
            int r  = j >> 4;
            int c8 = (j & 15) * 8;
            *(uint4*)&dst[(rowbase + r) * DATOM + c8] =
                *(uint4*)&stg[r * STG_STRIDE_H + c8];
        }
    }
}

// ==================================================================
// Kernel 4: one of {Q,G} per block (blockIdx.y). K = 512 in 4 chunks.
// Pure async copies for A and B each chunk.
// ==================================================================
__global__ void __launch_bounds__(256, 2)
qg_mma_kernel() {
    char* sm = dyn_smem;
    uint32_t sbase = smem_u32(sm);
    int tid = threadIdx.x;
    int warp = tid >> 5, lane = tid & 31;
    size_t rowbase = (size_t)blockIdx.x * 128;
    const __half* w = blockIdx.y ? g_hwg : g_hwq;
    float* dst      = blockIdx.y ? g_G : g_Q;

    int wm = warp & 3;
    int wn = warp >> 2;
    int lr = lane & 15;
    int lc = lane >> 4;
    uint32_t aAddr = sbase + OFF_A + (uint32_t)(wm * 32 + lr) * KV_STRIDE_B + lc * 16;
    uint32_t bAddr = sbase + OFF_B + (uint32_t)lr * KV_STRIDE_B + (wn * 64 + lc * 8) * 2;

    float c[2][8][4];
#pragma unroll
    for (int mt = 0; mt < 2; mt++)
#pragma unroll
        for (int nt = 0; nt < 8; nt++)
#pragma unroll
            for (int e = 0; e < 4; e++) c[mt][nt][e] = 0.f;

#pragma unroll 1
    for (int kc = 0; kc < 4; kc++) {
        int k0 = kc * 128;
#pragma unroll
        for (int t = 0; t < 8; t++) {
            int j   = tid + t * 256;
            int row = j >> 4;
            int c8  = (j & 15) * 8;
            uint32_t off = (uint32_t)row * KV_STRIDE_B + c8 * 2;
            CP_ASYNC16(sbase + OFF_A + off,
                       g_sn + (rowbase + row) * DTOK + k0 + c8);
            CP_ASYNC16(sbase + OFF_B + off,
                       w + (size_t)(k0 + row) * DATOM + c8);
        }
        CP_COMMIT();
        CP_WAIT0();
        __syncthreads();
#pragma unroll
        for (int ks = 0; ks < 8; ks++) {
            uint32_t ak = aAddr + ks * 32;
            uint32_t bk = bAddr + ks * 16 * KV_STRIDE_B;
            uint32_t aF[2][4];
            ldm4(aF[0], ak);
            ldm4(aF[1], ak + 16 * KV_STRIDE_B);
            uint32_t b[4][4];
#pragma unroll
            for (int i = 0; i < 4; i++) ldm4t(b[i], bk + i * 32);
#pragma unroll
            for (int mt = 0; mt < 2; mt++)
#pragma unroll
                for (int i = 0; i < 4; i++) {
                    mma16816(c[mt][2 * i],     aF[mt], b[i][0], b[i][1]);
                    mma16816(c[mt][2 * i + 1], aF[mt], b[i][2], b[i][3]);
                }
        }
        __syncthreads();
    }
    {
        float* stg = (float*)sm;
        int cr = lane >> 2, cc2 = (lane & 3) * 2;
#pragma unroll
        for (int mt = 0; mt < 2; mt++) {
            int r0 = wm * 32 + mt * 16 + cr;
#pragma unroll
            for (int nt = 0; nt < 8; nt++) {
                int cc = wn * 64 + nt * 8 + cc2;
                *(float2*)&stg[r0 * STG_STRIDE + cc] =
                    make_float2(c[mt][nt][0], c[mt][nt][1]);
                *(float2*)&stg[(r0 + 8) * STG_STRIDE + cc] =
                    make_float2(c[mt][nt][2], c[mt][nt][3]);
            }
        }
        __syncthreads();
#pragma unroll
        for (int t = 0; t < 16; t++) {
            int j  = tid + t * 256;
            int r  = j >> 5;
            int c4 = (j & 31) * 4;
            *(float4*)&dst[(rowbase + r) * DATOM + c4] =
                *(float4*)&stg[r * STG_STRIDE + c4];
        }
    }
}

// ==================================================================
// Kernel 5: ragged window attention + gate. WARP PER TOKEN.
// ==================================================================
__global__ void __launch_bounds__(256, 8)
attn_gate_kernel(const int* __restrict__ starts, const int* __restrict__ counts,
                 const float* __restrict__ tmask) {
    int warp = threadIdx.x >> 5, lane = threadIdx.x & 31;
    int bt = blockIdx.x * 8 + warp;      // token index
    int b  = bt >> 12;                   // batch (N = 4096)
    int start = starts[bt];
    int count = counts[bt];
    const float scale = 0.17677669529663687f;   // 1/sqrt(32)

    float4 q = *(const float4*)(g_Q + (size_t)bt * DATOM + lane * 4);
    const __half* kb = g_K + ((size_t)b * MM + start) * DATOM;

    float sc[WMAX];
#pragma unroll
    for (int w = 0; w < WMAX; w++) {
        float d = -1e30f;
        if (w < count) {
            uint2 raw = *(const uint2*)(kb + (size_t)w * DATOM + lane * 4);
            float2 f01 = __half22float2(*(__half2*)&raw.x);
            float2 f23 = __half22float2(*(__half2*)&raw.y);
            float t = q.x * f01.x + q.y * f01.y + q.z * f23.x + q.w * f23.y;
            t += __shfl_xor_sync(0xffffffffu, t, 1);
            t += __shfl_xor_sync(0xffffffffu, t, 2);
            t += __shfl_xor_sync(0xffffffffu, t, 4);
            d = t * scale;
        }
        sc[w] = d;
    }
    float m = -1e30f;
#pragma unroll
    for (int w = 0; w < WMAX; w++) m = fmaxf(m, sc[w]);
    float sum = 0.f;
#pragma unroll
    for (int w = 0; w < WMAX; w++) { sc[w] = expf(sc[w] - m); sum += sc[w]; }
    float inv = 1.f / sum;

    const __half* vb = g_V + ((size_t)b * MM + start) * DATOM;
    float4 acc = make_float4(0.f, 0.f, 0.f, 0.f);
#pragma unroll
    for (int w = 0; w < WMAX; w++) {
        if (w < count) {
            float p = sc[w] * inv;
            uint2 raw = *(const uint2*)(vb + (size_t)w * DATOM + lane * 4);
            float2 f01 = __half22float2(*(__half2*)&raw.x);
            float2 f23 = __half22float2(*(__half2*)&raw.y);
            acc.x = fmaf(p, f01.x, acc.x);
            acc.y = fmaf(p, f01.y, acc.y);
            acc.z = fmaf(p, f23.x, acc.z);
            acc.w = fmaf(p, f23.y, acc.w);
        }
    }
    float msk = tmask[bt];
    float4 g = *(const float4*)(g_G + (size_t)bt * DATOM + lane * 4);
    float ux = acc.x * msk / (1.f + expf(-g.x));
    float uy = acc.y * msk / (1.f + expf(-g.y));
    float uz = acc.z * msk / (1.f + expf(-g.z));
    float uw = acc.w * msk / (1.f + expf(-g.w));
    uint2 hv = make_uint2(pack_h2(ux, uy), pack_h2(uz, uw));
    *(uint2*)(g_U + (size_t)bt * DATOM + lane * 4) = hv;
}

// ==================================================================
// Kernel 6: out = U @ w_o. One 128-col quarter per block (y = 0..3).
// ==================================================================
__global__ void __launch_bounds__(256, 2)
out_mma_kernel(float* __restrict__ out) {
    char* sm = dyn_smem;
    uint32_t sbase = smem_u32(sm);
    int tid = threadIdx.x;
    int warp = tid >> 5, lane = tid & 31;
    size_t rowbase = (size_t)blockIdx.x * 128;
    int colbase = blockIdx.y * 128;

#pragma unroll
    for (int t = 0; t < 8; t++) {
        int j   = tid + t * 256;
        int row = j >> 4;
        int c8  = (j & 15) * 8;
        uint32_t off = (uint32_t)row * KV_STRIDE_B + c8 * 2;
        CP_ASYNC16(sbase + OFF_A + off, g_U + (rowbase + row) * DATOM + c8);
        CP_ASYNC16(sbase + OFF_B + off,
                   g_hwo + (size_t)row * DTOK + colbase + c8);
    }
    CP_COMMIT();
    CP_WAIT0();
    __syncthreads();

    int wm = warp & 3;
    int wn = warp >> 2;
    int lr = lane & 15;
    int lc = lane >> 4;
    uint32_t aAddr = sbase + OFF_A + (uint32_t)(wm * 32 + lr) * KV_STRIDE_B + lc * 16;
    uint32_t bAddr = sbase + OFF_B + (uint32_t)lr * KV_STRIDE_B + (wn * 64 + lc * 8) * 2;

    float c[2][8][4];
#pragma unroll
    for (int mt = 0; mt < 2; mt++)
#pragma unroll
        for (int nt = 0; nt < 8; nt++)
#pragma unroll
            for (int e = 0; e < 4; e++) c[mt][nt][e] = 0.f;

#pragma unroll
    for (int ks = 0; ks < 8; ks++) {
        uint32_t ak = aAddr + ks * 32;
        uint32_t bk = bAddr + ks * 16 * KV_STRIDE_B;
        uint32_t aF[2][4];
        ldm4(aF[0], ak);
        ldm4(aF[1], ak + 16 * KV_STRIDE_B);
        uint32_t b[4][4];
#pragma unroll
        for (int i = 0; i < 4; i++) ldm4t(b[i], bk + i * 32);
#pragma unroll
        for (int mt = 0; mt < 2; mt++)
#pragma unroll
            for (int i = 0; i < 4; i++) {
                mma16816(c[mt][2 * i],     aF[mt], b[i][0], b[i][1]);
                mma16816(c[mt][2 * i + 1], aF[mt], b[i][2], b[i][3]);
            }
    }
    __syncthreads();
    {
        float* stg = (float*)sm;
        int cr = lane >> 2, cc2 = (lane & 3) * 2;
#pragma unroll
        for (int mt = 0; mt < 2; mt++) {
            int r0 = wm * 32 + mt * 16 + cr;
#pragma unroll
            for (int nt = 0; nt < 8; nt++) {
                int cc = wn * 64 + nt * 8 + cc2;
                *(float2*)&stg[r0 * STG_STRIDE + cc] =
                    make_float2(c[mt][nt][0], c[mt][nt][1]);
                *(float2*)&stg[(r0 + 8) * STG_STRIDE + cc] =
                    make_float2(c[mt][nt][2], c[mt][nt][3]);
            }
        }
        __syncthreads();
#pragma unroll
        for (int t = 0; t < 16; t++) {
            int j  = tid + t * 256;
            int r  = j >> 5;
            int c4 = (j & 31) * 4;
            *(float4*)&out[(rowbase + r) * DTOK + colbase + c4] =
                *(float4*)&stg[r * STG_STRIDE + c4];
        }
    }
}

// ==================================================================
// Launch.
// ==================================================================
extern "C" void kernel_launch(void* const* d_in, const int* in_sizes, int n_in,
                              void* d_out, int out_size) {
    const float* s      = (const float*)d_in[0];
    const float* a      = (const float*)d_in[1];
    const int*   starts = (const int*)  d_in[2];
    const int*   counts = (const int*)  d_in[3];
    const float* tmask  = (const float*)d_in[4];
    const float* wq     = (const float*)d_in[5];
    const float* wk     = (const float*)d_in[6];
    const float* wv     = (const float*)d_in[7];
    const float* wg     = (const float*)d_in[8];
    const float* wo     = (const float*)d_in[9];
    const float* lnqg   = (const float*)d_in[10];
    const float* lnqb   = (const float*)d_in[11];
    const float* lnkg   = (const float*)d_in[12];
    const float* lnkb   = (const float*)d_in[13];
    float* out = (float*)d_out;

    cudaFuncSetAttribute(kv_mma_kernel,
                         cudaFuncAttributeMaxDynamicSharedMemorySize, GEMM_SMEM);
    cudaFuncSetAttribute(qg_mma_kernel,
                         cudaFuncAttributeMaxDynamicSharedMemorySize, GEMM_SMEM);
    cudaFuncSetAttribute(out_mma_kernel,
                         cudaFuncAttributeMaxDynamicSharedMemorySize, GEMM_SMEM);

    wprep_kernel<<<256, 256>>>(wq, wk, wv, wg, wo);
    s_prep_kernel<<<NTOK / 8, 256>>>(s, lnqg, lnqb);
    a_prep_kernel<<<NATOM / 8, 256>>>(a, lnkg, lnkb);
    kv_mma_kernel<<<dim3(NATOM / 128, 2), 256, GEMM_SMEM>>>();
    qg_mma_kernel<<<dim3(NTOK / 128, 2), 256, GEMM_SMEM>>>();
    attn_gate_kernel<<<NTOK / 8, 256>>>(starts, counts, tmask);
    out_mma_kernel<<<dim3(NTOK / 128, 4), 256, GEMM_SMEM>>>(out);
}